// round 10
// baseline (speedup 1.0000x reference)
#include <cuda_runtime.h>
#include <cuda_bf16.h>
#include <cstdint>

#define B_   2
#define S_   2048
#define DM_  2048
#define H_   32
#define KV_  8
#define HD_  64
#define GRP_ (H_ / KV_)   // 4
#define NQKV 3072          // fused QKV width: 2048 q | 512 k | 512 v
#define KOFF 2048
#define VOFF 2560

// ============================ PTX helpers (base sm_103 safe) ==================
__device__ __forceinline__ uint32_t smem_u32(const void* p) {
    uint32_t a;
    asm("{ .reg .u64 t; cvta.to.shared.u64 t, %1; cvt.u32.u64 %0, t; }"
        : "=r"(a) : "l"(p));
    return a;
}
__device__ __forceinline__ void cp_async16(uint32_t s, const void* g) {
    asm volatile("cp.async.cg.shared.global [%0], [%1], 16;" :: "r"(s), "l"(g));
}
#define CP_COMMIT() asm volatile("cp.async.commit_group;" ::: "memory")
#define CP_WAIT(n)  asm volatile("cp.async.wait_group %0;" :: "n"(n) : "memory")

__device__ __forceinline__ void ldsm_x4(uint32_t addr, uint32_t& r0, uint32_t& r1,
                                        uint32_t& r2, uint32_t& r3) {
    asm volatile("ldmatrix.sync.aligned.m8n8.x4.shared.b16 {%0,%1,%2,%3}, [%4];"
                 : "=r"(r0), "=r"(r1), "=r"(r2), "=r"(r3) : "r"(addr));
}
__device__ __forceinline__ void ldsm_x4t(uint32_t addr, uint32_t& r0, uint32_t& r1,
                                         uint32_t& r2, uint32_t& r3) {
    asm volatile("ldmatrix.sync.aligned.m8n8.x4.trans.shared.b16 {%0,%1,%2,%3}, [%4];"
                 : "=r"(r0), "=r"(r1), "=r"(r2), "=r"(r3) : "r"(addr));
}
__device__ __forceinline__ void mma_bf16(float* d, const uint32_t* a,
                                         uint32_t b0, uint32_t b1) {
    asm volatile("mma.sync.aligned.m16n8k16.row.col.f32.bf16.bf16.f32 "
                 "{%0,%1,%2,%3}, {%4,%5,%6,%7}, {%8,%9}, {%0,%1,%2,%3};"
                 : "+f"(d[0]), "+f"(d[1]), "+f"(d[2]), "+f"(d[3])
                 : "r"(a[0]), "r"(a[1]), "r"(a[2]), "r"(a[3]), "r"(b0), "r"(b1));
}
__device__ __forceinline__ uint32_t bpack(__nv_bfloat16 x, __nv_bfloat16 y) {
    __nv_bfloat162 t(x, y);
    return *reinterpret_cast<uint32_t*>(&t);
}

// ============================ scratch =========================================
__device__ __nv_bfloat16 g_hsh[(size_t)B_ * S_ * DM_];   // activations hi/lo
__device__ __nv_bfloat16 g_hsl[(size_t)B_ * S_ * DM_];
__device__ __nv_bfloat16 g_aoh[(size_t)B_ * S_ * DM_];   // attn out hi/lo
__device__ __nv_bfloat16 g_aol[(size_t)B_ * S_ * DM_];
__device__ __nv_bfloat16 g_wqkvh[(size_t)NQKV * DM_];    // [N,K] fused weights
__device__ __nv_bfloat16 g_wqkvl[(size_t)NQKV * DM_];
__device__ __nv_bfloat16 g_woh[(size_t)DM_ * DM_];
__device__ __nv_bfloat16 g_wol[(size_t)DM_ * DM_];
// attention operands (bf16 hi/lo, post-RoPE, Q pre-scaled by 1/8)
__device__ __nv_bfloat16 g_qh[(size_t)B_ * S_ * DM_];    // [row, h*64+d]
__device__ __nv_bfloat16 g_ql[(size_t)B_ * S_ * DM_];
__device__ __nv_bfloat16 g_kh[(size_t)B_ * KV_ * S_ * HD_]; // [b*KV+kvh][s][d]
__device__ __nv_bfloat16 g_kl[(size_t)B_ * KV_ * S_ * HD_];
__device__ __nv_bfloat16 g_vh[(size_t)B_ * KV_ * S_ * HD_];
__device__ __nv_bfloat16 g_vl[(size_t)B_ * KV_ * S_ * HD_];

// ====== ONE prep launch: weights transpose+split (z=0..3) + activations (z=4) =
__global__ void prep_all(const float* __restrict__ hs,
                         const float* __restrict__ Wq, const float* __restrict__ Wk,
                         const float* __restrict__ Wv, const float* __restrict__ Wo,
                         __nv_bfloat16* __restrict__ hsh, __nv_bfloat16* __restrict__ hsl,
                         __nv_bfloat16* __restrict__ qkvh, __nv_bfloat16* __restrict__ qkvl,
                         __nv_bfloat16* __restrict__ woh,  __nv_bfloat16* __restrict__ wol)
{
    const int z = blockIdx.z;
    const int tid = threadIdx.y * 32 + threadIdx.x;

    if (z == 4) {
        int bid = blockIdx.x + 128 * blockIdx.y;
        int i = bid * 256 + tid;
        float4 v = ((const float4*)hs)[i];
        __nv_bfloat16 h0 = __float2bfloat16(v.x);
        __nv_bfloat16 h1 = __float2bfloat16(v.y);
        __nv_bfloat16 h2 = __float2bfloat16(v.z);
        __nv_bfloat16 h3 = __float2bfloat16(v.w);
        __nv_bfloat16 l0 = __float2bfloat16(v.x - __bfloat162float(h0));
        __nv_bfloat16 l1 = __float2bfloat16(v.y - __bfloat162float(h1));
        __nv_bfloat16 l2 = __float2bfloat16(v.z - __bfloat162float(h2));
        __nv_bfloat16 l3 = __float2bfloat16(v.w - __bfloat162float(h3));
        ((__nv_bfloat162*)hsh)[2 * i]     = __nv_bfloat162(h0, h1);
        ((__nv_bfloat162*)hsh)[2 * i + 1] = __nv_bfloat162(h2, h3);
        ((__nv_bfloat162*)hsl)[2 * i]     = __nv_bfloat162(l0, l1);
        ((__nv_bfloat162*)hsl)[2 * i + 1] = __nv_bfloat162(l2, l3);
        return;
    }

    if (blockIdx.x >= 64) return;
    const int N = (z == 1 || z == 2) ? 512 : 2048;
    const int n0 = blockIdx.x * 32;
    if (n0 >= N) return;
    const int k0 = blockIdx.y * 32;
    const float* W = (z == 0) ? Wq : (z == 1) ? Wk : (z == 2) ? Wv : Wo;
    __nv_bfloat16* h = (z == 3) ? woh : qkvh;
    __nv_bfloat16* l = (z == 3) ? wol : qkvl;
    const size_t dof = (z == 1) ? (size_t)KOFF * DM_ : (z == 2) ? (size_t)VOFF * DM_ : 0;

    __shared__ float ts[32][33];
    int tx = threadIdx.x, ty = threadIdx.y;
    for (int i = ty; i < 32; i += 8)
        ts[i][tx] = W[(size_t)(k0 + i) * N + n0 + tx];
    __syncthreads();
    for (int i = ty; i < 32; i += 8) {
        float x = ts[tx][i];
        __nv_bfloat16 hv = __float2bfloat16(x);
        __nv_bfloat16 lv = __float2bfloat16(x - __bfloat162float(hv));
        size_t o = dof + (size_t)(n0 + i) * DM_ + k0 + tx;
        h[o] = hv;
        l[o] = lv;
    }
}

// ====== persistent warp-MMA GEMM, 3-term compensated ==========================
// fuse=0: C[M,N] fp32 (+bias from boff).
// fuse=1: QKV mode — no C write; epilogue stages tile in smem, applies RoPE
//         (q: *0.125, k: plain rope, v: passthrough) and emits bf16 hi/lo
//         operands directly (values identical to the old rope_split kernel).
#define TILE_B  8192
#define STAGE_B (4 * TILE_B)
#define NSTG    3
#define GSMEM   (NSTG * STAGE_B)
#define GGRID   296
#define SPITCH  132

__global__ __launch_bounds__(256, 2) void gemm_mma(
    const __nv_bfloat16* __restrict__ Ah, const __nv_bfloat16* __restrict__ Al,
    const __nv_bfloat16* __restrict__ Bh, const __nv_bfloat16* __restrict__ Bl,
    const float* __restrict__ bias, int boff, float* __restrict__ C,
    int M, int N, int K, int fuse,
    const float* __restrict__ cosb, const float* __restrict__ sinb,
    __nv_bfloat16* __restrict__ qh_, __nv_bfloat16* __restrict__ ql_,
    __nv_bfloat16* __restrict__ kh_, __nv_bfloat16* __restrict__ kl_,
    __nv_bfloat16* __restrict__ vh_, __nv_bfloat16* __restrict__ vl_)
{
    extern __shared__ char smem[];
    const uint32_t sb = smem_u32(smem);
    const int tid  = threadIdx.x;
    const int lane = tid & 31;
    const int wid  = tid >> 5;
    const int wm   = wid >> 2;
    const int wn   = wid & 3;
    const int K32 = K / 32;
    const int nx = N >> 7;
    const int ntiles = (M >> 7) * nx;

    const int lr0 = tid >> 2, lc = tid & 3;
    const int lr1 = lr0 + 64;
    const uint32_t so0 = (uint32_t)lr0 * 64 + ((uint32_t)(lc ^ ((lr0 >> 1) & 3)) << 4);
    const uint32_t so1 = (uint32_t)lr1 * 64 + ((uint32_t)(lc ^ ((lr1 >> 1) & 3)) << 4);
    const int ge = lc * 8;

    const int lrow = lane & 15, half = lane >> 4;
    const uint32_t lsw = (uint32_t)((lrow >> 1) & 3);
    const uint32_t a_row_off = (uint32_t)(wm * 64 + lrow) * 64;
    const uint32_t b_row_off = (uint32_t)(wn * 32 + lrow) * 64;

    for (int t = blockIdx.x; t < ntiles; t += gridDim.x) {
        const int m0 = (t / nx) << 7;
        const int n0 = (t % nx) << 7;

        float acc[4][4][4];
#pragma unroll
        for (int i = 0; i < 4; i++)
#pragma unroll
            for (int j = 0; j < 4; j++)
#pragma unroll
                for (int r = 0; r < 4; r++) acc[i][j][r] = 0.0f;

#define LOAD_STAGE(kt)                                                           \
    do {                                                                         \
        const int _k0 = (kt) * 32;                                               \
        const uint32_t _st = sb + ((kt) % NSTG) * STAGE_B;                       \
        size_t _a0 = (size_t)(m0 + lr0) * K + _k0 + ge;                          \
        size_t _a1 = (size_t)(m0 + lr1) * K + _k0 + ge;                          \
        size_t _b0 = (size_t)(n0 + lr0) * K + _k0 + ge;                          \
        size_t _b1 = (size_t)(n0 + lr1) * K + _k0 + ge;                          \
        cp_async16(_st + so0,              Ah + _a0);                            \
        cp_async16(_st + so1,              Ah + _a1);                            \
        cp_async16(_st + TILE_B + so0,     Al + _a0);                            \
        cp_async16(_st + TILE_B + so1,     Al + _a1);                            \
        cp_async16(_st + 2 * TILE_B + so0, Bh + _b0);                            \
        cp_async16(_st + 2 * TILE_B + so1, Bh + _b1);                            \
        cp_async16(_st + 3 * TILE_B + so0, Bl + _b0);                            \
        cp_async16(_st + 3 * TILE_B + so1, Bl + _b1);                            \
    } while (0)

        __syncthreads();   // all warps done with previous tile's smem
        LOAD_STAGE(0); CP_COMMIT();
        LOAD_STAGE(1); CP_COMMIT();

        for (int kt = 0; kt < K32; kt++) {
            CP_WAIT(1);
            __syncthreads();
            if (kt + 2 < K32) LOAD_STAGE(kt + 2);
            CP_COMMIT();

            const uint32_t st = sb + (kt % NSTG) * STAGE_B;
#pragma unroll
            for (int ks = 0; ks < 2; ks++) {
                const uint32_t cp0 = (((uint32_t)(ks * 2 + half)) ^ lsw) << 4;

                uint32_t bh[8], bl[8];
#pragma unroll
                for (int p = 0; p < 2; p++) {
                    uint32_t q0, q1, q2, q3;
                    ldsm_x4(st + 2 * TILE_B + b_row_off + p * 1024 + cp0, q0, q1, q2, q3);
                    bh[4 * p + 0] = q0; bh[4 * p + 1] = q2;
                    bh[4 * p + 2] = q1; bh[4 * p + 3] = q3;
                    ldsm_x4(st + 3 * TILE_B + b_row_off + p * 1024 + cp0, q0, q1, q2, q3);
                    bl[4 * p + 0] = q0; bl[4 * p + 1] = q2;
                    bl[4 * p + 2] = q1; bl[4 * p + 3] = q3;
                }

                uint32_t a[4][4];
#pragma unroll
                for (int i = 0; i < 4; i++)
                    ldsm_x4(st + a_row_off + i * 1024 + cp0,
                            a[i][0], a[i][1], a[i][2], a[i][3]);

#pragma unroll
                for (int i = 0; i < 4; i++)
#pragma unroll
                    for (int j = 0; j < 4; j++)
                        mma_bf16(acc[i][j], a[i], bh[2 * j], bh[2 * j + 1]);
#pragma unroll
                for (int i = 0; i < 4; i++)
#pragma unroll
                    for (int j = 0; j < 4; j++)
                        mma_bf16(acc[i][j], a[i], bl[2 * j], bl[2 * j + 1]);

#pragma unroll
                for (int i = 0; i < 4; i++)
                    ldsm_x4(st + TILE_B + a_row_off + i * 1024 + cp0,
                            a[i][0], a[i][1], a[i][2], a[i][3]);
#pragma unroll
                for (int i = 0; i < 4; i++)
#pragma unroll
                    for (int j = 0; j < 4; j++)
                        mma_bf16(acc[i][j], a[i], bh[2 * j], bh[2 * j + 1]);
            }
        }
#undef LOAD_STAGE

        if (!fuse) {
#pragma unroll
            for (int i = 0; i < 4; i++) {
                const int row = m0 + wm * 64 + i * 16 + (lane >> 2);
#pragma unroll
                for (int j = 0; j < 4; j++) {
                    const int col = n0 + wn * 32 + j * 8 + (lane & 3) * 2;
                    float b0 = 0.f, b1 = 0.f;
                    const int bi = col - boff;
                    if (bias && bi >= 0) { b0 = bias[bi]; b1 = bias[bi + 1]; }
                    float2 v0, v1;
                    v0.x = acc[i][j][0] + b0; v0.y = acc[i][j][1] + b1;
                    v1.x = acc[i][j][2] + b0; v1.y = acc[i][j][3] + b1;
                    *(float2*)(C + (size_t)row * N + col)       = v0;
                    *(float2*)(C + (size_t)(row + 8) * N + col) = v1;
                }
            }
        } else {
            // ---- fused QKV epilogue: stage fp32 tile, rope+split, emit bf16 ----
            CP_WAIT(0);
            __syncthreads();                 // stage buffers now free
            float* stg = (float*)smem;
#pragma unroll
            for (int i = 0; i < 4; i++) {
                const int rl = wm * 64 + i * 16 + (lane >> 2);
#pragma unroll
                for (int j = 0; j < 4; j++) {
                    const int cl = wn * 32 + j * 8 + (lane & 3) * 2;
                    const int col = n0 + cl;
                    float b0 = 0.f, b1 = 0.f;
                    const int bi = col - boff;
                    if (bias && bi >= 0) { b0 = bias[bi]; b1 = bias[bi + 1]; }
                    float2 v0, v1;
                    v0.x = acc[i][j][0] + b0; v0.y = acc[i][j][1] + b1;
                    v1.x = acc[i][j][2] + b0; v1.y = acc[i][j][3] + b1;
                    *(float2*)&stg[rl * SPITCH + cl]       = v0;
                    *(float2*)&stg[(rl + 8) * SPITCH + cl] = v1;
                }
            }
            __syncthreads();

            for (int w = 0; w < 32; w++) {
                const int p  = w * 256 + tid;
                const int rl = p >> 6;
                const int pc = p & 63;
                const int hh = pc >> 5;      // warp-uniform
                const int d  = pc & 31;
                const int gr = m0 + rl;
                const float x1 = stg[rl * SPITCH + hh * 64 + d];
                const float x2 = stg[rl * SPITCH + hh * 64 + d + 32];
                const int gc = n0 + hh * 64;   // head base column (64-aligned)

                __nv_bfloat16 *dh, *dl;
                size_t off;
                float y1, y2;
                if (gc < KOFF) {               // q: rope + 1/8
                    const float c1 = cosb[gr * 64 + d],      s1 = sinb[gr * 64 + d];
                    const float c2 = cosb[gr * 64 + d + 32], s2 = sinb[gr * 64 + d + 32];
                    y1 = (x1 * c1 - x2 * s1) * 0.125f;
                    y2 = (x2 * c2 + x1 * s2) * 0.125f;
                    dh = qh_; dl = ql_;
                    off = (size_t)gr * DM_ + gc + d;
                } else if (gc < VOFF) {        // k: rope
                    const float c1 = cosb[gr * 64 + d],      s1 = sinb[gr * 64 + d];
                    const float c2 = cosb[gr * 64 + d + 32], s2 = sinb[gr * 64 + d + 32];
                    y1 = x1 * c1 - x2 * s1;
                    y2 = x2 * c2 + x1 * s2;
                    const int kvh = (gc - KOFF) >> 6;
                    const int bb = gr >> 11, s = gr & (S_ - 1);
                    dh = kh_; dl = kl_;
                    off = ((size_t)(bb * KV_ + kvh) * S_ + s) * HD_ + d;
                } else {                       // v: passthrough (bias already in)
                    y1 = x1; y2 = x2;
                    const int kvh = (gc - VOFF) >> 6;
                    const int bb = gr >> 11, s = gr & (S_ - 1);
                    dh = vh_; dl = vl_;
                    off = ((size_t)(bb * KV_ + kvh) * S_ + s) * HD_ + d;
                }
                const __nv_bfloat16 h1 = __float2bfloat16(y1);
                const __nv_bfloat16 h2 = __float2bfloat16(y2);
                dh[off]      = h1;
                dh[off + 32] = h2;
                dl[off]      = __float2bfloat16(y1 - __bfloat162float(h1));
                dl[off + 32] = __float2bfloat16(y2 - __bfloat162float(h2));
            }
            // loop-top __syncthreads protects stg before next tile's loads
        }
    }
}

// =========== tensor-core flash attention (3-term split-bf16, unchanged r9) ====
#define AQ_H   0
#define AQ_L   16384
#define AKV0   32768
#define AKV_ST 32768
#define ASMEM  98304

__global__ __launch_bounds__(256, 2) void attn_mma(
    const __nv_bfloat16* __restrict__ qh, const __nv_bfloat16* __restrict__ ql,
    const __nv_bfloat16* __restrict__ kh, const __nv_bfloat16* __restrict__ kl,
    const __nv_bfloat16* __restrict__ vh, const __nv_bfloat16* __restrict__ vl,
    __nv_bfloat16* __restrict__ oh, __nv_bfloat16* __restrict__ ol)
{
    extern __shared__ char smem[];
    const uint32_t sb = smem_u32(smem);
    const int tid  = threadIdx.x;
    const int lane = tid & 31;
    const int warp = tid >> 5;
    const int wr0  = warp * 16;
    const int m0 = (gridDim.x - 1 - blockIdx.x) * 128;   // heavy tiles first
    const int h  = blockIdx.y;
    const int b  = blockIdx.z;
    const int kvh = h >> 2;

    const size_t kvbase = (size_t)(b * KV_ + kvh) * S_ * HD_;

    {
        const size_t qg = (size_t)(b * S_ + m0) * DM_ + h * HD_;
#pragma unroll
        for (int i = 0; i < 4; i++) {
            int c = tid + 256 * i;
            int row = c >> 3, u = c & 7;
            uint32_t ad = sb + row * 128 + (((uint32_t)(u ^ (row & 7))) << 4);
            cp_async16(ad,          qh + qg + (size_t)row * DM_ + u * 8);
            cp_async16(ad + AQ_L,   ql + qg + (size_t)row * DM_ + u * 8);
        }
    }
    CP_COMMIT();

    const int NT = (m0 >> 6) + 2;

#define LOAD_KV(t)                                                                \
    do {                                                                          \
        const int _j0 = (t) * 64;                                                 \
        const uint32_t _st = sb + AKV0 + ((t) & 1) * AKV_ST;                      \
        _Pragma("unroll")                                                         \
        for (int _i = 0; _i < 2; _i++) {                                          \
            int _c = tid * 2 + _i;                                                \
            int _r = _c >> 3, _u = _c & 7;                                        \
            uint32_t _ad = _st + _r * 128 + (((uint32_t)(_u ^ (_r & 7))) << 4);   \
            size_t _g = kvbase + (size_t)(_j0 + _r) * HD_ + _u * 8;               \
            cp_async16(_ad,          kh + _g);                                    \
            cp_async16(_ad + 8192,   kl + _g);                                    \
            cp_async16(_ad + 16384,  vh + _g);                                    \
            cp_async16(_ad + 24576,  vl + _g);                                    \
        }                                                                         \
    } while (0)

    LOAD_KV(0);
    CP_COMMIT();

    CP_WAIT(1);
    __syncthreads();

    uint32_t Qh_[4][4], Ql_[4][4];
    {
        const int row = wr0 + (lane & 15);
#pragma unroll
        for (int kk = 0; kk < 4; kk++) {
            uint32_t u = (uint32_t)(kk * 2 + (lane >> 4));
            uint32_t ad = sb + row * 128 + ((u ^ (uint32_t)(row & 7)) << 4);
            ldsm_x4(ad,        Qh_[kk][0], Qh_[kk][1], Qh_[kk][2], Qh_[kk][3]);
            ldsm_x4(ad + AQ_L, Ql_[kk][0], Ql_[kk][1], Ql_[kk][2], Ql_[kk][3]);
        }
    }

    float o[8][4];
#pragma unroll
    for (int d = 0; d < 8; d++)
#pragma unroll
        for (int r = 0; r < 4; r++) o[d][r] = 0.0f;
    float m1 = -1e30f, m2 = -1e30f, l1 = 0.0f, l2 = 0.0f;

    const int row1 = m0 + wr0 + (lane >> 2);
    const int row2 = row1 + 8;

    for (int t = 0; t < NT; t++) {
        CP_WAIT(0);
        __syncthreads();
        if (t + 1 < NT) LOAD_KV(t + 1);
        CP_COMMIT();

        const int j0 = t * 64;
        if (j0 <= m0 + wr0 + 15) {
            const uint32_t st = sb + AKV0 + (t & 1) * AKV_ST;

            float s[8][4];
#pragma unroll
            for (int n = 0; n < 8; n++)
#pragma unroll
                for (int r = 0; r < 4; r++) s[n][r] = 0.0f;

#pragma unroll
            for (int np = 0; np < 4; np++) {
                const int krow = np * 16 + (lane & 15);
#pragma unroll
                for (int kk = 0; kk < 4; kk++) {
                    uint32_t u = (uint32_t)(kk * 2 + (lane >> 4));
                    uint32_t ad = st + krow * 128 + ((u ^ (uint32_t)(krow & 7)) << 4);
                    uint32_t f0, f1, f2, f3;
                    ldsm_x4(ad, f0, f1, f2, f3);            // Kh fragment
                    mma_bf16(s[2 * np],     Qh_[kk], f0, f2);
                    mma_bf16(s[2 * np + 1], Qh_[kk], f1, f3);
                    mma_bf16(s[2 * np],     Ql_[kk], f0, f2);
                    mma_bf16(s[2 * np + 1], Ql_[kk], f1, f3);
                    ldsm_x4(ad + 8192, f0, f1, f2, f3);     // Kl fragment (reuse regs)
                    mma_bf16(s[2 * np],     Qh_[kk], f0, f2);
                    mma_bf16(s[2 * np + 1], Qh_[kk], f1, f3);
                }
            }

            if (j0 + 63 > m0 + wr0) {
#pragma unroll
                for (int n = 0; n < 8; n++) {
                    const int col = j0 + n * 8 + ((lane & 3) << 1);
                    if (col     > row1) s[n][0] = -1e30f;
                    if (col + 1 > row1) s[n][1] = -1e30f;
                    if (col     > row2) s[n][2] = -1e30f;
                    if (col + 1 > row2) s[n][3] = -1e30f;
                }
            }

            float mx1 = -1e30f, mx2 = -1e30f;
#pragma unroll
            for (int n = 0; n < 8; n++) {
                mx1 = fmaxf(mx1, fmaxf(s[n][0], s[n][1]));
                mx2 = fmaxf(mx2, fmaxf(s[n][2], s[n][3]));
            }
            mx1 = fmaxf(mx1, __shfl_xor_sync(0xffffffff, mx1, 1));
            mx1 = fmaxf(mx1, __shfl_xor_sync(0xffffffff, mx1, 2));
            mx2 = fmaxf(mx2, __shfl_xor_sync(0xffffffff, mx2, 1));
            mx2 = fmaxf(mx2, __shfl_xor_sync(0xffffffff, mx2, 2));

            const float M1 = fmaxf(m1, mx1), M2 = fmaxf(m2, mx2);
            const float c1 = __expf(m1 - M1), c2 = __expf(m2 - M2);
            float ls1 = 0.0f, ls2 = 0.0f;
#pragma unroll
            for (int n = 0; n < 8; n++) {
                s[n][0] = __expf(s[n][0] - M1); ls1 += s[n][0];
                s[n][1] = __expf(s[n][1] - M1); ls1 += s[n][1];
                s[n][2] = __expf(s[n][2] - M2); ls2 += s[n][2];
                s[n][3] = __expf(s[n][3] - M2); ls2 += s[n][3];
            }
            ls1 += __shfl_xor_sync(0xffffffff, ls1, 1);
            ls1 += __shfl_xor_sync(0xffffffff, ls1, 2);
            ls2 += __shfl_xor_sync(0xffffffff, ls2, 1);
            ls2 += __shfl_xor_sync(0xffffffff, ls2, 2);
            l1 = l1 * c1 + ls1;  l2 = l2 * c2 + ls2;
            m1 = M1;             m2 = M2;
#pragma unroll
            for (int d = 0; d < 8; d++) {
                o[d][0] *= c1; o[d][1] *= c1;
                o[d][2] *= c2; o[d][3] *= c2;
            }

            uint32_t ph[4][4], pl[4][4];
#pragma unroll
            for (int jj = 0; jj < 4; jj++) {
#pragma unroll
                for (int q = 0; q < 4; q++) {
                    const int n = 2 * jj + (q >> 1);
                    const int r = (q & 1) * 2;
                    float a = s[n][r], bq = s[n][r + 1];
                    __nv_bfloat16 ha = __float2bfloat16(a);
                    __nv_bfloat16 hb = __float2bfloat16(bq);
                    ph[jj][q] = bpack(ha, hb);
                    pl[jj][q] = bpack(__float2bfloat16(a - __bfloat162float(ha)),
                                      __float2bfloat16(bq - __bfloat162float(hb)));
                }
            }

#pragma unroll
            for (int dg = 0; dg < 4; dg++) {
#pragma unroll
                for (int jj = 0; jj < 4; jj++) {
                    const int vrow = jj * 16 + (lane & 15);
                    uint32_t u = (uint32_t)(dg * 2 + (lane >> 4));
                    uint32_t ad = st + 16384 + vrow * 128 + ((u ^ (uint32_t)(vrow & 7)) << 4);
                    uint32_t f0, f1, f2, f3;
                    ldsm_x4t(ad, f0, f1, f2, f3);           // Vh fragment
                    mma_bf16(o[2 * dg],     ph[jj], f0, f1);
                    mma_bf16(o[2 * dg + 1], ph[jj], f2, f3);
                    mma_bf16(o[2 * dg],     pl[jj], f0, f1);
                    mma_bf16(o[2 * dg + 1], pl[jj], f2, f3);
                    ldsm_x4t(ad + 8192, f0, f1, f2, f3);    // Vl fragment (reuse regs)
                    mma_bf16(o[2 * dg],     ph[jj], f0, f1);
                    mma_bf16(o[2 * dg + 1], ph[jj], f2, f3);
                }
            }
        }
    }
#undef LOAD_KV

    const float inv1 = 1.0f / l1;
    const float inv2 = 1.0f / l2;
#pragma unroll
    for (int d = 0; d < 8; d++) {
        const int col = h * HD_ + d * 8 + ((lane & 3) << 1);
        {
            size_t ad = (size_t)(b * S_ + row1) * DM_ + col;
            float x0 = o[d][0] * inv1, x1 = o[d][1] * inv1;
            __nv_bfloat16 h0 = __float2bfloat16(x0);
            __nv_bfloat16 h1 = __float2bfloat16(x1);
            *(uint32_t*)(oh + ad) = bpack(h0, h1);
            *(uint32_t*)(ol + ad) = bpack(__float2bfloat16(x0 - __bfloat162float(h0)),
                                          __float2bfloat16(x1 - __bfloat162float(h1)));
        }
        {
            size_t ad = (size_t)(b * S_ + row2) * DM_ + col;
            float x0 = o[d][2] * inv2, x1 = o[d][3] * inv2;
            __nv_bfloat16 h0 = __float2bfloat16(x0);
            __nv_bfloat16 h1 = __float2bfloat16(x1);
            *(uint32_t*)(oh + ad) = bpack(h0, h1);
            *(uint32_t*)(ol + ad) = bpack(__float2bfloat16(x0 - __bfloat162float(h0)),
                                          __float2bfloat16(x1 - __bfloat162float(h1)));
        }
    }
}

// ================================ launch ======================================
extern "C" void kernel_launch(void* const* d_in, const int* in_sizes, int n_in,
                              void* d_out, int out_size)
{
    const float* hs    = (const float*)d_in[0];
    const float* cosb  = (const float*)d_in[2];
    const float* sinb  = (const float*)d_in[3];
    const float* W_q   = (const float*)d_in[4];
    const float* W_k   = (const float*)d_in[5];
    const float* W_v   = (const float*)d_in[6];
    const float* b_v   = (const float*)d_in[7];
    const float* W_o   = (const float*)d_in[8];
    const float* b_o   = (const float*)d_in[9];
    float* out = (float*)d_out;

    __nv_bfloat16 *hsh, *hsl, *aoh, *aol, *wqkvh, *wqkvl, *woh, *wol;
    __nv_bfloat16 *qhp, *qlp, *khp, *klp, *vhp, *vlp;
    cudaGetSymbolAddress((void**)&hsh, g_hsh);
    cudaGetSymbolAddress((void**)&hsl, g_hsl);
    cudaGetSymbolAddress((void**)&aoh, g_aoh);
    cudaGetSymbolAddress((void**)&aol, g_aol);
    cudaGetSymbolAddress((void**)&wqkvh, g_wqkvh);
    cudaGetSymbolAddress((void**)&wqkvl, g_wqkvl);
    cudaGetSymbolAddress((void**)&woh, g_woh);
    cudaGetSymbolAddress((void**)&wol, g_wol);
    cudaGetSymbolAddress((void**)&qhp, g_qh);
    cudaGetSymbolAddress((void**)&qlp, g_ql);
    cudaGetSymbolAddress((void**)&khp, g_kh);
    cudaGetSymbolAddress((void**)&klp, g_kl);
    cudaGetSymbolAddress((void**)&vhp, g_vh);
    cudaGetSymbolAddress((void**)&vlp, g_vl);

    cudaFuncSetAttribute(gemm_mma,
                         cudaFuncAttributeMaxDynamicSharedMemorySize, GSMEM);
    cudaFuncSetAttribute(attn_mma,
                         cudaFuncAttributeMaxDynamicSharedMemorySize, ASMEM);

    const int M = B_ * S_;       // 4096

    // launch 0: ALL prep (weights + activations) in one grid
    prep_all<<<dim3(128, 64, 5), dim3(32, 8)>>>(
        hs, W_q, W_k, W_v, W_o, hsh, hsl, wqkvh, wqkvl, woh, wol);

    // launch 1: fused QKV projection + RoPE + hi/lo split (persistent)
    gemm_mma<<<GGRID, 256, GSMEM>>>(
        hsh, hsl, wqkvh, wqkvl, b_v, VOFF, nullptr, M, NQKV, DM_,
        1, cosb, sinb, qhp, qlp, khp, klp, vhp, vlp);

    // launch 2: tensor-core flash attention, 2 CTAs/SM
    attn_mma<<<dim3(S_ / 128, H_, B_), 256, ASMEM>>>(
        qhp, qlp, khp, klp, vhp, vlp, aoh, aol);

    // launch 3 (PROFILED): O projection (persistent)
    gemm_mma<<<GGRID, 256, GSMEM>>>(
        aoh, aol, woh, wol, b_o, 0, out, M, DM_, DM_,
        0, nullptr, nullptr,
        nullptr, nullptr, nullptr, nullptr, nullptr, nullptr);
}

// round 11
// speedup vs baseline: 1.6249x; 1.6249x over previous
#include <cuda_runtime.h>
#include <cuda_bf16.h>
#include <cstdint>

#define B_   2
#define S_   2048
#define DM_  2048
#define H_   32
#define KV_  8
#define HD_  64
#define GRP_ (H_ / KV_)   // 4
#define NQKV 3072          // fused QKV width: 2048 q | 512 k | 512 v
#define KOFF 2048
#define VOFF 2560

// ============================ PTX helpers (base sm_103 safe) ==================
__device__ __forceinline__ uint32_t smem_u32(const void* p) {
    uint32_t a;
    asm("{ .reg .u64 t; cvta.to.shared.u64 t, %1; cvt.u32.u64 %0, t; }"
        : "=r"(a) : "l"(p));
    return a;
}
__device__ __forceinline__ void cp_async16(uint32_t s, const void* g) {
    asm volatile("cp.async.cg.shared.global [%0], [%1], 16;" :: "r"(s), "l"(g));
}
#define CP_COMMIT() asm volatile("cp.async.commit_group;" ::: "memory")
#define CP_WAIT(n)  asm volatile("cp.async.wait_group %0;" :: "n"(n) : "memory")

__device__ __forceinline__ void ldsm_x4(uint32_t addr, uint32_t& r0, uint32_t& r1,
                                        uint32_t& r2, uint32_t& r3) {
    asm volatile("ldmatrix.sync.aligned.m8n8.x4.shared.b16 {%0,%1,%2,%3}, [%4];"
                 : "=r"(r0), "=r"(r1), "=r"(r2), "=r"(r3) : "r"(addr));
}
__device__ __forceinline__ void ldsm_x4t(uint32_t addr, uint32_t& r0, uint32_t& r1,
                                         uint32_t& r2, uint32_t& r3) {
    asm volatile("ldmatrix.sync.aligned.m8n8.x4.trans.shared.b16 {%0,%1,%2,%3}, [%4];"
                 : "=r"(r0), "=r"(r1), "=r"(r2), "=r"(r3) : "r"(addr));
}
__device__ __forceinline__ void mma_bf16(float* d, const uint32_t* a,
                                         uint32_t b0, uint32_t b1) {
    asm volatile("mma.sync.aligned.m16n8k16.row.col.f32.bf16.bf16.f32 "
                 "{%0,%1,%2,%3}, {%4,%5,%6,%7}, {%8,%9}, {%0,%1,%2,%3};"
                 : "+f"(d[0]), "+f"(d[1]), "+f"(d[2]), "+f"(d[3])
                 : "r"(a[0]), "r"(a[1]), "r"(a[2]), "r"(a[3]), "r"(b0), "r"(b1));
}
__device__ __forceinline__ uint32_t bpack(__nv_bfloat16 x, __nv_bfloat16 y) {
    __nv_bfloat162 t(x, y);
    return *reinterpret_cast<uint32_t*>(&t);
}

// ============================ scratch =========================================
__device__ float g_qkv[(size_t)B_ * S_ * NQKV];          // 48 MB fused q|k|v

__device__ __nv_bfloat16 g_hsh[(size_t)B_ * S_ * DM_];   // activations hi/lo
__device__ __nv_bfloat16 g_hsl[(size_t)B_ * S_ * DM_];
__device__ __nv_bfloat16 g_aoh[(size_t)B_ * S_ * DM_];   // attn out hi/lo
__device__ __nv_bfloat16 g_aol[(size_t)B_ * S_ * DM_];
__device__ __nv_bfloat16 g_wqkvh[(size_t)NQKV * DM_];    // [N,K] fused weights
__device__ __nv_bfloat16 g_wqkvl[(size_t)NQKV * DM_];
__device__ __nv_bfloat16 g_woh[(size_t)DM_ * DM_];
__device__ __nv_bfloat16 g_wol[(size_t)DM_ * DM_];
// attention operands (bf16 hi/lo, post-RoPE, Q pre-scaled by 1/8)
__device__ __nv_bfloat16 g_qh[(size_t)B_ * S_ * DM_];    // [row, h*64+d]
__device__ __nv_bfloat16 g_ql[(size_t)B_ * S_ * DM_];
__device__ __nv_bfloat16 g_kh[(size_t)B_ * KV_ * S_ * HD_]; // [b*KV+kvh][s][d]
__device__ __nv_bfloat16 g_kl[(size_t)B_ * KV_ * S_ * HD_];
__device__ __nv_bfloat16 g_vh[(size_t)B_ * KV_ * S_ * HD_];
__device__ __nv_bfloat16 g_vl[(size_t)B_ * KV_ * S_ * HD_];

// ====== ONE prep launch: weights transpose+split (z=0..3) + activations (z=4) =
__global__ void prep_all(const float* __restrict__ hs,
                         const float* __restrict__ Wq, const float* __restrict__ Wk,
                         const float* __restrict__ Wv, const float* __restrict__ Wo,
                         __nv_bfloat16* __restrict__ hsh, __nv_bfloat16* __restrict__ hsl,
                         __nv_bfloat16* __restrict__ qkvh, __nv_bfloat16* __restrict__ qkvl,
                         __nv_bfloat16* __restrict__ woh,  __nv_bfloat16* __restrict__ wol)
{
    const int z = blockIdx.z;
    const int tid = threadIdx.y * 32 + threadIdx.x;

    if (z == 4) {
        int bid = blockIdx.x + 128 * blockIdx.y;
        int i = bid * 256 + tid;
        float4 v = ((const float4*)hs)[i];
        __nv_bfloat16 h0 = __float2bfloat16(v.x);
        __nv_bfloat16 h1 = __float2bfloat16(v.y);
        __nv_bfloat16 h2 = __float2bfloat16(v.z);
        __nv_bfloat16 h3 = __float2bfloat16(v.w);
        __nv_bfloat16 l0 = __float2bfloat16(v.x - __bfloat162float(h0));
        __nv_bfloat16 l1 = __float2bfloat16(v.y - __bfloat162float(h1));
        __nv_bfloat16 l2 = __float2bfloat16(v.z - __bfloat162float(h2));
        __nv_bfloat16 l3 = __float2bfloat16(v.w - __bfloat162float(h3));
        ((__nv_bfloat162*)hsh)[2 * i]     = __nv_bfloat162(h0, h1);
        ((__nv_bfloat162*)hsh)[2 * i + 1] = __nv_bfloat162(h2, h3);
        ((__nv_bfloat162*)hsl)[2 * i]     = __nv_bfloat162(l0, l1);
        ((__nv_bfloat162*)hsl)[2 * i + 1] = __nv_bfloat162(l2, l3);
        return;
    }

    if (blockIdx.x >= 64) return;
    const int N = (z == 1 || z == 2) ? 512 : 2048;
    const int n0 = blockIdx.x * 32;
    if (n0 >= N) return;
    const int k0 = blockIdx.y * 32;
    const float* W = (z == 0) ? Wq : (z == 1) ? Wk : (z == 2) ? Wv : Wo;
    __nv_bfloat16* h = (z == 3) ? woh : qkvh;
    __nv_bfloat16* l = (z == 3) ? wol : qkvl;
    const size_t dof = (z == 1) ? (size_t)KOFF * DM_ : (z == 2) ? (size_t)VOFF * DM_ : 0;

    __shared__ float ts[32][33];
    int tx = threadIdx.x, ty = threadIdx.y;
    for (int i = ty; i < 32; i += 8)
        ts[i][tx] = W[(size_t)(k0 + i) * N + n0 + tx];
    __syncthreads();
    for (int i = ty; i < 32; i += 8) {
        float x = ts[tx][i];
        __nv_bfloat16 hv = __float2bfloat16(x);
        __nv_bfloat16 lv = __float2bfloat16(x - __bfloat162float(hv));
        size_t o = dof + (size_t)(n0 + i) * DM_ + k0 + tx;
        h[o] = hv;
        l[o] = lv;
    }
}

// ====== persistent warp-MMA GEMM, 3-term compensated (EXACT r9 revert) ========
#define TILE_B  8192
#define STAGE_B (4 * TILE_B)
#define NSTG    3
#define GSMEM   (NSTG * STAGE_B)
#define GGRID   296

__global__ __launch_bounds__(256, 2) void gemm_mma(
    const __nv_bfloat16* __restrict__ Ah, const __nv_bfloat16* __restrict__ Al,
    const __nv_bfloat16* __restrict__ Bh, const __nv_bfloat16* __restrict__ Bl,
    const float* __restrict__ bias, int boff, float* __restrict__ C,
    int M, int N, int K)
{
    extern __shared__ char smem[];
    const uint32_t sb = smem_u32(smem);
    const int tid  = threadIdx.x;
    const int lane = tid & 31;
    const int wid  = tid >> 5;
    const int wm   = wid >> 2;
    const int wn   = wid & 3;
    const int K32 = K / 32;
    const int nx = N >> 7;
    const int ntiles = (M >> 7) * nx;

    const int lr0 = tid >> 2, lc = tid & 3;
    const int lr1 = lr0 + 64;
    const uint32_t so0 = (uint32_t)lr0 * 64 + ((uint32_t)(lc ^ ((lr0 >> 1) & 3)) << 4);
    const uint32_t so1 = (uint32_t)lr1 * 64 + ((uint32_t)(lc ^ ((lr1 >> 1) & 3)) << 4);
    const int ge = lc * 8;

    const int lrow = lane & 15, half = lane >> 4;
    const uint32_t lsw = (uint32_t)((lrow >> 1) & 3);
    const uint32_t a_row_off = (uint32_t)(wm * 64 + lrow) * 64;
    const uint32_t b_row_off = (uint32_t)(wn * 32 + lrow) * 64;

    for (int t = blockIdx.x; t < ntiles; t += gridDim.x) {
        const int m0 = (t / nx) << 7;
        const int n0 = (t % nx) << 7;

        float acc[4][4][4];
#pragma unroll
        for (int i = 0; i < 4; i++)
#pragma unroll
            for (int j = 0; j < 4; j++)
#pragma unroll
                for (int r = 0; r < 4; r++) acc[i][j][r] = 0.0f;

#define LOAD_STAGE(kt)                                                           \
    do {                                                                         \
        const int _k0 = (kt) * 32;                                               \
        const uint32_t _st = sb + ((kt) % NSTG) * STAGE_B;                       \
        size_t _a0 = (size_t)(m0 + lr0) * K + _k0 + ge;                          \
        size_t _a1 = (size_t)(m0 + lr1) * K + _k0 + ge;                          \
        size_t _b0 = (size_t)(n0 + lr0) * K + _k0 + ge;                          \
        size_t _b1 = (size_t)(n0 + lr1) * K + _k0 + ge;                          \
        cp_async16(_st + so0,              Ah + _a0);                            \
        cp_async16(_st + so1,              Ah + _a1);                            \
        cp_async16(_st + TILE_B + so0,     Al + _a0);                            \
        cp_async16(_st + TILE_B + so1,     Al + _a1);                            \
        cp_async16(_st + 2 * TILE_B + so0, Bh + _b0);                            \
        cp_async16(_st + 2 * TILE_B + so1, Bh + _b1);                            \
        cp_async16(_st + 3 * TILE_B + so0, Bl + _b0);                            \
        cp_async16(_st + 3 * TILE_B + so1, Bl + _b1);                            \
    } while (0)

        __syncthreads();
        LOAD_STAGE(0); CP_COMMIT();
        LOAD_STAGE(1); CP_COMMIT();

        for (int kt = 0; kt < K32; kt++) {
            CP_WAIT(1);
            __syncthreads();
            if (kt + 2 < K32) LOAD_STAGE(kt + 2);
            CP_COMMIT();

            const uint32_t st = sb + (kt % NSTG) * STAGE_B;
#pragma unroll
            for (int ks = 0; ks < 2; ks++) {
                const uint32_t cp0 = (((uint32_t)(ks * 2 + half)) ^ lsw) << 4;

                uint32_t bh[8], bl[8];
#pragma unroll
                for (int p = 0; p < 2; p++) {
                    uint32_t q0, q1, q2, q3;
                    ldsm_x4(st + 2 * TILE_B + b_row_off + p * 1024 + cp0, q0, q1, q2, q3);
                    bh[4 * p + 0] = q0; bh[4 * p + 1] = q2;
                    bh[4 * p + 2] = q1; bh[4 * p + 3] = q3;
                    ldsm_x4(st + 3 * TILE_B + b_row_off + p * 1024 + cp0, q0, q1, q2, q3);
                    bl[4 * p + 0] = q0; bl[4 * p + 1] = q2;
                    bl[4 * p + 2] = q1; bl[4 * p + 3] = q3;
                }

                uint32_t a[4][4];
#pragma unroll
                for (int i = 0; i < 4; i++)
                    ldsm_x4(st + a_row_off + i * 1024 + cp0,
                            a[i][0], a[i][1], a[i][2], a[i][3]);

#pragma unroll
                for (int i = 0; i < 4; i++)
#pragma unroll
                    for (int j = 0; j < 4; j++)
                        mma_bf16(acc[i][j], a[i], bh[2 * j], bh[2 * j + 1]);
#pragma unroll
                for (int i = 0; i < 4; i++)
#pragma unroll
                    for (int j = 0; j < 4; j++)
                        mma_bf16(acc[i][j], a[i], bl[2 * j], bl[2 * j + 1]);

#pragma unroll
                for (int i = 0; i < 4; i++)
                    ldsm_x4(st + TILE_B + a_row_off + i * 1024 + cp0,
                            a[i][0], a[i][1], a[i][2], a[i][3]);
#pragma unroll
                for (int i = 0; i < 4; i++)
#pragma unroll
                    for (int j = 0; j < 4; j++)
                        mma_bf16(acc[i][j], a[i], bh[2 * j], bh[2 * j + 1]);
            }
        }
#undef LOAD_STAGE

#pragma unroll
        for (int i = 0; i < 4; i++) {
            const int row = m0 + wm * 64 + i * 16 + (lane >> 2);
#pragma unroll
            for (int j = 0; j < 4; j++) {
                const int col = n0 + wn * 32 + j * 8 + (lane & 3) * 2;
                float b0 = 0.f, b1 = 0.f;
                const int bi = col - boff;
                if (bias && bi >= 0) { b0 = bias[bi]; b1 = bias[bi + 1]; }
                float2 v0, v1;
                v0.x = acc[i][j][0] + b0; v0.y = acc[i][j][1] + b1;
                v1.x = acc[i][j][2] + b0; v1.y = acc[i][j][3] + b1;
                *(float2*)(C + (size_t)row * N + col)       = v0;
                *(float2*)(C + (size_t)(row + 8) * N + col) = v1;
            }
        }
    }
}

// ====== RoPE + scale + bf16 hi/lo split of q,k,v out of fused buffer ==========
__global__ void rope_split_kernel(const float* __restrict__ qkv,
                                  const float* __restrict__ cosb,
                                  const float* __restrict__ sinb,
                                  __nv_bfloat16* __restrict__ qh, __nv_bfloat16* __restrict__ ql,
                                  __nv_bfloat16* __restrict__ kh, __nv_bfloat16* __restrict__ kl,
                                  __nv_bfloat16* __restrict__ vh, __nv_bfloat16* __restrict__ vl)
{
    int idx = blockIdx.x * blockDim.x + threadIdx.x;
    if (idx >= B_ * S_ * 48 * 32) return;
    int d  = idx & 31;
    int hh = (idx >> 5) % 48;
    int r  = idx / (32 * 48);

    const float* cp = cosb + (size_t)r * HD_;
    const float* sp = sinb + (size_t)r * HD_;

    __nv_bfloat16 *dh, *dl;
    size_t doff;
    float x1, x2;
    if (hh < 32) {
        const float* p = qkv + (size_t)r * NQKV + hh * HD_;
        float a = p[d], b = p[d + 32];
        x1 = (a * cp[d]      - b * sp[d])      * 0.125f;
        x2 = (b * cp[d + 32] + a * sp[d + 32]) * 0.125f;
        dh = qh; dl = ql;
        doff = (size_t)r * DM_ + hh * HD_ + d;
    } else if (hh < 40) {
        int kvh = hh - 32;
        const float* p = qkv + (size_t)r * NQKV + KOFF + kvh * HD_;
        float a = p[d], b = p[d + 32];
        x1 = a * cp[d]      - b * sp[d];
        x2 = b * cp[d + 32] + a * sp[d + 32];
        dh = kh; dl = kl;
        int bb = r >> 11, s = r & (S_ - 1);
        doff = ((size_t)(bb * KV_ + kvh) * S_ + s) * HD_ + d;
    } else {
        int kvh = hh - 40;
        const float* p = qkv + (size_t)r * NQKV + VOFF + kvh * HD_;
        x1 = p[d]; x2 = p[d + 32];
        dh = vh; dl = vl;
        int bb = r >> 11, s = r & (S_ - 1);
        doff = ((size_t)(bb * KV_ + kvh) * S_ + s) * HD_ + d;
    }
    __nv_bfloat16 h1 = __float2bfloat16(x1);
    __nv_bfloat16 h2 = __float2bfloat16(x2);
    dh[doff]      = h1;
    dh[doff + 32] = h2;
    dl[doff]      = __float2bfloat16(x1 - __bfloat162float(h1));
    dl[doff + 32] = __float2bfloat16(x2 - __bfloat162float(h2));
}

// =========== tensor-core flash attention (3-term split-bf16) ==================
// q-tile 64 (4 warps x 16 rows), kv-tile 32, 4 CTAs/SM.
// smem: Qh(8K) Ql(8K) | 2 stages x [Kh Kl Vh Vl](4K each) = 48 KB.
#define AQ_L   8192
#define AKV0   16384
#define AKV_ST 16384
#define ASMEM  49152

__global__ __launch_bounds__(128, 4) void attn_mma(
    const __nv_bfloat16* __restrict__ qh, const __nv_bfloat16* __restrict__ ql,
    const __nv_bfloat16* __restrict__ kh, const __nv_bfloat16* __restrict__ kl,
    const __nv_bfloat16* __restrict__ vh, const __nv_bfloat16* __restrict__ vl,
    __nv_bfloat16* __restrict__ oh, __nv_bfloat16* __restrict__ ol)
{
    extern __shared__ char smem[];
    const uint32_t sb = smem_u32(smem);
    const int tid  = threadIdx.x;
    const int lane = tid & 31;
    const int warp = tid >> 5;        // 0..3
    const int wr0  = warp * 16;
    const int m0 = (gridDim.x - 1 - blockIdx.x) * 64;    // heavy tiles first
    const int h  = blockIdx.y;
    const int b  = blockIdx.z;
    const int kvh = h >> 2;

    const size_t kvbase = (size_t)(b * KV_ + kvh) * S_ * HD_;

    // ---- stage Q (hi+lo): 64 rows x 128B each buffer ---------------------------
    {
        const size_t qg = (size_t)(b * S_ + m0) * DM_ + h * HD_;
#pragma unroll
        for (int i = 0; i < 4; i++) {
            int c = tid + 128 * i;          // 0..511
            int row = c >> 3, u = c & 7;
            uint32_t ad = sb + row * 128 + (((uint32_t)(u ^ (row & 7))) << 4);
            cp_async16(ad,          qh + qg + (size_t)row * DM_ + u * 8);
            cp_async16(ad + AQ_L,   ql + qg + (size_t)row * DM_ + u * 8);
        }
    }
    CP_COMMIT();

    const int NT = (m0 >> 5) + 2;

    // kv tile (32 rows): 4 buffers x 4KB; 2 chunks per thread per buffer
#define LOAD_KV(t)                                                                \
    do {                                                                          \
        const int _j0 = (t) * 32;                                                 \
        const uint32_t _st = sb + AKV0 + ((t) & 1) * AKV_ST;                      \
        _Pragma("unroll")                                                         \
        for (int _i = 0; _i < 2; _i++) {                                          \
            int _c = tid * 2 + _i;                                                \
            int _r = _c >> 3, _u = _c & 7;                                        \
            uint32_t _ad = _st + _r * 128 + (((uint32_t)(_u ^ (_r & 7))) << 4);   \
            size_t _g = kvbase + (size_t)(_j0 + _r) * HD_ + _u * 8;               \
            cp_async16(_ad,          kh + _g);                                    \
            cp_async16(_ad + 4096,   kl + _g);                                    \
            cp_async16(_ad + 8192,   vh + _g);                                    \
            cp_async16(_ad + 12288,  vl + _g);                                    \
        }                                                                         \
    } while (0)

    LOAD_KV(0);
    CP_COMMIT();

    CP_WAIT(1);
    __syncthreads();

    // ---- Q fragments (A, m16k16 x 4 ksteps) ------------------------------------
    uint32_t Qh_[4][4], Ql_[4][4];
    {
        const int row = wr0 + (lane & 15);
#pragma unroll
        for (int kk = 0; kk < 4; kk++) {
            uint32_t u = (uint32_t)(kk * 2 + (lane >> 4));
            uint32_t ad = sb + row * 128 + ((u ^ (uint32_t)(row & 7)) << 4);
            ldsm_x4(ad,        Qh_[kk][0], Qh_[kk][1], Qh_[kk][2], Qh_[kk][3]);
            ldsm_x4(ad + AQ_L, Ql_[kk][0], Ql_[kk][1], Ql_[kk][2], Ql_[kk][3]);
        }
    }

    float o[8][4];
#pragma unroll
    for (int d = 0; d < 8; d++)
#pragma unroll
        for (int r = 0; r < 4; r++) o[d][r] = 0.0f;
    float m1 = -1e30f, m2 = -1e30f, l1 = 0.0f, l2 = 0.0f;

    const int row1 = m0 + wr0 + (lane >> 2);
    const int row2 = row1 + 8;

    for (int t = 0; t < NT; t++) {
        CP_WAIT(0);
        __syncthreads();
        if (t + 1 < NT) LOAD_KV(t + 1);
        CP_COMMIT();

        const int j0 = t * 32;
        if (j0 <= m0 + wr0 + 15) {
            const uint32_t st = sb + AKV0 + (t & 1) * AKV_ST;

            // ---- S = Q K^T (3-term); K hi/lo share one fragment window ---------
            float s[4][4];
#pragma unroll
            for (int n = 0; n < 4; n++)
#pragma unroll
                for (int r = 0; r < 4; r++) s[n][r] = 0.0f;

#pragma unroll
            for (int np = 0; np < 2; np++) {
                const int krow = np * 16 + (lane & 15);
#pragma unroll
                for (int kk = 0; kk < 4; kk++) {
                    uint32_t u = (uint32_t)(kk * 2 + (lane >> 4));
                    uint32_t ad = st + krow * 128 + ((u ^ (uint32_t)(krow & 7)) << 4);
                    uint32_t f0, f1, f2, f3;
                    ldsm_x4(ad, f0, f1, f2, f3);            // Kh fragment
                    mma_bf16(s[2 * np],     Qh_[kk], f0, f2);
                    mma_bf16(s[2 * np + 1], Qh_[kk], f1, f3);
                    mma_bf16(s[2 * np],     Ql_[kk], f0, f2);
                    mma_bf16(s[2 * np + 1], Ql_[kk], f1, f3);
                    ldsm_x4(ad + 4096, f0, f1, f2, f3);     // Kl fragment (reuse regs)
                    mma_bf16(s[2 * np],     Qh_[kk], f0, f2);
                    mma_bf16(s[2 * np + 1], Qh_[kk], f1, f3);
                }
            }

            if (j0 + 31 > m0 + wr0) {
#pragma unroll
                for (int n = 0; n < 4; n++) {
                    const int col = j0 + n * 8 + ((lane & 3) << 1);
                    if (col     > row1) s[n][0] = -1e30f;
                    if (col + 1 > row1) s[n][1] = -1e30f;
                    if (col     > row2) s[n][2] = -1e30f;
                    if (col + 1 > row2) s[n][3] = -1e30f;
                }
            }

            float mx1 = -1e30f, mx2 = -1e30f;
#pragma unroll
            for (int n = 0; n < 4; n++) {
                mx1 = fmaxf(mx1, fmaxf(s[n][0], s[n][1]));
                mx2 = fmaxf(mx2, fmaxf(s[n][2], s[n][3]));
            }
            mx1 = fmaxf(mx1, __shfl_xor_sync(0xffffffff, mx1, 1));
            mx1 = fmaxf(mx1, __shfl_xor_sync(0xffffffff, mx1, 2));
            mx2 = fmaxf(mx2, __shfl_xor_sync(0xffffffff, mx2, 1));
            mx2 = fmaxf(mx2, __shfl_xor_sync(0xffffffff, mx2, 2));

            const float M1 = fmaxf(m1, mx1), M2 = fmaxf(m2, mx2);
            const float c1 = __expf(m1 - M1), c2 = __expf(m2 - M2);
            float ls1 = 0.0f, ls2 = 0.0f;
#pragma unroll
            for (int n = 0; n < 4; n++) {
                s[n][0] = __expf(s[n][0] - M1); ls1 += s[n][0];
                s[n][1] = __expf(s[n][1] - M1); ls1 += s[n][1];
                s[n][2] = __expf(s[n][2] - M2); ls2 += s[n][2];
                s[n][3] = __expf(s[n][3] - M2); ls2 += s[n][3];
            }
            ls1 += __shfl_xor_sync(0xffffffff, ls1, 1);
            ls1 += __shfl_xor_sync(0xffffffff, ls1, 2);
            ls2 += __shfl_xor_sync(0xffffffff, ls2, 1);
            ls2 += __shfl_xor_sync(0xffffffff, ls2, 2);
            l1 = l1 * c1 + ls1;  l2 = l2 * c2 + ls2;
            m1 = M1;             m2 = M2;
#pragma unroll
            for (int d = 0; d < 8; d++) {
                o[d][0] *= c1; o[d][1] *= c1;
                o[d][2] *= c2; o[d][3] *= c2;
            }

            // ---- P -> bf16 hi/lo A-fragments ------------------------------------
            uint32_t ph[2][4], pl[2][4];
#pragma unroll
            for (int jj = 0; jj < 2; jj++) {
#pragma unroll
                for (int q = 0; q < 4; q++) {
                    const int n = 2 * jj + (q >> 1);
                    const int r = (q & 1) * 2;
                    float a = s[n][r], bq = s[n][r + 1];
                    __nv_bfloat16 ha = __float2bfloat16(a);
                    __nv_bfloat16 hb = __float2bfloat16(bq);
                    ph[jj][q] = bpack(ha, hb);
                    pl[jj][q] = bpack(__float2bfloat16(a - __bfloat162float(ha)),
                                      __float2bfloat16(bq - __bfloat162float(hb)));
                }
            }

            // ---- O += P V (3-term); V hi/lo share one fragment window -----------
#pragma unroll
            for (int dg = 0; dg < 4; dg++) {
#pragma unroll
                for (int jj = 0; jj < 2; jj++) {
                    const int vrow = jj * 16 + (lane & 15);
                    uint32_t u = (uint32_t)(dg * 2 + (lane >> 4));
                    uint32_t ad = st + 8192 + vrow * 128 + ((u ^ (uint32_t)(vrow & 7)) << 4);
                    uint32_t f0, f1, f2, f3;
                    ldsm_x4t(ad, f0, f1, f2, f3);           // Vh fragment
                    mma_bf16(o[2 * dg],     ph[jj], f0, f1);
                    mma_bf16(o[2 * dg + 1], ph[jj], f2, f3);
                    mma_bf16(o[2 * dg],     pl[jj], f0, f1);
                    mma_bf16(o[2 * dg + 1], pl[jj], f2, f3);
                    ldsm_x4t(ad + 4096, f0, f1, f2, f3);    // Vl fragment (reuse regs)
                    mma_bf16(o[2 * dg],     ph[jj], f0, f1);
                    mma_bf16(o[2 * dg + 1], ph[jj], f2, f3);
                }
            }
        }
    }
#undef LOAD_KV

    const float inv1 = 1.0f / l1;
    const float inv2 = 1.0f / l2;
#pragma unroll
    for (int d = 0; d < 8; d++) {
        const int col = h * HD_ + d * 8 + ((lane & 3) << 1);
        {
            size_t ad = (size_t)(b * S_ + row1) * DM_ + col;
            float x0 = o[d][0] * inv1, x1 = o[d][1] * inv1;
            __nv_bfloat16 h0 = __float2bfloat16(x0);
            __nv_bfloat16 h1 = __float2bfloat16(x1);
            *(uint32_t*)(oh + ad) = bpack(h0, h1);
            *(uint32_t*)(ol + ad) = bpack(__float2bfloat16(x0 - __bfloat162float(h0)),
                                          __float2bfloat16(x1 - __bfloat162float(h1)));
        }
        {
            size_t ad = (size_t)(b * S_ + row2) * DM_ + col;
            float x0 = o[d][2] * inv2, x1 = o[d][3] * inv2;
            __nv_bfloat16 h0 = __float2bfloat16(x0);
            __nv_bfloat16 h1 = __float2bfloat16(x1);
            *(uint32_t*)(oh + ad) = bpack(h0, h1);
            *(uint32_t*)(ol + ad) = bpack(__float2bfloat16(x0 - __bfloat162float(h0)),
                                          __float2bfloat16(x1 - __bfloat162float(h1)));
        }
    }
}

// ================================ launch ======================================
extern "C" void kernel_launch(void* const* d_in, const int* in_sizes, int n_in,
                              void* d_out, int out_size)
{
    const float* hs    = (const float*)d_in[0];
    const float* cosb  = (const float*)d_in[2];
    const float* sinb  = (const float*)d_in[3];
    const float* W_q   = (const float*)d_in[4];
    const float* W_k   = (const float*)d_in[5];
    const float* W_v   = (const float*)d_in[6];
    const float* b_v   = (const float*)d_in[7];
    const float* W_o   = (const float*)d_in[8];
    const float* b_o   = (const float*)d_in[9];
    float* out = (float*)d_out;

    float* qkv;
    cudaGetSymbolAddress((void**)&qkv, g_qkv);
    __nv_bfloat16 *hsh, *hsl, *aoh, *aol, *wqkvh, *wqkvl, *woh, *wol;
    __nv_bfloat16 *qhp, *qlp, *khp, *klp, *vhp, *vlp;
    cudaGetSymbolAddress((void**)&hsh, g_hsh);
    cudaGetSymbolAddress((void**)&hsl, g_hsl);
    cudaGetSymbolAddress((void**)&aoh, g_aoh);
    cudaGetSymbolAddress((void**)&aol, g_aol);
    cudaGetSymbolAddress((void**)&wqkvh, g_wqkvh);
    cudaGetSymbolAddress((void**)&wqkvl, g_wqkvl);
    cudaGetSymbolAddress((void**)&woh, g_woh);
    cudaGetSymbolAddress((void**)&wol, g_wol);
    cudaGetSymbolAddress((void**)&qhp, g_qh);
    cudaGetSymbolAddress((void**)&qlp, g_ql);
    cudaGetSymbolAddress((void**)&khp, g_kh);
    cudaGetSymbolAddress((void**)&klp, g_kl);
    cudaGetSymbolAddress((void**)&vhp, g_vh);
    cudaGetSymbolAddress((void**)&vlp, g_vl);

    cudaFuncSetAttribute(gemm_mma,
                         cudaFuncAttributeMaxDynamicSharedMemorySize, GSMEM);
    cudaFuncSetAttribute(attn_mma,
                         cudaFuncAttributeMaxDynamicSharedMemorySize, ASMEM);

    const int M = B_ * S_;       // 4096

    // launch 0: ALL prep (weights + activations) in one grid
    prep_all<<<dim3(128, 64, 5), dim3(32, 8)>>>(
        hs, W_q, W_k, W_v, W_o, hsh, hsl, wqkvh, wqkvl, woh, wol);

    // launch 1: fused QKV projection (persistent)
    gemm_mma<<<GGRID, 256, GSMEM>>>(
        hsh, hsl, wqkvh, wqkvl, b_v, VOFF, qkv, M, NQKV, DM_);

    // launch 2: RoPE + scale + split to attention operand layouts
    {
        int total = B_ * S_ * 48 * 32;
        rope_split_kernel<<<(total + 255) / 256, 256>>>(
            qkv, cosb, sinb, qhp, qlp, khp, klp, vhp, vlp);
    }

    // launch 3 (PROFILED): tensor-core flash attention, 4 CTAs/SM
    attn_mma<<<dim3(S_ / 64, H_, B_), 128, ASMEM>>>(
        qhp, qlp, khp, klp, vhp, vlp, aoh, aol);

    // launch 4: O projection (persistent)
    gemm_mma<<<GGRID, 256, GSMEM>>>(
        aoh, aol, woh, wol, b_o, 0, out, M, DM_, DM_);
}

// round 12
// speedup vs baseline: 1.6358x; 1.0067x over previous
#include <cuda_runtime.h>
#include <cuda_bf16.h>
#include <cstdint>

#define B_   2
#define S_   2048
#define DM_  2048
#define H_   32
#define KV_  8
#define HD_  64
#define GRP_ (H_ / KV_)   // 4
#define NQKV 3072          // fused QKV width: 2048 q | 512 k | 512 v
#define KOFF 2048
#define VOFF 2560

// ============================ PTX helpers (base sm_103 safe) ==================
__device__ __forceinline__ uint32_t smem_u32(const void* p) {
    uint32_t a;
    asm("{ .reg .u64 t; cvta.to.shared.u64 t, %1; cvt.u32.u64 %0, t; }"
        : "=r"(a) : "l"(p));
    return a;
}
__device__ __forceinline__ void cp_async16(uint32_t s, const void* g) {
    asm volatile("cp.async.cg.shared.global [%0], [%1], 16;" :: "r"(s), "l"(g));
}
#define CP_COMMIT() asm volatile("cp.async.commit_group;" ::: "memory")
#define CP_WAIT(n)  asm volatile("cp.async.wait_group %0;" :: "n"(n) : "memory")

__device__ __forceinline__ void ldsm_x4(uint32_t addr, uint32_t& r0, uint32_t& r1,
                                        uint32_t& r2, uint32_t& r3) {
    asm volatile("ldmatrix.sync.aligned.m8n8.x4.shared.b16 {%0,%1,%2,%3}, [%4];"
                 : "=r"(r0), "=r"(r1), "=r"(r2), "=r"(r3) : "r"(addr));
}
__device__ __forceinline__ void ldsm_x4t(uint32_t addr, uint32_t& r0, uint32_t& r1,
                                         uint32_t& r2, uint32_t& r3) {
    asm volatile("ldmatrix.sync.aligned.m8n8.x4.trans.shared.b16 {%0,%1,%2,%3}, [%4];"
                 : "=r"(r0), "=r"(r1), "=r"(r2), "=r"(r3) : "r"(addr));
}
__device__ __forceinline__ void mma_bf16(float* d, const uint32_t* a,
                                         uint32_t b0, uint32_t b1) {
    asm volatile("mma.sync.aligned.m16n8k16.row.col.f32.bf16.bf16.f32 "
                 "{%0,%1,%2,%3}, {%4,%5,%6,%7}, {%8,%9}, {%0,%1,%2,%3};"
                 : "+f"(d[0]), "+f"(d[1]), "+f"(d[2]), "+f"(d[3])
                 : "r"(a[0]), "r"(a[1]), "r"(a[2]), "r"(a[3]), "r"(b0), "r"(b1));
}
__device__ __forceinline__ uint32_t bpack(__nv_bfloat16 x, __nv_bfloat16 y) {
    __nv_bfloat162 t(x, y);
    return *reinterpret_cast<uint32_t*>(&t);
}
// d = {lo = bf16rn(lo_f), hi = bf16rn(hi_f)} in ONE cvt instruction
__device__ __forceinline__ uint32_t cvt_bf16x2(float hi_f, float lo_f) {
    uint32_t r;
    asm("cvt.rn.bf16x2.f32 %0, %1, %2;" : "=r"(r) : "f"(hi_f), "f"(lo_f));
    return r;
}
__device__ __forceinline__ float ex2f(float x) {
    float y;
    asm("ex2.approx.f32 %0, %1;" : "=f"(y) : "f"(x));
    return y;
}

// ============================ scratch =========================================
__device__ float g_qkv[(size_t)B_ * S_ * NQKV];          // 48 MB fused q|k|v

__device__ __nv_bfloat16 g_hsh[(size_t)B_ * S_ * DM_];   // activations hi/lo
__device__ __nv_bfloat16 g_hsl[(size_t)B_ * S_ * DM_];
__device__ __nv_bfloat16 g_aoh[(size_t)B_ * S_ * DM_];   // attn out hi/lo
__device__ __nv_bfloat16 g_aol[(size_t)B_ * S_ * DM_];
__device__ __nv_bfloat16 g_wqkvh[(size_t)NQKV * DM_];    // [N,K] fused weights
__device__ __nv_bfloat16 g_wqkvl[(size_t)NQKV * DM_];
__device__ __nv_bfloat16 g_woh[(size_t)DM_ * DM_];
__device__ __nv_bfloat16 g_wol[(size_t)DM_ * DM_];
// attention operands (bf16 hi/lo, post-RoPE, Q pre-scaled by log2(e)/8)
__device__ __nv_bfloat16 g_qh[(size_t)B_ * S_ * DM_];    // [row, h*64+d]
__device__ __nv_bfloat16 g_ql[(size_t)B_ * S_ * DM_];
__device__ __nv_bfloat16 g_kh[(size_t)B_ * KV_ * S_ * HD_]; // [b*KV+kvh][s][d]
__device__ __nv_bfloat16 g_kl[(size_t)B_ * KV_ * S_ * HD_];
__device__ __nv_bfloat16 g_vh[(size_t)B_ * KV_ * S_ * HD_];
__device__ __nv_bfloat16 g_vl[(size_t)B_ * KV_ * S_ * HD_];

// ====== ONE prep launch: weights transpose+split (z=0..3) + activations (z=4) =
__global__ void prep_all(const float* __restrict__ hs,
                         const float* __restrict__ Wq, const float* __restrict__ Wk,
                         const float* __restrict__ Wv, const float* __restrict__ Wo,
                         __nv_bfloat16* __restrict__ hsh, __nv_bfloat16* __restrict__ hsl,
                         __nv_bfloat16* __restrict__ qkvh, __nv_bfloat16* __restrict__ qkvl,
                         __nv_bfloat16* __restrict__ woh,  __nv_bfloat16* __restrict__ wol)
{
    const int z = blockIdx.z;
    const int tid = threadIdx.y * 32 + threadIdx.x;

    if (z == 4) {
        int bid = blockIdx.x + 128 * blockIdx.y;
        int i = bid * 256 + tid;
        float4 v = ((const float4*)hs)[i];
        __nv_bfloat16 h0 = __float2bfloat16(v.x);
        __nv_bfloat16 h1 = __float2bfloat16(v.y);
        __nv_bfloat16 h2 = __float2bfloat16(v.z);
        __nv_bfloat16 h3 = __float2bfloat16(v.w);
        __nv_bfloat16 l0 = __float2bfloat16(v.x - __bfloat162float(h0));
        __nv_bfloat16 l1 = __float2bfloat16(v.y - __bfloat162float(h1));
        __nv_bfloat16 l2 = __float2bfloat16(v.z - __bfloat162float(h2));
        __nv_bfloat16 l3 = __float2bfloat16(v.w - __bfloat162float(h3));
        ((__nv_bfloat162*)hsh)[2 * i]     = __nv_bfloat162(h0, h1);
        ((__nv_bfloat162*)hsh)[2 * i + 1] = __nv_bfloat162(h2, h3);
        ((__nv_bfloat162*)hsl)[2 * i]     = __nv_bfloat162(l0, l1);
        ((__nv_bfloat162*)hsl)[2 * i + 1] = __nv_bfloat162(l2, l3);
        return;
    }

    if (blockIdx.x >= 64) return;
    const int N = (z == 1 || z == 2) ? 512 : 2048;
    const int n0 = blockIdx.x * 32;
    if (n0 >= N) return;
    const int k0 = blockIdx.y * 32;
    const float* W = (z == 0) ? Wq : (z == 1) ? Wk : (z == 2) ? Wv : Wo;
    __nv_bfloat16* h = (z == 3) ? woh : qkvh;
    __nv_bfloat16* l = (z == 3) ? wol : qkvl;
    const size_t dof = (z == 1) ? (size_t)KOFF * DM_ : (z == 2) ? (size_t)VOFF * DM_ : 0;

    __shared__ float ts[32][33];
    int tx = threadIdx.x, ty = threadIdx.y;
    for (int i = ty; i < 32; i += 8)
        ts[i][tx] = W[(size_t)(k0 + i) * N + n0 + tx];
    __syncthreads();
    for (int i = ty; i < 32; i += 8) {
        float x = ts[tx][i];
        __nv_bfloat16 hv = __float2bfloat16(x);
        __nv_bfloat16 lv = __float2bfloat16(x - __bfloat162float(hv));
        size_t o = dof + (size_t)(n0 + i) * DM_ + k0 + tx;
        h[o] = hv;
        l[o] = lv;
    }
}

// ====== persistent warp-MMA GEMM, 3-term compensated (EXACT r11) ==============
#define TILE_B  8192
#define STAGE_B (4 * TILE_B)
#define NSTG    3
#define GSMEM   (NSTG * STAGE_B)
#define GGRID   296

__global__ __launch_bounds__(256, 2) void gemm_mma(
    const __nv_bfloat16* __restrict__ Ah, const __nv_bfloat16* __restrict__ Al,
    const __nv_bfloat16* __restrict__ Bh, const __nv_bfloat16* __restrict__ Bl,
    const float* __restrict__ bias, int boff, float* __restrict__ C,
    int M, int N, int K)
{
    extern __shared__ char smem[];
    const uint32_t sb = smem_u32(smem);
    const int tid  = threadIdx.x;
    const int lane = tid & 31;
    const int wid  = tid >> 5;
    const int wm   = wid >> 2;
    const int wn   = wid & 3;
    const int K32 = K / 32;
    const int nx = N >> 7;
    const int ntiles = (M >> 7) * nx;

    const int lr0 = tid >> 2, lc = tid & 3;
    const int lr1 = lr0 + 64;
    const uint32_t so0 = (uint32_t)lr0 * 64 + ((uint32_t)(lc ^ ((lr0 >> 1) & 3)) << 4);
    const uint32_t so1 = (uint32_t)lr1 * 64 + ((uint32_t)(lc ^ ((lr1 >> 1) & 3)) << 4);
    const int ge = lc * 8;

    const int lrow = lane & 15, half = lane >> 4;
    const uint32_t lsw = (uint32_t)((lrow >> 1) & 3);
    const uint32_t a_row_off = (uint32_t)(wm * 64 + lrow) * 64;
    const uint32_t b_row_off = (uint32_t)(wn * 32 + lrow) * 64;

    for (int t = blockIdx.x; t < ntiles; t += gridDim.x) {
        const int m0 = (t / nx) << 7;
        const int n0 = (t % nx) << 7;

        float acc[4][4][4];
#pragma unroll
        for (int i = 0; i < 4; i++)
#pragma unroll
            for (int j = 0; j < 4; j++)
#pragma unroll
                for (int r = 0; r < 4; r++) acc[i][j][r] = 0.0f;

#define LOAD_STAGE(kt)                                                           \
    do {                                                                         \
        const int _k0 = (kt) * 32;                                               \
        const uint32_t _st = sb + ((kt) % NSTG) * STAGE_B;                       \
        size_t _a0 = (size_t)(m0 + lr0) * K + _k0 + ge;                          \
        size_t _a1 = (size_t)(m0 + lr1) * K + _k0 + ge;                          \
        size_t _b0 = (size_t)(n0 + lr0) * K + _k0 + ge;                          \
        size_t _b1 = (size_t)(n0 + lr1) * K + _k0 + ge;                          \
        cp_async16(_st + so0,              Ah + _a0);                            \
        cp_async16(_st + so1,              Ah + _a1);                            \
        cp_async16(_st + TILE_B + so0,     Al + _a0);                            \
        cp_async16(_st + TILE_B + so1,     Al + _a1);                            \
        cp_async16(_st + 2 * TILE_B + so0, Bh + _b0);                            \
        cp_async16(_st + 2 * TILE_B + so1, Bh + _b1);                            \
        cp_async16(_st + 3 * TILE_B + so0, Bl + _b0);                            \
        cp_async16(_st + 3 * TILE_B + so1, Bl + _b1);                            \
    } while (0)

        __syncthreads();
        LOAD_STAGE(0); CP_COMMIT();
        LOAD_STAGE(1); CP_COMMIT();

        for (int kt = 0; kt < K32; kt++) {
            CP_WAIT(1);
            __syncthreads();
            if (kt + 2 < K32) LOAD_STAGE(kt + 2);
            CP_COMMIT();

            const uint32_t st = sb + (kt % NSTG) * STAGE_B;
#pragma unroll
            for (int ks = 0; ks < 2; ks++) {
                const uint32_t cp0 = (((uint32_t)(ks * 2 + half)) ^ lsw) << 4;

                uint32_t bh[8], bl[8];
#pragma unroll
                for (int p = 0; p < 2; p++) {
                    uint32_t q0, q1, q2, q3;
                    ldsm_x4(st + 2 * TILE_B + b_row_off + p * 1024 + cp0, q0, q1, q2, q3);
                    bh[4 * p + 0] = q0; bh[4 * p + 1] = q2;
                    bh[4 * p + 2] = q1; bh[4 * p + 3] = q3;
                    ldsm_x4(st + 3 * TILE_B + b_row_off + p * 1024 + cp0, q0, q1, q2, q3);
                    bl[4 * p + 0] = q0; bl[4 * p + 1] = q2;
                    bl[4 * p + 2] = q1; bl[4 * p + 3] = q3;
                }

                uint32_t a[4][4];
#pragma unroll
                for (int i = 0; i < 4; i++)
                    ldsm_x4(st + a_row_off + i * 1024 + cp0,
                            a[i][0], a[i][1], a[i][2], a[i][3]);

#pragma unroll
                for (int i = 0; i < 4; i++)
#pragma unroll
                    for (int j = 0; j < 4; j++)
                        mma_bf16(acc[i][j], a[i], bh[2 * j], bh[2 * j + 1]);
#pragma unroll
                for (int i = 0; i < 4; i++)
#pragma unroll
                    for (int j = 0; j < 4; j++)
                        mma_bf16(acc[i][j], a[i], bl[2 * j], bl[2 * j + 1]);

#pragma unroll
                for (int i = 0; i < 4; i++)
                    ldsm_x4(st + TILE_B + a_row_off + i * 1024 + cp0,
                            a[i][0], a[i][1], a[i][2], a[i][3]);
#pragma unroll
                for (int i = 0; i < 4; i++)
#pragma unroll
                    for (int j = 0; j < 4; j++)
                        mma_bf16(acc[i][j], a[i], bh[2 * j], bh[2 * j + 1]);
            }
        }
#undef LOAD_STAGE

#pragma unroll
        for (int i = 0; i < 4; i++) {
            const int row = m0 + wm * 64 + i * 16 + (lane >> 2);
#pragma unroll
            for (int j = 0; j < 4; j++) {
                const int col = n0 + wn * 32 + j * 8 + (lane & 3) * 2;
                float b0 = 0.f, b1 = 0.f;
                const int bi = col - boff;
                if (bias && bi >= 0) { b0 = bias[bi]; b1 = bias[bi + 1]; }
                float2 v0, v1;
                v0.x = acc[i][j][0] + b0; v0.y = acc[i][j][1] + b1;
                v1.x = acc[i][j][2] + b0; v1.y = acc[i][j][3] + b1;
                *(float2*)(C + (size_t)row * N + col)       = v0;
                *(float2*)(C + (size_t)(row + 8) * N + col) = v1;
            }
        }
    }
}

// ====== RoPE + scale + bf16 hi/lo split of q,k,v out of fused buffer ==========
// Q is pre-scaled by log2(e)/8 so attention softmax can use raw ex2.
#define QSCALE 0.1803368801111204f   // 0.125 * log2(e)

__global__ void rope_split_kernel(const float* __restrict__ qkv,
                                  const float* __restrict__ cosb,
                                  const float* __restrict__ sinb,
                                  __nv_bfloat16* __restrict__ qh, __nv_bfloat16* __restrict__ ql,
                                  __nv_bfloat16* __restrict__ kh, __nv_bfloat16* __restrict__ kl,
                                  __nv_bfloat16* __restrict__ vh, __nv_bfloat16* __restrict__ vl)
{
    int idx = blockIdx.x * blockDim.x + threadIdx.x;
    if (idx >= B_ * S_ * 48 * 32) return;
    int d  = idx & 31;
    int hh = (idx >> 5) % 48;
    int r  = idx / (32 * 48);

    const float* cp = cosb + (size_t)r * HD_;
    const float* sp = sinb + (size_t)r * HD_;

    __nv_bfloat16 *dh, *dl;
    size_t doff;
    float x1, x2;
    if (hh < 32) {
        const float* p = qkv + (size_t)r * NQKV + hh * HD_;
        float a = p[d], b = p[d + 32];
        x1 = (a * cp[d]      - b * sp[d])      * QSCALE;
        x2 = (b * cp[d + 32] + a * sp[d + 32]) * QSCALE;
        dh = qh; dl = ql;
        doff = (size_t)r * DM_ + hh * HD_ + d;
    } else if (hh < 40) {
        int kvh = hh - 32;
        const float* p = qkv + (size_t)r * NQKV + KOFF + kvh * HD_;
        float a = p[d], b = p[d + 32];
        x1 = a * cp[d]      - b * sp[d];
        x2 = b * cp[d + 32] + a * sp[d + 32];
        dh = kh; dl = kl;
        int bb = r >> 11, s = r & (S_ - 1);
        doff = ((size_t)(bb * KV_ + kvh) * S_ + s) * HD_ + d;
    } else {
        int kvh = hh - 40;
        const float* p = qkv + (size_t)r * NQKV + VOFF + kvh * HD_;
        x1 = p[d]; x2 = p[d + 32];
        dh = vh; dl = vl;
        int bb = r >> 11, s = r & (S_ - 1);
        doff = ((size_t)(bb * KV_ + kvh) * S_ + s) * HD_ + d;
    }
    __nv_bfloat16 h1 = __float2bfloat16(x1);
    __nv_bfloat16 h2 = __float2bfloat16(x2);
    dh[doff]      = h1;
    dh[doff + 32] = h2;
    dl[doff]      = __float2bfloat16(x1 - __bfloat162float(h1));
    dl[doff + 32] = __float2bfloat16(x2 - __bfloat162float(h2));
}

// =========== tensor-core flash attention (3-term split-bf16) ==================
// q-tile 64 (4 warps x 16 rows), kv-tile 32, 4 CTAs/SM. Scores in log2 domain.
#define AQ_L   8192
#define AKV0   16384
#define AKV_ST 16384
#define ASMEM  49152

__global__ __launch_bounds__(128, 4) void attn_mma(
    const __nv_bfloat16* __restrict__ qh, const __nv_bfloat16* __restrict__ ql,
    const __nv_bfloat16* __restrict__ kh, const __nv_bfloat16* __restrict__ kl,
    const __nv_bfloat16* __restrict__ vh, const __nv_bfloat16* __restrict__ vl,
    __nv_bfloat16* __restrict__ oh, __nv_bfloat16* __restrict__ ol)
{
    extern __shared__ char smem[];
    const uint32_t sb = smem_u32(smem);
    const int tid  = threadIdx.x;
    const int lane = tid & 31;
    const int warp = tid >> 5;        // 0..3
    const int wr0  = warp * 16;
    const int m0 = (gridDim.x - 1 - blockIdx.x) * 64;    // heavy tiles first
    const int h  = blockIdx.y;
    const int b  = blockIdx.z;
    const int kvh = h >> 2;

    const size_t kvbase = (size_t)(b * KV_ + kvh) * S_ * HD_;

    {
        const size_t qg = (size_t)(b * S_ + m0) * DM_ + h * HD_;
#pragma unroll
        for (int i = 0; i < 4; i++) {
            int c = tid + 128 * i;
            int row = c >> 3, u = c & 7;
            uint32_t ad = sb + row * 128 + (((uint32_t)(u ^ (row & 7))) << 4);
            cp_async16(ad,          qh + qg + (size_t)row * DM_ + u * 8);
            cp_async16(ad + AQ_L,   ql + qg + (size_t)row * DM_ + u * 8);
        }
    }
    CP_COMMIT();

    const int NT = (m0 >> 5) + 2;

#define LOAD_KV(t)                                                                \
    do {                                                                          \
        const int _j0 = (t) * 32;                                                 \
        const uint32_t _st = sb + AKV0 + ((t) & 1) * AKV_ST;                      \
        _Pragma("unroll")                                                         \
        for (int _i = 0; _i < 2; _i++) {                                          \
            int _c = tid * 2 + _i;                                                \
            int _r = _c >> 3, _u = _c & 7;                                        \
            uint32_t _ad = _st + _r * 128 + (((uint32_t)(_u ^ (_r & 7))) << 4);   \
            size_t _g = kvbase + (size_t)(_j0 + _r) * HD_ + _u * 8;               \
            cp_async16(_ad,          kh + _g);                                    \
            cp_async16(_ad + 4096,   kl + _g);                                    \
            cp_async16(_ad + 8192,   vh + _g);                                    \
            cp_async16(_ad + 12288,  vl + _g);                                    \
        }                                                                         \
    } while (0)

    LOAD_KV(0);
    CP_COMMIT();

    CP_WAIT(1);
    __syncthreads();

    uint32_t Qh_[4][4], Ql_[4][4];
    {
        const int row = wr0 + (lane & 15);
#pragma unroll
        for (int kk = 0; kk < 4; kk++) {
            uint32_t u = (uint32_t)(kk * 2 + (lane >> 4));
            uint32_t ad = sb + row * 128 + ((u ^ (uint32_t)(row & 7)) << 4);
            ldsm_x4(ad,        Qh_[kk][0], Qh_[kk][1], Qh_[kk][2], Qh_[kk][3]);
            ldsm_x4(ad + AQ_L, Ql_[kk][0], Ql_[kk][1], Ql_[kk][2], Ql_[kk][3]);
        }
    }

    float o[8][4];
#pragma unroll
    for (int d = 0; d < 8; d++)
#pragma unroll
        for (int r = 0; r < 4; r++) o[d][r] = 0.0f;
    float m1 = -1e30f, m2 = -1e30f, l1 = 0.0f, l2 = 0.0f;

    const int row1 = m0 + wr0 + (lane >> 2);
    const int row2 = row1 + 8;

    for (int t = 0; t < NT; t++) {
        CP_WAIT(0);
        __syncthreads();
        if (t + 1 < NT) LOAD_KV(t + 1);
        CP_COMMIT();

        const int j0 = t * 32;
        if (j0 <= m0 + wr0 + 15) {
            const uint32_t st = sb + AKV0 + (t & 1) * AKV_ST;

            // ---- S = Q K^T (3-term, log2 domain) --------------------------------
            float s[4][4];
#pragma unroll
            for (int n = 0; n < 4; n++)
#pragma unroll
                for (int r = 0; r < 4; r++) s[n][r] = 0.0f;

#pragma unroll
            for (int np = 0; np < 2; np++) {
                const int krow = np * 16 + (lane & 15);
#pragma unroll
                for (int kk = 0; kk < 4; kk++) {
                    uint32_t u = (uint32_t)(kk * 2 + (lane >> 4));
                    uint32_t ad = st + krow * 128 + ((u ^ (uint32_t)(krow & 7)) << 4);
                    uint32_t f0, f1, f2, f3;
                    ldsm_x4(ad, f0, f1, f2, f3);            // Kh fragment
                    mma_bf16(s[2 * np],     Qh_[kk], f0, f2);
                    mma_bf16(s[2 * np + 1], Qh_[kk], f1, f3);
                    mma_bf16(s[2 * np],     Ql_[kk], f0, f2);
                    mma_bf16(s[2 * np + 1], Ql_[kk], f1, f3);
                    ldsm_x4(ad + 4096, f0, f1, f2, f3);     // Kl fragment (reuse regs)
                    mma_bf16(s[2 * np],     Qh_[kk], f0, f2);
                    mma_bf16(s[2 * np + 1], Qh_[kk], f1, f3);
                }
            }

            if (j0 + 31 > m0 + wr0) {
#pragma unroll
                for (int n = 0; n < 4; n++) {
                    const int col = j0 + n * 8 + ((lane & 3) << 1);
                    if (col     > row1) s[n][0] = -1e30f;
                    if (col + 1 > row1) s[n][1] = -1e30f;
                    if (col     > row2) s[n][2] = -1e30f;
                    if (col + 1 > row2) s[n][3] = -1e30f;
                }
            }

            // ---- online softmax (base-2) ----------------------------------------
            float mx1 = -1e30f, mx2 = -1e30f;
#pragma unroll
            for (int n = 0; n < 4; n++) {
                mx1 = fmaxf(mx1, fmaxf(s[n][0], s[n][1]));
                mx2 = fmaxf(mx2, fmaxf(s[n][2], s[n][3]));
            }
            mx1 = fmaxf(mx1, __shfl_xor_sync(0xffffffff, mx1, 1));
            mx1 = fmaxf(mx1, __shfl_xor_sync(0xffffffff, mx1, 2));
            mx2 = fmaxf(mx2, __shfl_xor_sync(0xffffffff, mx2, 1));
            mx2 = fmaxf(mx2, __shfl_xor_sync(0xffffffff, mx2, 2));

            const float M1 = fmaxf(m1, mx1), M2 = fmaxf(m2, mx2);
            const float c1 = ex2f(m1 - M1), c2 = ex2f(m2 - M2);
            float ls1 = 0.0f, ls2 = 0.0f;
#pragma unroll
            for (int n = 0; n < 4; n++) {
                s[n][0] = ex2f(s[n][0] - M1); ls1 += s[n][0];
                s[n][1] = ex2f(s[n][1] - M1); ls1 += s[n][1];
                s[n][2] = ex2f(s[n][2] - M2); ls2 += s[n][2];
                s[n][3] = ex2f(s[n][3] - M2); ls2 += s[n][3];
            }
            ls1 += __shfl_xor_sync(0xffffffff, ls1, 1);
            ls1 += __shfl_xor_sync(0xffffffff, ls1, 2);
            ls2 += __shfl_xor_sync(0xffffffff, ls2, 1);
            ls2 += __shfl_xor_sync(0xffffffff, ls2, 2);
            l1 = l1 * c1 + ls1;  l2 = l2 * c2 + ls2;
            m1 = M1;             m2 = M2;
#pragma unroll
            for (int d = 0; d < 8; d++) {
                o[d][0] *= c1; o[d][1] *= c1;
                o[d][2] *= c2; o[d][3] *= c2;
            }

            // ---- P -> bf16 hi/lo A-fragments (packed cvt, exact same values) ----
            uint32_t ph[2][4], pl[2][4];
#pragma unroll
            for (int jj = 0; jj < 2; jj++) {
#pragma unroll
                for (int q = 0; q < 4; q++) {
                    const int n = 2 * jj + (q >> 1);
                    const int r = (q & 1) * 2;
                    const float a = s[n][r], bq = s[n][r + 1];
                    const uint32_t hp = cvt_bf16x2(bq, a);   // {lo=bf16(a), hi=bf16(bq)}
                    const float fa = __uint_as_float(hp << 16);
                    const float fb = __uint_as_float(hp & 0xffff0000u);
                    ph[jj][q] = hp;
                    pl[jj][q] = cvt_bf16x2(bq - fb, a - fa);
                }
            }

            // ---- O += P V (3-term); V hi/lo share one fragment window -----------
#pragma unroll
            for (int dg = 0; dg < 4; dg++) {
#pragma unroll
                for (int jj = 0; jj < 2; jj++) {
                    const int vrow = jj * 16 + (lane & 15);
                    uint32_t u = (uint32_t)(dg * 2 + (lane >> 4));
                    uint32_t ad = st + 8192 + vrow * 128 + ((u ^ (uint32_t)(vrow & 7)) << 4);
                    uint32_t f0, f1, f2, f3;
                    ldsm_x4t(ad, f0, f1, f2, f3);           // Vh fragment
                    mma_bf16(o[2 * dg],     ph[jj], f0, f1);
                    mma_bf16(o[2 * dg + 1], ph[jj], f2, f3);
                    mma_bf16(o[2 * dg],     pl[jj], f0, f1);
                    mma_bf16(o[2 * dg + 1], pl[jj], f2, f3);
                    ldsm_x4t(ad + 4096, f0, f1, f2, f3);    // Vl fragment (reuse regs)
                    mma_bf16(o[2 * dg],     ph[jj], f0, f1);
                    mma_bf16(o[2 * dg + 1], ph[jj], f2, f3);
                }
            }
        }
    }
#undef LOAD_KV

    const float inv1 = 1.0f / l1;
    const float inv2 = 1.0f / l2;
#pragma unroll
    for (int d = 0; d < 8; d++) {
        const int col = h * HD_ + d * 8 + ((lane & 3) << 1);
        {
            size_t ad = (size_t)(b * S_ + row1) * DM_ + col;
            const float x0 = o[d][0] * inv1, x1 = o[d][1] * inv1;
            const uint32_t hp = cvt_bf16x2(x1, x0);
            const float f0 = __uint_as_float(hp << 16);
            const float f1 = __uint_as_float(hp & 0xffff0000u);
            *(uint32_t*)(oh + ad) = hp;
            *(uint32_t*)(ol + ad) = cvt_bf16x2(x1 - f1, x0 - f0);
        }
        {
            size_t ad = (size_t)(b * S_ + row2) * DM_ + col;
            const float x0 = o[d][2] * inv2, x1 = o[d][3] * inv2;
            const uint32_t hp = cvt_bf16x2(x1, x0);
            const float f0 = __uint_as_float(hp << 16);
            const float f1 = __uint_as_float(hp & 0xffff0000u);
            *(uint32_t*)(oh + ad) = hp;
            *(uint32_t*)(ol + ad) = cvt_bf16x2(x1 - f1, x0 - f0);
        }
    }
}

// ================================ launch ======================================
extern "C" void kernel_launch(void* const* d_in, const int* in_sizes, int n_in,
                              void* d_out, int out_size)
{
    const float* hs    = (const float*)d_in[0];
    const float* cosb  = (const float*)d_in[2];
    const float* sinb  = (const float*)d_in[3];
    const float* W_q   = (const float*)d_in[4];
    const float* W_k   = (const float*)d_in[5];
    const float* W_v   = (const float*)d_in[6];
    const float* b_v   = (const float*)d_in[7];
    const float* W_o   = (const float*)d_in[8];
    const float* b_o   = (const float*)d_in[9];
    float* out = (float*)d_out;

    float* qkv;
    cudaGetSymbolAddress((void**)&qkv, g_qkv);
    __nv_bfloat16 *hsh, *hsl, *aoh, *aol, *wqkvh, *wqkvl, *woh, *wol;
    __nv_bfloat16 *qhp, *qlp, *khp, *klp, *vhp, *vlp;
    cudaGetSymbolAddress((void**)&hsh, g_hsh);
    cudaGetSymbolAddress((void**)&hsl, g_hsl);
    cudaGetSymbolAddress((void**)&aoh, g_aoh);
    cudaGetSymbolAddress((void**)&aol, g_aol);
    cudaGetSymbolAddress((void**)&wqkvh, g_wqkvh);
    cudaGetSymbolAddress((void**)&wqkvl, g_wqkvl);
    cudaGetSymbolAddress((void**)&woh, g_woh);
    cudaGetSymbolAddress((void**)&wol, g_wol);
    cudaGetSymbolAddress((void**)&qhp, g_qh);
    cudaGetSymbolAddress((void**)&qlp, g_ql);
    cudaGetSymbolAddress((void**)&khp, g_kh);
    cudaGetSymbolAddress((void**)&klp, g_kl);
    cudaGetSymbolAddress((void**)&vhp, g_vh);
    cudaGetSymbolAddress((void**)&vlp, g_vl);

    cudaFuncSetAttribute(gemm_mma,
                         cudaFuncAttributeMaxDynamicSharedMemorySize, GSMEM);
    cudaFuncSetAttribute(attn_mma,
                         cudaFuncAttributeMaxDynamicSharedMemorySize, ASMEM);

    const int M = B_ * S_;       // 4096

    // launch 0: ALL prep (weights + activations) in one grid
    prep_all<<<dim3(128, 64, 5), dim3(32, 8)>>>(
        hs, W_q, W_k, W_v, W_o, hsh, hsl, wqkvh, wqkvl, woh, wol);

    // launch 1: fused QKV projection (persistent)
    gemm_mma<<<GGRID, 256, GSMEM>>>(
        hsh, hsl, wqkvh, wqkvl, b_v, VOFF, qkv, M, NQKV, DM_);

    // launch 2: RoPE + scale(log2e/8) + split to attention operand layouts
    {
        int total = B_ * S_ * 48 * 32;
        rope_split_kernel<<<(total + 255) / 256, 256>>>(
            qkv, cosb, sinb, qhp, qlp, khp, klp, vhp, vlp);
    }

    // launch 3 (PROFILED): tensor-core flash attention, 4 CTAs/SM
    attn_mma<<<dim3(S_ / 64, H_, B_), 128, ASMEM>>>(
        qhp, qlp, khp, klp, vhp, vlp, aoh, aol);

    // launch 4: O projection (persistent)
    gemm_mma<<<GGRID, 256, GSMEM>>>(
        aoh, aol, woh, wol, b_o, 0, out, M, DM_, DM_);
}

// round 13
// speedup vs baseline: 1.6739x; 1.0233x over previous
#include <cuda_runtime.h>
#include <cuda_bf16.h>
#include <cstdint>

#define B_   2
#define S_   2048
#define DM_  2048
#define H_   32
#define KV_  8
#define HD_  64
#define GRP_ (H_ / KV_)   // 4
#define NQKV 3072          // fused QKV width: 2048 q | 512 k | 512 v
#define KOFF 2048
#define VOFF 2560

// ============================ PTX helpers (base sm_103 safe) ==================
__device__ __forceinline__ uint32_t smem_u32(const void* p) {
    uint32_t a;
    asm("{ .reg .u64 t; cvta.to.shared.u64 t, %1; cvt.u32.u64 %0, t; }"
        : "=r"(a) : "l"(p));
    return a;
}
__device__ __forceinline__ void cp_async16(uint32_t s, const void* g) {
    asm volatile("cp.async.cg.shared.global [%0], [%1], 16;" :: "r"(s), "l"(g));
}
#define CP_COMMIT() asm volatile("cp.async.commit_group;" ::: "memory")
#define CP_WAIT(n)  asm volatile("cp.async.wait_group %0;" :: "n"(n) : "memory")

__device__ __forceinline__ void ldsm_x4(uint32_t addr, uint32_t& r0, uint32_t& r1,
                                        uint32_t& r2, uint32_t& r3) {
    asm volatile("ldmatrix.sync.aligned.m8n8.x4.shared.b16 {%0,%1,%2,%3}, [%4];"
                 : "=r"(r0), "=r"(r1), "=r"(r2), "=r"(r3) : "r"(addr));
}
__device__ __forceinline__ void ldsm_x4t(uint32_t addr, uint32_t& r0, uint32_t& r1,
                                         uint32_t& r2, uint32_t& r3) {
    asm volatile("ldmatrix.sync.aligned.m8n8.x4.trans.shared.b16 {%0,%1,%2,%3}, [%4];"
                 : "=r"(r0), "=r"(r1), "=r"(r2), "=r"(r3) : "r"(addr));
}
__device__ __forceinline__ void mma_bf16(float* d, const uint32_t* a,
                                         uint32_t b0, uint32_t b1) {
    asm volatile("mma.sync.aligned.m16n8k16.row.col.f32.bf16.bf16.f32 "
                 "{%0,%1,%2,%3}, {%4,%5,%6,%7}, {%8,%9}, {%0,%1,%2,%3};"
                 : "+f"(d[0]), "+f"(d[1]), "+f"(d[2]), "+f"(d[3])
                 : "r"(a[0]), "r"(a[1]), "r"(a[2]), "r"(a[3]), "r"(b0), "r"(b1));
}
__device__ __forceinline__ uint32_t bpack(__nv_bfloat16 x, __nv_bfloat16 y) {
    __nv_bfloat162 t(x, y);
    return *reinterpret_cast<uint32_t*>(&t);
}
__device__ __forceinline__ uint32_t cvt_bf16x2(float hi_f, float lo_f) {
    uint32_t r;
    asm("cvt.rn.bf16x2.f32 %0, %1, %2;" : "=r"(r) : "f"(hi_f), "f"(lo_f));
    return r;
}
__device__ __forceinline__ float ex2f(float x) {
    float y;
    asm("ex2.approx.f32 %0, %1;" : "=f"(y) : "f"(x));
    return y;
}

// ============================ scratch =========================================
__device__ float g_qkv[(size_t)B_ * S_ * NQKV];          // 48 MB fused q|k|v
__device__ int   g_ctr[2];                               // work-steal counters

__device__ __nv_bfloat16 g_hsh[(size_t)B_ * S_ * DM_];   // activations hi/lo
__device__ __nv_bfloat16 g_hsl[(size_t)B_ * S_ * DM_];
__device__ __nv_bfloat16 g_aoh[(size_t)B_ * S_ * DM_];   // attn out hi/lo
__device__ __nv_bfloat16 g_aol[(size_t)B_ * S_ * DM_];
__device__ __nv_bfloat16 g_wqkvh[(size_t)NQKV * DM_];    // [N,K] fused weights
__device__ __nv_bfloat16 g_wqkvl[(size_t)NQKV * DM_];
__device__ __nv_bfloat16 g_woh[(size_t)DM_ * DM_];
__device__ __nv_bfloat16 g_wol[(size_t)DM_ * DM_];
// attention operands (bf16 hi/lo, post-RoPE, Q pre-scaled by log2(e)/8)
__device__ __nv_bfloat16 g_qh[(size_t)B_ * S_ * DM_];    // [row, h*64+d]
__device__ __nv_bfloat16 g_ql[(size_t)B_ * S_ * DM_];
__device__ __nv_bfloat16 g_kh[(size_t)B_ * KV_ * S_ * HD_]; // [b*KV+kvh][s][d]
__device__ __nv_bfloat16 g_kl[(size_t)B_ * KV_ * S_ * HD_];
__device__ __nv_bfloat16 g_vh[(size_t)B_ * KV_ * S_ * HD_];
__device__ __nv_bfloat16 g_vl[(size_t)B_ * KV_ * S_ * HD_];

#define GGRID   296

// ====== ONE prep launch: weights transpose+split (z=0..3) + activations (z=4) =
__global__ void prep_all(const float* __restrict__ hs,
                         const float* __restrict__ Wq, const float* __restrict__ Wk,
                         const float* __restrict__ Wv, const float* __restrict__ Wo,
                         __nv_bfloat16* __restrict__ hsh, __nv_bfloat16* __restrict__ hsl,
                         __nv_bfloat16* __restrict__ qkvh, __nv_bfloat16* __restrict__ qkvl,
                         __nv_bfloat16* __restrict__ woh,  __nv_bfloat16* __restrict__ wol)
{
    const int z = blockIdx.z;
    const int tid = threadIdx.y * 32 + threadIdx.x;

    // reset work-steal counters (once per replay)
    if (z == 0 && blockIdx.x == 0 && blockIdx.y == 0 && tid == 0) {
        g_ctr[0] = GGRID;
        g_ctr[1] = GGRID;
    }

    if (z == 4) {
        int bid = blockIdx.x + 128 * blockIdx.y;
        int i = bid * 256 + tid;
        float4 v = ((const float4*)hs)[i];
        __nv_bfloat16 h0 = __float2bfloat16(v.x);
        __nv_bfloat16 h1 = __float2bfloat16(v.y);
        __nv_bfloat16 h2 = __float2bfloat16(v.z);
        __nv_bfloat16 h3 = __float2bfloat16(v.w);
        __nv_bfloat16 l0 = __float2bfloat16(v.x - __bfloat162float(h0));
        __nv_bfloat16 l1 = __float2bfloat16(v.y - __bfloat162float(h1));
        __nv_bfloat16 l2 = __float2bfloat16(v.z - __bfloat162float(h2));
        __nv_bfloat16 l3 = __float2bfloat16(v.w - __bfloat162float(h3));
        ((__nv_bfloat162*)hsh)[2 * i]     = __nv_bfloat162(h0, h1);
        ((__nv_bfloat162*)hsh)[2 * i + 1] = __nv_bfloat162(h2, h3);
        ((__nv_bfloat162*)hsl)[2 * i]     = __nv_bfloat162(l0, l1);
        ((__nv_bfloat162*)hsl)[2 * i + 1] = __nv_bfloat162(l2, l3);
        return;
    }

    if (blockIdx.x >= 64) return;
    const int N = (z == 1 || z == 2) ? 512 : 2048;
    const int n0 = blockIdx.x * 32;
    if (n0 >= N) return;
    const int k0 = blockIdx.y * 32;
    const float* W = (z == 0) ? Wq : (z == 1) ? Wk : (z == 2) ? Wv : Wo;
    __nv_bfloat16* h = (z == 3) ? woh : qkvh;
    __nv_bfloat16* l = (z == 3) ? wol : qkvl;
    const size_t dof = (z == 1) ? (size_t)KOFF * DM_ : (z == 2) ? (size_t)VOFF * DM_ : 0;

    __shared__ float ts[32][33];
    int tx = threadIdx.x, ty = threadIdx.y;
    for (int i = ty; i < 32; i += 8)
        ts[i][tx] = W[(size_t)(k0 + i) * N + n0 + tx];
    __syncthreads();
    for (int i = ty; i < 32; i += 8) {
        float x = ts[tx][i];
        __nv_bfloat16 hv = __float2bfloat16(x);
        __nv_bfloat16 lv = __float2bfloat16(x - __bfloat162float(hv));
        size_t o = dof + (size_t)(n0 + i) * DM_ + k0 + tx;
        h[o] = hv;
        l[o] = lv;
    }
}

// ====== persistent warp-MMA GEMM, 3-term compensated, WORK-STEALING ==========
#define TILE_B  8192
#define STAGE_B (4 * TILE_B)
#define NSTG    3
#define GSMEM   (NSTG * STAGE_B + 16)   // +16: next-tile broadcast word

__global__ __launch_bounds__(256, 2) void gemm_mma(
    const __nv_bfloat16* __restrict__ Ah, const __nv_bfloat16* __restrict__ Al,
    const __nv_bfloat16* __restrict__ Bh, const __nv_bfloat16* __restrict__ Bl,
    const float* __restrict__ bias, int boff, float* __restrict__ C,
    int M, int N, int K, int ctr_id)
{
    extern __shared__ char smem[];
    const uint32_t sb = smem_u32(smem);
    int* snext = (int*)(smem + NSTG * STAGE_B);
    const int tid  = threadIdx.x;
    const int lane = tid & 31;
    const int wid  = tid >> 5;
    const int wm   = wid >> 2;
    const int wn   = wid & 3;
    const int K32 = K / 32;
    const int nx = N >> 7;
    const int ntiles = (M >> 7) * nx;

    const int lr0 = tid >> 2, lc = tid & 3;
    const int lr1 = lr0 + 64;
    const uint32_t so0 = (uint32_t)lr0 * 64 + ((uint32_t)(lc ^ ((lr0 >> 1) & 3)) << 4);
    const uint32_t so1 = (uint32_t)lr1 * 64 + ((uint32_t)(lc ^ ((lr1 >> 1) & 3)) << 4);
    const int ge = lc * 8;

    const int lrow = lane & 15, half = lane >> 4;
    const uint32_t lsw = (uint32_t)((lrow >> 1) & 3);
    const uint32_t a_row_off = (uint32_t)(wm * 64 + lrow) * 64;
    const uint32_t b_row_off = (uint32_t)(wn * 32 + lrow) * 64;

    int t = blockIdx.x;
    while (t < ntiles) {
        const int m0 = (t / nx) << 7;
        const int n0 = (t % nx) << 7;

        float acc[4][4][4];
#pragma unroll
        for (int i = 0; i < 4; i++)
#pragma unroll
            for (int j = 0; j < 4; j++)
#pragma unroll
                for (int r = 0; r < 4; r++) acc[i][j][r] = 0.0f;

#define LOAD_STAGE(kt)                                                           \
    do {                                                                         \
        const int _k0 = (kt) * 32;                                               \
        const uint32_t _st = sb + ((kt) % NSTG) * STAGE_B;                       \
        size_t _a0 = (size_t)(m0 + lr0) * K + _k0 + ge;                          \
        size_t _a1 = (size_t)(m0 + lr1) * K + _k0 + ge;                          \
        size_t _b0 = (size_t)(n0 + lr0) * K + _k0 + ge;                          \
        size_t _b1 = (size_t)(n0 + lr1) * K + _k0 + ge;                          \
        cp_async16(_st + so0,              Ah + _a0);                            \
        cp_async16(_st + so1,              Ah + _a1);                            \
        cp_async16(_st + TILE_B + so0,     Al + _a0);                            \
        cp_async16(_st + TILE_B + so1,     Al + _a1);                            \
        cp_async16(_st + 2 * TILE_B + so0, Bh + _b0);                            \
        cp_async16(_st + 2 * TILE_B + so1, Bh + _b1);                            \
        cp_async16(_st + 3 * TILE_B + so0, Bl + _b0);                            \
        cp_async16(_st + 3 * TILE_B + so1, Bl + _b1);                            \
    } while (0)

        __syncthreads();
        LOAD_STAGE(0); CP_COMMIT();
        LOAD_STAGE(1); CP_COMMIT();

        for (int kt = 0; kt < K32; kt++) {
            CP_WAIT(1);
            __syncthreads();
            if (kt + 2 < K32) LOAD_STAGE(kt + 2);
            CP_COMMIT();

            const uint32_t st = sb + (kt % NSTG) * STAGE_B;
#pragma unroll
            for (int ks = 0; ks < 2; ks++) {
                const uint32_t cp0 = (((uint32_t)(ks * 2 + half)) ^ lsw) << 4;

                uint32_t bh[8], bl[8];
#pragma unroll
                for (int p = 0; p < 2; p++) {
                    uint32_t q0, q1, q2, q3;
                    ldsm_x4(st + 2 * TILE_B + b_row_off + p * 1024 + cp0, q0, q1, q2, q3);
                    bh[4 * p + 0] = q0; bh[4 * p + 1] = q2;
                    bh[4 * p + 2] = q1; bh[4 * p + 3] = q3;
                    ldsm_x4(st + 3 * TILE_B + b_row_off + p * 1024 + cp0, q0, q1, q2, q3);
                    bl[4 * p + 0] = q0; bl[4 * p + 1] = q2;
                    bl[4 * p + 2] = q1; bl[4 * p + 3] = q3;
                }

                uint32_t a[4][4];
#pragma unroll
                for (int i = 0; i < 4; i++)
                    ldsm_x4(st + a_row_off + i * 1024 + cp0,
                            a[i][0], a[i][1], a[i][2], a[i][3]);

#pragma unroll
                for (int i = 0; i < 4; i++)
#pragma unroll
                    for (int j = 0; j < 4; j++)
                        mma_bf16(acc[i][j], a[i], bh[2 * j], bh[2 * j + 1]);
#pragma unroll
                for (int i = 0; i < 4; i++)
#pragma unroll
                    for (int j = 0; j < 4; j++)
                        mma_bf16(acc[i][j], a[i], bl[2 * j], bl[2 * j + 1]);

#pragma unroll
                for (int i = 0; i < 4; i++)
                    ldsm_x4(st + TILE_B + a_row_off + i * 1024 + cp0,
                            a[i][0], a[i][1], a[i][2], a[i][3]);
#pragma unroll
                for (int i = 0; i < 4; i++)
#pragma unroll
                    for (int j = 0; j < 4; j++)
                        mma_bf16(acc[i][j], a[i], bh[2 * j], bh[2 * j + 1]);
            }
        }
#undef LOAD_STAGE

        // grab next tile early (ATOMG latency hides behind the epilogue stores)
        if (tid == 0) *snext = atomicAdd(&g_ctr[ctr_id], 1);

#pragma unroll
        for (int i = 0; i < 4; i++) {
            const int row = m0 + wm * 64 + i * 16 + (lane >> 2);
#pragma unroll
            for (int j = 0; j < 4; j++) {
                const int col = n0 + wn * 32 + j * 8 + (lane & 3) * 2;
                float b0 = 0.f, b1 = 0.f;
                const int bi = col - boff;
                if (bias && bi >= 0) { b0 = bias[bi]; b1 = bias[bi + 1]; }
                float2 v0, v1;
                v0.x = acc[i][j][0] + b0; v0.y = acc[i][j][1] + b1;
                v1.x = acc[i][j][2] + b0; v1.y = acc[i][j][3] + b1;
                *(float2*)(C + (size_t)row * N + col)       = v0;
                *(float2*)(C + (size_t)(row + 8) * N + col) = v1;
            }
        }

        __syncthreads();          // snext visible to all threads
        t = *snext;
    }
}

// ====== RoPE + scale + bf16 hi/lo split of q,k,v out of fused buffer ==========
#define QSCALE 0.1803368801111204f   // 0.125 * log2(e)

__global__ void rope_split_kernel(const float* __restrict__ qkv,
                                  const float* __restrict__ cosb,
                                  const float* __restrict__ sinb,
                                  __nv_bfloat16* __restrict__ qh, __nv_bfloat16* __restrict__ ql,
                                  __nv_bfloat16* __restrict__ kh, __nv_bfloat16* __restrict__ kl,
                                  __nv_bfloat16* __restrict__ vh, __nv_bfloat16* __restrict__ vl)
{
    int idx = blockIdx.x * blockDim.x + threadIdx.x;
    if (idx >= B_ * S_ * 48 * 32) return;
    int d  = idx & 31;
    int hh = (idx >> 5) % 48;
    int r  = idx / (32 * 48);

    const float* cp = cosb + (size_t)r * HD_;
    const float* sp = sinb + (size_t)r * HD_;

    __nv_bfloat16 *dh, *dl;
    size_t doff;
    float x1, x2;
    if (hh < 32) {
        const float* p = qkv + (size_t)r * NQKV + hh * HD_;
        float a = p[d], b = p[d + 32];
        x1 = (a * cp[d]      - b * sp[d])      * QSCALE;
        x2 = (b * cp[d + 32] + a * sp[d + 32]) * QSCALE;
        dh = qh; dl = ql;
        doff = (size_t)r * DM_ + hh * HD_ + d;
    } else if (hh < 40) {
        int kvh = hh - 32;
        const float* p = qkv + (size_t)r * NQKV + KOFF + kvh * HD_;
        float a = p[d], b = p[d + 32];
        x1 = a * cp[d]      - b * sp[d];
        x2 = b * cp[d + 32] + a * sp[d + 32];
        dh = kh; dl = kl;
        int bb = r >> 11, s = r & (S_ - 1);
        doff = ((size_t)(bb * KV_ + kvh) * S_ + s) * HD_ + d;
    } else {
        int kvh = hh - 40;
        const float* p = qkv + (size_t)r * NQKV + VOFF + kvh * HD_;
        x1 = p[d]; x2 = p[d + 32];
        dh = vh; dl = vl;
        int bb = r >> 11, s = r & (S_ - 1);
        doff = ((size_t)(bb * KV_ + kvh) * S_ + s) * HD_ + d;
    }
    __nv_bfloat16 h1 = __float2bfloat16(x1);
    __nv_bfloat16 h2 = __float2bfloat16(x2);
    dh[doff]      = h1;
    dh[doff + 32] = h2;
    dl[doff]      = __float2bfloat16(x1 - __bfloat162float(h1));
    dl[doff + 32] = __float2bfloat16(x2 - __bfloat162float(h2));
}

// =========== tensor-core flash attention (3-term split-bf16, EXACT r12) =======
#define AQ_L   8192
#define AKV0   16384
#define AKV_ST 16384
#define ASMEM  49152

__global__ __launch_bounds__(128, 4) void attn_mma(
    const __nv_bfloat16* __restrict__ qh, const __nv_bfloat16* __restrict__ ql,
    const __nv_bfloat16* __restrict__ kh, const __nv_bfloat16* __restrict__ kl,
    const __nv_bfloat16* __restrict__ vh, const __nv_bfloat16* __restrict__ vl,
    __nv_bfloat16* __restrict__ oh, __nv_bfloat16* __restrict__ ol)
{
    extern __shared__ char smem[];
    const uint32_t sb = smem_u32(smem);
    const int tid  = threadIdx.x;
    const int lane = tid & 31;
    const int warp = tid >> 5;
    const int wr0  = warp * 16;
    const int m0 = (gridDim.x - 1 - blockIdx.x) * 64;    // heavy tiles first
    const int h  = blockIdx.y;
    const int b  = blockIdx.z;
    const int kvh = h >> 2;

    const size_t kvbase = (size_t)(b * KV_ + kvh) * S_ * HD_;

    {
        const size_t qg = (size_t)(b * S_ + m0) * DM_ + h * HD_;
#pragma unroll
        for (int i = 0; i < 4; i++) {
            int c = tid + 128 * i;
            int row = c >> 3, u = c & 7;
            uint32_t ad = sb + row * 128 + (((uint32_t)(u ^ (row & 7))) << 4);
            cp_async16(ad,          qh + qg + (size_t)row * DM_ + u * 8);
            cp_async16(ad + AQ_L,   ql + qg + (size_t)row * DM_ + u * 8);
        }
    }
    CP_COMMIT();

    const int NT = (m0 >> 5) + 2;

#define LOAD_KV(t)                                                                \
    do {                                                                          \
        const int _j0 = (t) * 32;                                                 \
        const uint32_t _st = sb + AKV0 + ((t) & 1) * AKV_ST;                      \
        _Pragma("unroll")                                                         \
        for (int _i = 0; _i < 2; _i++) {                                          \
            int _c = tid * 2 + _i;                                                \
            int _r = _c >> 3, _u = _c & 7;                                        \
            uint32_t _ad = _st + _r * 128 + (((uint32_t)(_u ^ (_r & 7))) << 4);   \
            size_t _g = kvbase + (size_t)(_j0 + _r) * HD_ + _u * 8;               \
            cp_async16(_ad,          kh + _g);                                    \
            cp_async16(_ad + 4096,   kl + _g);                                    \
            cp_async16(_ad + 8192,   vh + _g);                                    \
            cp_async16(_ad + 12288,  vl + _g);                                    \
        }                                                                         \
    } while (0)

    LOAD_KV(0);
    CP_COMMIT();

    CP_WAIT(1);
    __syncthreads();

    uint32_t Qh_[4][4], Ql_[4][4];
    {
        const int row = wr0 + (lane & 15);
#pragma unroll
        for (int kk = 0; kk < 4; kk++) {
            uint32_t u = (uint32_t)(kk * 2 + (lane >> 4));
            uint32_t ad = sb + row * 128 + ((u ^ (uint32_t)(row & 7)) << 4);
            ldsm_x4(ad,        Qh_[kk][0], Qh_[kk][1], Qh_[kk][2], Qh_[kk][3]);
            ldsm_x4(ad + AQ_L, Ql_[kk][0], Ql_[kk][1], Ql_[kk][2], Ql_[kk][3]);
        }
    }

    float o[8][4];
#pragma unroll
    for (int d = 0; d < 8; d++)
#pragma unroll
        for (int r = 0; r < 4; r++) o[d][r] = 0.0f;
    float m1 = -1e30f, m2 = -1e30f, l1 = 0.0f, l2 = 0.0f;

    const int row1 = m0 + wr0 + (lane >> 2);
    const int row2 = row1 + 8;

    for (int t = 0; t < NT; t++) {
        CP_WAIT(0);
        __syncthreads();
        if (t + 1 < NT) LOAD_KV(t + 1);
        CP_COMMIT();

        const int j0 = t * 32;
        if (j0 <= m0 + wr0 + 15) {
            const uint32_t st = sb + AKV0 + (t & 1) * AKV_ST;

            float s[4][4];
#pragma unroll
            for (int n = 0; n < 4; n++)
#pragma unroll
                for (int r = 0; r < 4; r++) s[n][r] = 0.0f;

#pragma unroll
            for (int np = 0; np < 2; np++) {
                const int krow = np * 16 + (lane & 15);
#pragma unroll
                for (int kk = 0; kk < 4; kk++) {
                    uint32_t u = (uint32_t)(kk * 2 + (lane >> 4));
                    uint32_t ad = st + krow * 128 + ((u ^ (uint32_t)(krow & 7)) << 4);
                    uint32_t f0, f1, f2, f3;
                    ldsm_x4(ad, f0, f1, f2, f3);
                    mma_bf16(s[2 * np],     Qh_[kk], f0, f2);
                    mma_bf16(s[2 * np + 1], Qh_[kk], f1, f3);
                    mma_bf16(s[2 * np],     Ql_[kk], f0, f2);
                    mma_bf16(s[2 * np + 1], Ql_[kk], f1, f3);
                    ldsm_x4(ad + 4096, f0, f1, f2, f3);
                    mma_bf16(s[2 * np],     Qh_[kk], f0, f2);
                    mma_bf16(s[2 * np + 1], Qh_[kk], f1, f3);
                }
            }

            if (j0 + 31 > m0 + wr0) {
#pragma unroll
                for (int n = 0; n < 4; n++) {
                    const int col = j0 + n * 8 + ((lane & 3) << 1);
                    if (col     > row1) s[n][0] = -1e30f;
                    if (col + 1 > row1) s[n][1] = -1e30f;
                    if (col     > row2) s[n][2] = -1e30f;
                    if (col + 1 > row2) s[n][3] = -1e30f;
                }
            }

            float mx1 = -1e30f, mx2 = -1e30f;
#pragma unroll
            for (int n = 0; n < 4; n++) {
                mx1 = fmaxf(mx1, fmaxf(s[n][0], s[n][1]));
                mx2 = fmaxf(mx2, fmaxf(s[n][2], s[n][3]));
            }
            mx1 = fmaxf(mx1, __shfl_xor_sync(0xffffffff, mx1, 1));
            mx1 = fmaxf(mx1, __shfl_xor_sync(0xffffffff, mx1, 2));
            mx2 = fmaxf(mx2, __shfl_xor_sync(0xffffffff, mx2, 1));
            mx2 = fmaxf(mx2, __shfl_xor_sync(0xffffffff, mx2, 2));

            const float M1 = fmaxf(m1, mx1), M2 = fmaxf(m2, mx2);
            const float c1 = ex2f(m1 - M1), c2 = ex2f(m2 - M2);
            float ls1 = 0.0f, ls2 = 0.0f;
#pragma unroll
            for (int n = 0; n < 4; n++) {
                s[n][0] = ex2f(s[n][0] - M1); ls1 += s[n][0];
                s[n][1] = ex2f(s[n][1] - M1); ls1 += s[n][1];
                s[n][2] = ex2f(s[n][2] - M2); ls2 += s[n][2];
                s[n][3] = ex2f(s[n][3] - M2); ls2 += s[n][3];
            }
            ls1 += __shfl_xor_sync(0xffffffff, ls1, 1);
            ls1 += __shfl_xor_sync(0xffffffff, ls1, 2);
            ls2 += __shfl_xor_sync(0xffffffff, ls2, 1);
            ls2 += __shfl_xor_sync(0xffffffff, ls2, 2);
            l1 = l1 * c1 + ls1;  l2 = l2 * c2 + ls2;
            m1 = M1;             m2 = M2;
#pragma unroll
            for (int d = 0; d < 8; d++) {
                o[d][0] *= c1; o[d][1] *= c1;
                o[d][2] *= c2; o[d][3] *= c2;
            }

            uint32_t ph[2][4], pl[2][4];
#pragma unroll
            for (int jj = 0; jj < 2; jj++) {
#pragma unroll
                for (int q = 0; q < 4; q++) {
                    const int n = 2 * jj + (q >> 1);
                    const int r = (q & 1) * 2;
                    const float a = s[n][r], bq = s[n][r + 1];
                    const uint32_t hp = cvt_bf16x2(bq, a);
                    const float fa = __uint_as_float(hp << 16);
                    const float fb = __uint_as_float(hp & 0xffff0000u);
                    ph[jj][q] = hp;
                    pl[jj][q] = cvt_bf16x2(bq - fb, a - fa);
                }
            }

#pragma unroll
            for (int dg = 0; dg < 4; dg++) {
#pragma unroll
                for (int jj = 0; jj < 2; jj++) {
                    const int vrow = jj * 16 + (lane & 15);
                    uint32_t u = (uint32_t)(dg * 2 + (lane >> 4));
                    uint32_t ad = st + 8192 + vrow * 128 + ((u ^ (uint32_t)(vrow & 7)) << 4);
                    uint32_t f0, f1, f2, f3;
                    ldsm_x4t(ad, f0, f1, f2, f3);
                    mma_bf16(o[2 * dg],     ph[jj], f0, f1);
                    mma_bf16(o[2 * dg + 1], ph[jj], f2, f3);
                    mma_bf16(o[2 * dg],     pl[jj], f0, f1);
                    mma_bf16(o[2 * dg + 1], pl[jj], f2, f3);
                    ldsm_x4t(ad + 4096, f0, f1, f2, f3);
                    mma_bf16(o[2 * dg],     ph[jj], f0, f1);
                    mma_bf16(o[2 * dg + 1], ph[jj], f2, f3);
                }
            }
        }
    }
#undef LOAD_KV

    const float inv1 = 1.0f / l1;
    const float inv2 = 1.0f / l2;
#pragma unroll
    for (int d = 0; d < 8; d++) {
        const int col = h * HD_ + d * 8 + ((lane & 3) << 1);
        {
            size_t ad = (size_t)(b * S_ + row1) * DM_ + col;
            const float x0 = o[d][0] * inv1, x1 = o[d][1] * inv1;
            const uint32_t hp = cvt_bf16x2(x1, x0);
            const float f0 = __uint_as_float(hp << 16);
            const float f1 = __uint_as_float(hp & 0xffff0000u);
            *(uint32_t*)(oh + ad) = hp;
            *(uint32_t*)(ol + ad) = cvt_bf16x2(x1 - f1, x0 - f0);
        }
        {
            size_t ad = (size_t)(b * S_ + row2) * DM_ + col;
            const float x0 = o[d][2] * inv2, x1 = o[d][3] * inv2;
            const uint32_t hp = cvt_bf16x2(x1, x0);
            const float f0 = __uint_as_float(hp << 16);
            const float f1 = __uint_as_float(hp & 0xffff0000u);
            *(uint32_t*)(oh + ad) = hp;
            *(uint32_t*)(ol + ad) = cvt_bf16x2(x1 - f1, x0 - f0);
        }
    }
}

// ================================ launch ======================================
extern "C" void kernel_launch(void* const* d_in, const int* in_sizes, int n_in,
                              void* d_out, int out_size)
{
    const float* hs    = (const float*)d_in[0];
    const float* cosb  = (const float*)d_in[2];
    const float* sinb  = (const float*)d_in[3];
    const float* W_q   = (const float*)d_in[4];
    const float* W_k   = (const float*)d_in[5];
    const float* W_v   = (const float*)d_in[6];
    const float* b_v   = (const float*)d_in[7];
    const float* W_o   = (const float*)d_in[8];
    const float* b_o   = (const float*)d_in[9];
    float* out = (float*)d_out;

    float* qkv;
    cudaGetSymbolAddress((void**)&qkv, g_qkv);
    __nv_bfloat16 *hsh, *hsl, *aoh, *aol, *wqkvh, *wqkvl, *woh, *wol;
    __nv_bfloat16 *qhp, *qlp, *khp, *klp, *vhp, *vlp;
    cudaGetSymbolAddress((void**)&hsh, g_hsh);
    cudaGetSymbolAddress((void**)&hsl, g_hsl);
    cudaGetSymbolAddress((void**)&aoh, g_aoh);
    cudaGetSymbolAddress((void**)&aol, g_aol);
    cudaGetSymbolAddress((void**)&wqkvh, g_wqkvh);
    cudaGetSymbolAddress((void**)&wqkvl, g_wqkvl);
    cudaGetSymbolAddress((void**)&woh, g_woh);
    cudaGetSymbolAddress((void**)&wol, g_wol);
    cudaGetSymbolAddress((void**)&qhp, g_qh);
    cudaGetSymbolAddress((void**)&qlp, g_ql);
    cudaGetSymbolAddress((void**)&khp, g_kh);
    cudaGetSymbolAddress((void**)&klp, g_kl);
    cudaGetSymbolAddress((void**)&vhp, g_vh);
    cudaGetSymbolAddress((void**)&vlp, g_vl);

    cudaFuncSetAttribute(gemm_mma,
                         cudaFuncAttributeMaxDynamicSharedMemorySize, GSMEM);
    cudaFuncSetAttribute(attn_mma,
                         cudaFuncAttributeMaxDynamicSharedMemorySize, ASMEM);

    const int M = B_ * S_;       // 4096

    // launch 0: ALL prep (weights + activations + counter reset) in one grid
    prep_all<<<dim3(128, 64, 5), dim3(32, 8)>>>(
        hs, W_q, W_k, W_v, W_o, hsh, hsl, wqkvh, wqkvl, woh, wol);

    // launch 1: fused QKV projection (persistent, work-stealing on ctr 0)
    gemm_mma<<<GGRID, 256, GSMEM>>>(
        hsh, hsl, wqkvh, wqkvl, b_v, VOFF, qkv, M, NQKV, DM_, 0);

    // launch 2: RoPE + scale(log2e/8) + split to attention operand layouts
    {
        int total = B_ * S_ * 48 * 32;
        rope_split_kernel<<<(total + 255) / 256, 256>>>(
            qkv, cosb, sinb, qhp, qlp, khp, klp, vhp, vlp);
    }

    // launch 3 (PROFILED): tensor-core flash attention, 4 CTAs/SM
    attn_mma<<<dim3(S_ / 64, H_, B_), 128, ASMEM>>>(
        qhp, qlp, khp, klp, vhp, vlp, aoh, aol);

    // launch 4: O projection (persistent, work-stealing on ctr 1)
    gemm_mma<<<GGRID, 256, GSMEM>>>(
        aoh, aol, woh, wol, b_o, 0, out, M, DM_, DM_, 1);
}

// round 14
// speedup vs baseline: 1.6863x; 1.0074x over previous
#include <cuda_runtime.h>
#include <cuda_bf16.h>
#include <cstdint>

#define B_   2
#define S_   2048
#define DM_  2048
#define H_   32
#define KV_  8
#define HD_  64
#define GRP_ (H_ / KV_)   // 4
#define NQKV 3072          // fused QKV width: 2048 q | 512 k | 512 v
#define KOFF 2048
#define VOFF 2560

// ============================ PTX helpers (base sm_103 safe) ==================
__device__ __forceinline__ uint32_t smem_u32(const void* p) {
    uint32_t a;
    asm("{ .reg .u64 t; cvta.to.shared.u64 t, %1; cvt.u32.u64 %0, t; }"
        : "=r"(a) : "l"(p));
    return a;
}
__device__ __forceinline__ void cp_async16(uint32_t s, const void* g) {
    asm volatile("cp.async.cg.shared.global [%0], [%1], 16;" :: "r"(s), "l"(g));
}
#define CP_COMMIT() asm volatile("cp.async.commit_group;" ::: "memory")
#define CP_WAIT(n)  asm volatile("cp.async.wait_group %0;" :: "n"(n) : "memory")

__device__ __forceinline__ void ldsm_x4(uint32_t addr, uint32_t& r0, uint32_t& r1,
                                        uint32_t& r2, uint32_t& r3) {
    asm volatile("ldmatrix.sync.aligned.m8n8.x4.shared.b16 {%0,%1,%2,%3}, [%4];"
                 : "=r"(r0), "=r"(r1), "=r"(r2), "=r"(r3) : "r"(addr));
}
__device__ __forceinline__ void ldsm_x4t(uint32_t addr, uint32_t& r0, uint32_t& r1,
                                         uint32_t& r2, uint32_t& r3) {
    asm volatile("ldmatrix.sync.aligned.m8n8.x4.trans.shared.b16 {%0,%1,%2,%3}, [%4];"
                 : "=r"(r0), "=r"(r1), "=r"(r2), "=r"(r3) : "r"(addr));
}
__device__ __forceinline__ void mma_bf16(float* d, const uint32_t* a,
                                         uint32_t b0, uint32_t b1) {
    asm volatile("mma.sync.aligned.m16n8k16.row.col.f32.bf16.bf16.f32 "
                 "{%0,%1,%2,%3}, {%4,%5,%6,%7}, {%8,%9}, {%0,%1,%2,%3};"
                 : "+f"(d[0]), "+f"(d[1]), "+f"(d[2]), "+f"(d[3])
                 : "r"(a[0]), "r"(a[1]), "r"(a[2]), "r"(a[3]), "r"(b0), "r"(b1));
}
__device__ __forceinline__ uint32_t cvt_bf16x2(float hi_f, float lo_f) {
    uint32_t r;
    asm("cvt.rn.bf16x2.f32 %0, %1, %2;" : "=r"(r) : "f"(hi_f), "f"(lo_f));
    return r;
}
__device__ __forceinline__ float ex2f(float x) {
    float y;
    asm("ex2.approx.f32 %0, %1;" : "=f"(y) : "f"(x));
    return y;
}

// ============================ scratch =========================================
__device__ float g_qkv[(size_t)B_ * S_ * NQKV];          // 48 MB fused q|k|v
__device__ int   g_ctr[2];                               // work-steal counters

__device__ __nv_bfloat16 g_hsh[(size_t)B_ * S_ * DM_];   // activations hi/lo
__device__ __nv_bfloat16 g_hsl[(size_t)B_ * S_ * DM_];
__device__ __nv_bfloat16 g_aoh[(size_t)B_ * S_ * DM_];   // attn out hi/lo
__device__ __nv_bfloat16 g_aol[(size_t)B_ * S_ * DM_];
__device__ __nv_bfloat16 g_wqkvh[(size_t)NQKV * DM_];    // [N,K] fused weights
__device__ __nv_bfloat16 g_wqkvl[(size_t)NQKV * DM_];
__device__ __nv_bfloat16 g_woh[(size_t)DM_ * DM_];
__device__ __nv_bfloat16 g_wol[(size_t)DM_ * DM_];
// attention operands (bf16 hi/lo, post-RoPE, Q pre-scaled by log2(e)/8)
__device__ __nv_bfloat16 g_qh[(size_t)B_ * S_ * DM_];    // [row, h*64+d]
__device__ __nv_bfloat16 g_ql[(size_t)B_ * S_ * DM_];
__device__ __nv_bfloat16 g_kh[(size_t)B_ * KV_ * S_ * HD_]; // [b*KV+kvh][s][d]
__device__ __nv_bfloat16 g_kl[(size_t)B_ * KV_ * S_ * HD_];
__device__ __nv_bfloat16 g_vh[(size_t)B_ * KV_ * S_ * HD_];
__device__ __nv_bfloat16 g_vl[(size_t)B_ * KV_ * S_ * HD_];

#define GGRID   296

// ====== ONE prep launch: weights transpose+split (z=0..3) + activations (z=4) =
// weight path: 64k x 32n tile per block, packed bf16x2 stores (bit-identical
// values to the old scalar path; cvt.rn == __float2bfloat16 rounding).
__global__ void prep_all(const float* __restrict__ hs,
                         const float* __restrict__ Wq, const float* __restrict__ Wk,
                         const float* __restrict__ Wv, const float* __restrict__ Wo,
                         __nv_bfloat16* __restrict__ hsh, __nv_bfloat16* __restrict__ hsl,
                         __nv_bfloat16* __restrict__ qkvh, __nv_bfloat16* __restrict__ qkvl,
                         __nv_bfloat16* __restrict__ woh,  __nv_bfloat16* __restrict__ wol)
{
    const int z = blockIdx.z;
    const int tid = threadIdx.y * 32 + threadIdx.x;

    // reset work-steal counters (once per replay)
    if (z == 0 && blockIdx.x == 0 && blockIdx.y == 0 && tid == 0) {
        g_ctr[0] = GGRID;
        g_ctr[1] = GGRID;
    }

    if (z == 4) {
        int bid = blockIdx.x + 128 * blockIdx.y;
        int i = bid * 256 + tid;
        float4 v = ((const float4*)hs)[i];
        uint32_t hp0 = cvt_bf16x2(v.y, v.x);
        uint32_t hp1 = cvt_bf16x2(v.w, v.z);
        float f0 = __uint_as_float(hp0 << 16);
        float f1 = __uint_as_float(hp0 & 0xffff0000u);
        float f2 = __uint_as_float(hp1 << 16);
        float f3 = __uint_as_float(hp1 & 0xffff0000u);
        ((uint32_t*)hsh)[2 * i]     = hp0;
        ((uint32_t*)hsh)[2 * i + 1] = hp1;
        ((uint32_t*)hsl)[2 * i]     = cvt_bf16x2(v.y - f1, v.x - f0);
        ((uint32_t*)hsl)[2 * i + 1] = cvt_bf16x2(v.w - f3, v.z - f2);
        return;
    }

    // weights: fp32 [K,N] -> bf16 hi/lo transposed [N,K]
    if (blockIdx.y >= 32) return;               // 64 k-rows per block
    const int N = (z == 1 || z == 2) ? 512 : 2048;
    const int n0 = blockIdx.x * 32;
    if (n0 >= N) return;
    const int k0 = blockIdx.y * 64;
    const float* W = (z == 0) ? Wq : (z == 1) ? Wk : (z == 2) ? Wv : Wo;
    __nv_bfloat16* h = (z == 3) ? woh : qkvh;
    __nv_bfloat16* l = (z == 3) ? wol : qkvl;
    const size_t dof = (z == 1) ? (size_t)KOFF * DM_ : (z == 2) ? (size_t)VOFF * DM_ : 0;

    __shared__ float ts[64][33];
    const int tx = threadIdx.x, ty = threadIdx.y;
    for (int i = ty; i < 64; i += 8)
        ts[i][tx] = W[(size_t)(k0 + i) * N + n0 + tx];
    __syncthreads();
    for (int i = ty; i < 32; i += 8) {
        const float x0 = ts[2 * tx][i];         // (k = k0+2tx,   n = n0+i)
        const float x1 = ts[2 * tx + 1][i];     // (k = k0+2tx+1, n = n0+i)
        const uint32_t hp = cvt_bf16x2(x1, x0);
        const float f0 = __uint_as_float(hp << 16);
        const float f1 = __uint_as_float(hp & 0xffff0000u);
        const size_t o = dof + (size_t)(n0 + i) * DM_ + k0 + 2 * tx;
        *(uint32_t*)(h + o) = hp;
        *(uint32_t*)(l + o) = cvt_bf16x2(x1 - f1, x0 - f0);
    }
}

// ====== persistent warp-MMA GEMM, 3-term compensated, WORK-STEALING (r13) =====
#define TILE_B  8192
#define STAGE_B (4 * TILE_B)
#define NSTG    3
#define GSMEM   (NSTG * STAGE_B + 16)   // +16: next-tile broadcast word

__global__ __launch_bounds__(256, 2) void gemm_mma(
    const __nv_bfloat16* __restrict__ Ah, const __nv_bfloat16* __restrict__ Al,
    const __nv_bfloat16* __restrict__ Bh, const __nv_bfloat16* __restrict__ Bl,
    const float* __restrict__ bias, int boff, float* __restrict__ C,
    int M, int N, int K, int ctr_id)
{
    extern __shared__ char smem[];
    const uint32_t sb = smem_u32(smem);
    int* snext = (int*)(smem + NSTG * STAGE_B);
    const int tid  = threadIdx.x;
    const int lane = tid & 31;
    const int wid  = tid >> 5;
    const int wm   = wid >> 2;
    const int wn   = wid & 3;
    const int K32 = K / 32;
    const int nx = N >> 7;
    const int ntiles = (M >> 7) * nx;

    const int lr0 = tid >> 2, lc = tid & 3;
    const int lr1 = lr0 + 64;
    const uint32_t so0 = (uint32_t)lr0 * 64 + ((uint32_t)(lc ^ ((lr0 >> 1) & 3)) << 4);
    const uint32_t so1 = (uint32_t)lr1 * 64 + ((uint32_t)(lc ^ ((lr1 >> 1) & 3)) << 4);
    const int ge = lc * 8;

    const int lrow = lane & 15, half = lane >> 4;
    const uint32_t lsw = (uint32_t)((lrow >> 1) & 3);
    const uint32_t a_row_off = (uint32_t)(wm * 64 + lrow) * 64;
    const uint32_t b_row_off = (uint32_t)(wn * 32 + lrow) * 64;

    int t = blockIdx.x;
    while (t < ntiles) {
        const int m0 = (t / nx) << 7;
        const int n0 = (t % nx) << 7;

        float acc[4][4][4];
#pragma unroll
        for (int i = 0; i < 4; i++)
#pragma unroll
            for (int j = 0; j < 4; j++)
#pragma unroll
                for (int r = 0; r < 4; r++) acc[i][j][r] = 0.0f;

#define LOAD_STAGE(kt)                                                           \
    do {                                                                         \
        const int _k0 = (kt) * 32;                                               \
        const uint32_t _st = sb + ((kt) % NSTG) * STAGE_B;                       \
        size_t _a0 = (size_t)(m0 + lr0) * K + _k0 + ge;                          \
        size_t _a1 = (size_t)(m0 + lr1) * K + _k0 + ge;                          \
        size_t _b0 = (size_t)(n0 + lr0) * K + _k0 + ge;                          \
        size_t _b1 = (size_t)(n0 + lr1) * K + _k0 + ge;                          \
        cp_async16(_st + so0,              Ah + _a0);                            \
        cp_async16(_st + so1,              Ah + _a1);                            \
        cp_async16(_st + TILE_B + so0,     Al + _a0);                            \
        cp_async16(_st + TILE_B + so1,     Al + _a1);                            \
        cp_async16(_st + 2 * TILE_B + so0, Bh + _b0);                            \
        cp_async16(_st + 2 * TILE_B + so1, Bh + _b1);                            \
        cp_async16(_st + 3 * TILE_B + so0, Bl + _b0);                            \
        cp_async16(_st + 3 * TILE_B + so1, Bl + _b1);                            \
    } while (0)

        __syncthreads();
        LOAD_STAGE(0); CP_COMMIT();
        LOAD_STAGE(1); CP_COMMIT();

        for (int kt = 0; kt < K32; kt++) {
            CP_WAIT(1);
            __syncthreads();
            if (kt + 2 < K32) LOAD_STAGE(kt + 2);
            CP_COMMIT();

            const uint32_t st = sb + (kt % NSTG) * STAGE_B;
#pragma unroll
            for (int ks = 0; ks < 2; ks++) {
                const uint32_t cp0 = (((uint32_t)(ks * 2 + half)) ^ lsw) << 4;

                uint32_t bh[8], bl[8];
#pragma unroll
                for (int p = 0; p < 2; p++) {
                    uint32_t q0, q1, q2, q3;
                    ldsm_x4(st + 2 * TILE_B + b_row_off + p * 1024 + cp0, q0, q1, q2, q3);
                    bh[4 * p + 0] = q0; bh[4 * p + 1] = q2;
                    bh[4 * p + 2] = q1; bh[4 * p + 3] = q3;
                    ldsm_x4(st + 3 * TILE_B + b_row_off + p * 1024 + cp0, q0, q1, q2, q3);
                    bl[4 * p + 0] = q0; bl[4 * p + 1] = q2;
                    bl[4 * p + 2] = q1; bl[4 * p + 3] = q3;
                }

                uint32_t a[4][4];
#pragma unroll
                for (int i = 0; i < 4; i++)
                    ldsm_x4(st + a_row_off + i * 1024 + cp0,
                            a[i][0], a[i][1], a[i][2], a[i][3]);

#pragma unroll
                for (int i = 0; i < 4; i++)
#pragma unroll
                    for (int j = 0; j < 4; j++)
                        mma_bf16(acc[i][j], a[i], bh[2 * j], bh[2 * j + 1]);
#pragma unroll
                for (int i = 0; i < 4; i++)
#pragma unroll
                    for (int j = 0; j < 4; j++)
                        mma_bf16(acc[i][j], a[i], bl[2 * j], bl[2 * j + 1]);

#pragma unroll
                for (int i = 0; i < 4; i++)
                    ldsm_x4(st + TILE_B + a_row_off + i * 1024 + cp0,
                            a[i][0], a[i][1], a[i][2], a[i][3]);
#pragma unroll
                for (int i = 0; i < 4; i++)
#pragma unroll
                    for (int j = 0; j < 4; j++)
                        mma_bf16(acc[i][j], a[i], bh[2 * j], bh[2 * j + 1]);
            }
        }
#undef LOAD_STAGE

        // grab next tile early (ATOMG latency hides behind the epilogue stores)
        if (tid == 0) *snext = atomicAdd(&g_ctr[ctr_id], 1);

#pragma unroll
        for (int i = 0; i < 4; i++) {
            const int row = m0 + wm * 64 + i * 16 + (lane >> 2);
#pragma unroll
            for (int j = 0; j < 4; j++) {
                const int col = n0 + wn * 32 + j * 8 + (lane & 3) * 2;
                float b0 = 0.f, b1 = 0.f;
                const int bi = col - boff;
                if (bias && bi >= 0) { b0 = bias[bi]; b1 = bias[bi + 1]; }
                float2 v0, v1;
                v0.x = acc[i][j][0] + b0; v0.y = acc[i][j][1] + b1;
                v1.x = acc[i][j][2] + b0; v1.y = acc[i][j][3] + b1;
                *(float2*)(C + (size_t)row * N + col)       = v0;
                *(float2*)(C + (size_t)(row + 8) * N + col) = v1;
            }
        }

        __syncthreads();          // snext visible to all threads
        t = *snext;
    }
}

// ====== RoPE + scale + bf16 hi/lo split of q,k,v out of fused buffer ==========
#define QSCALE 0.1803368801111204f   // 0.125 * log2(e)

__global__ void rope_split_kernel(const float* __restrict__ qkv,
                                  const float* __restrict__ cosb,
                                  const float* __restrict__ sinb,
                                  __nv_bfloat16* __restrict__ qh, __nv_bfloat16* __restrict__ ql,
                                  __nv_bfloat16* __restrict__ kh, __nv_bfloat16* __restrict__ kl,
                                  __nv_bfloat16* __restrict__ vh, __nv_bfloat16* __restrict__ vl)
{
    int idx = blockIdx.x * blockDim.x + threadIdx.x;
    if (idx >= B_ * S_ * 48 * 32) return;
    int d  = idx & 31;
    int hh = (idx >> 5) % 48;
    int r  = idx / (32 * 48);

    const float* cp = cosb + (size_t)r * HD_;
    const float* sp = sinb + (size_t)r * HD_;

    __nv_bfloat16 *dh, *dl;
    size_t doff;
    float x1, x2;
    if (hh < 32) {
        const float* p = qkv + (size_t)r * NQKV + hh * HD_;
        float a = p[d], b = p[d + 32];
        x1 = (a * cp[d]      - b * sp[d])      * QSCALE;
        x2 = (b * cp[d + 32] + a * sp[d + 32]) * QSCALE;
        dh = qh; dl = ql;
        doff = (size_t)r * DM_ + hh * HD_ + d;
    } else if (hh < 40) {
        int kvh = hh - 32;
        const float* p = qkv + (size_t)r * NQKV + KOFF + kvh * HD_;
        float a = p[d], b = p[d + 32];
        x1 = a * cp[d]      - b * sp[d];
        x2 = b * cp[d + 32] + a * sp[d + 32];
        dh = kh; dl = kl;
        int bb = r >> 11, s = r & (S_ - 1);
        doff = ((size_t)(bb * KV_ + kvh) * S_ + s) * HD_ + d;
    } else {
        int kvh = hh - 40;
        const float* p = qkv + (size_t)r * NQKV + VOFF + kvh * HD_;
        x1 = p[d]; x2 = p[d + 32];
        dh = vh; dl = vl;
        int bb = r >> 11, s = r & (S_ - 1);
        doff = ((size_t)(bb * KV_ + kvh) * S_ + s) * HD_ + d;
    }
    __nv_bfloat16 h1 = __float2bfloat16(x1);
    __nv_bfloat16 h2 = __float2bfloat16(x2);
    dh[doff]      = h1;
    dh[doff + 32] = h2;
    dl[doff]      = __float2bfloat16(x1 - __bfloat162float(h1));
    dl[doff + 32] = __float2bfloat16(x2 - __bfloat162float(h2));
}

// =========== tensor-core flash attention (3-term split-bf16, EXACT r13) =======
#define AQ_L   8192
#define AKV0   16384
#define AKV_ST 16384
#define ASMEM  49152

__global__ __launch_bounds__(128, 4) void attn_mma(
    const __nv_bfloat16* __restrict__ qh, const __nv_bfloat16* __restrict__ ql,
    const __nv_bfloat16* __restrict__ kh, const __nv_bfloat16* __restrict__ kl,
    const __nv_bfloat16* __restrict__ vh, const __nv_bfloat16* __restrict__ vl,
    __nv_bfloat16* __restrict__ oh, __nv_bfloat16* __restrict__ ol)
{
    extern __shared__ char smem[];
    const uint32_t sb = smem_u32(smem);
    const int tid  = threadIdx.x;
    const int lane = tid & 31;
    const int warp = tid >> 5;
    const int wr0  = warp * 16;
    const int m0 = (gridDim.x - 1 - blockIdx.x) * 64;    // heavy tiles first
    const int h  = blockIdx.y;
    const int b  = blockIdx.z;
    const int kvh = h >> 2;

    const size_t kvbase = (size_t)(b * KV_ + kvh) * S_ * HD_;

    {
        const size_t qg = (size_t)(b * S_ + m0) * DM_ + h * HD_;
#pragma unroll
        for (int i = 0; i < 4; i++) {
            int c = tid + 128 * i;
            int row = c >> 3, u = c & 7;
            uint32_t ad = sb + row * 128 + (((uint32_t)(u ^ (row & 7))) << 4);
            cp_async16(ad,          qh + qg + (size_t)row * DM_ + u * 8);
            cp_async16(ad + AQ_L,   ql + qg + (size_t)row * DM_ + u * 8);
        }
    }
    CP_COMMIT();

    const int NT = (m0 >> 5) + 2;

#define LOAD_KV(t)                                                                \
    do {                                                                          \
        const int _j0 = (t) * 32;                                                 \
        const uint32_t _st = sb + AKV0 + ((t) & 1) * AKV_ST;                      \
        _Pragma("unroll")                                                         \
        for (int _i = 0; _i < 2; _i++) {                                          \
            int _c = tid * 2 + _i;                                                \
            int _r = _c >> 3, _u = _c & 7;                                        \
            uint32_t _ad = _st + _r * 128 + (((uint32_t)(_u ^ (_r & 7))) << 4);   \
            size_t _g = kvbase + (size_t)(_j0 + _r) * HD_ + _u * 8;               \
            cp_async16(_ad,          kh + _g);                                    \
            cp_async16(_ad + 4096,   kl + _g);                                    \
            cp_async16(_ad + 8192,   vh + _g);                                    \
            cp_async16(_ad + 12288,  vl + _g);                                    \
        }                                                                         \
    } while (0)

    LOAD_KV(0);
    CP_COMMIT();

    CP_WAIT(1);
    __syncthreads();

    uint32_t Qh_[4][4], Ql_[4][4];
    {
        const int row = wr0 + (lane & 15);
#pragma unroll
        for (int kk = 0; kk < 4; kk++) {
            uint32_t u = (uint32_t)(kk * 2 + (lane >> 4));
            uint32_t ad = sb + row * 128 + ((u ^ (uint32_t)(row & 7)) << 4);
            ldsm_x4(ad,        Qh_[kk][0], Qh_[kk][1], Qh_[kk][2], Qh_[kk][3]);
            ldsm_x4(ad + AQ_L, Ql_[kk][0], Ql_[kk][1], Ql_[kk][2], Ql_[kk][3]);
        }
    }

    float o[8][4];
#pragma unroll
    for (int d = 0; d < 8; d++)
#pragma unroll
        for (int r = 0; r < 4; r++) o[d][r] = 0.0f;
    float m1 = -1e30f, m2 = -1e30f, l1 = 0.0f, l2 = 0.0f;

    const int row1 = m0 + wr0 + (lane >> 2);
    const int row2 = row1 + 8;

    for (int t = 0; t < NT; t++) {
        CP_WAIT(0);
        __syncthreads();
        if (t + 1 < NT) LOAD_KV(t + 1);
        CP_COMMIT();

        const int j0 = t * 32;
        if (j0 <= m0 + wr0 + 15) {
            const uint32_t st = sb + AKV0 + (t & 1) * AKV_ST;

            float s[4][4];
#pragma unroll
            for (int n = 0; n < 4; n++)
#pragma unroll
                for (int r = 0; r < 4; r++) s[n][r] = 0.0f;

#pragma unroll
            for (int np = 0; np < 2; np++) {
                const int krow = np * 16 + (lane & 15);
#pragma unroll
                for (int kk = 0; kk < 4; kk++) {
                    uint32_t u = (uint32_t)(kk * 2 + (lane >> 4));
                    uint32_t ad = st + krow * 128 + ((u ^ (uint32_t)(krow & 7)) << 4);
                    uint32_t f0, f1, f2, f3;
                    ldsm_x4(ad, f0, f1, f2, f3);
                    mma_bf16(s[2 * np],     Qh_[kk], f0, f2);
                    mma_bf16(s[2 * np + 1], Qh_[kk], f1, f3);
                    mma_bf16(s[2 * np],     Ql_[kk], f0, f2);
                    mma_bf16(s[2 * np + 1], Ql_[kk], f1, f3);
                    ldsm_x4(ad + 4096, f0, f1, f2, f3);
                    mma_bf16(s[2 * np],     Qh_[kk], f0, f2);
                    mma_bf16(s[2 * np + 1], Qh_[kk], f1, f3);
                }
            }

            if (j0 + 31 > m0 + wr0) {
#pragma unroll
                for (int n = 0; n < 4; n++) {
                    const int col = j0 + n * 8 + ((lane & 3) << 1);
                    if (col     > row1) s[n][0] = -1e30f;
                    if (col + 1 > row1) s[n][1] = -1e30f;
                    if (col     > row2) s[n][2] = -1e30f;
                    if (col + 1 > row2) s[n][3] = -1e30f;
                }
            }

            float mx1 = -1e30f, mx2 = -1e30f;
#pragma unroll
            for (int n = 0; n < 4; n++) {
                mx1 = fmaxf(mx1, fmaxf(s[n][0], s[n][1]));
                mx2 = fmaxf(mx2, fmaxf(s[n][2], s[n][3]));
            }
            mx1 = fmaxf(mx1, __shfl_xor_sync(0xffffffff, mx1, 1));
            mx1 = fmaxf(mx1, __shfl_xor_sync(0xffffffff, mx1, 2));
            mx2 = fmaxf(mx2, __shfl_xor_sync(0xffffffff, mx2, 1));
            mx2 = fmaxf(mx2, __shfl_xor_sync(0xffffffff, mx2, 2));

            const float M1 = fmaxf(m1, mx1), M2 = fmaxf(m2, mx2);
            const float c1 = ex2f(m1 - M1), c2 = ex2f(m2 - M2);
            float ls1 = 0.0f, ls2 = 0.0f;
#pragma unroll
            for (int n = 0; n < 4; n++) {
                s[n][0] = ex2f(s[n][0] - M1); ls1 += s[n][0];
                s[n][1] = ex2f(s[n][1] - M1); ls1 += s[n][1];
                s[n][2] = ex2f(s[n][2] - M2); ls2 += s[n][2];
                s[n][3] = ex2f(s[n][3] - M2); ls2 += s[n][3];
            }
            ls1 += __shfl_xor_sync(0xffffffff, ls1, 1);
            ls1 += __shfl_xor_sync(0xffffffff, ls1, 2);
            ls2 += __shfl_xor_sync(0xffffffff, ls2, 1);
            ls2 += __shfl_xor_sync(0xffffffff, ls2, 2);
            l1 = l1 * c1 + ls1;  l2 = l2 * c2 + ls2;
            m1 = M1;             m2 = M2;
#pragma unroll
            for (int d = 0; d < 8; d++) {
                o[d][0] *= c1; o[d][1] *= c1;
                o[d][2] *= c2; o[d][3] *= c2;
            }

            uint32_t ph[2][4], pl[2][4];
#pragma unroll
            for (int jj = 0; jj < 2; jj++) {
#pragma unroll
                for (int q = 0; q < 4; q++) {
                    const int n = 2 * jj + (q >> 1);
                    const int r = (q & 1) * 2;
                    const float a = s[n][r], bq = s[n][r + 1];
                    const uint32_t hp = cvt_bf16x2(bq, a);
                    const float fa = __uint_as_float(hp << 16);
                    const float fb = __uint_as_float(hp & 0xffff0000u);
                    ph[jj][q] = hp;
                    pl[jj][q] = cvt_bf16x2(bq - fb, a - fa);
                }
            }

#pragma unroll
            for (int dg = 0; dg < 4; dg++) {
#pragma unroll
                for (int jj = 0; jj < 2; jj++) {
                    const int vrow = jj * 16 + (lane & 15);
                    uint32_t u = (uint32_t)(dg * 2 + (lane >> 4));
                    uint32_t ad = st + 8192 + vrow * 128 + ((u ^ (uint32_t)(vrow & 7)) << 4);
                    uint32_t f0, f1, f2, f3;
                    ldsm_x4t(ad, f0, f1, f2, f3);
                    mma_bf16(o[2 * dg],     ph[jj], f0, f1);
                    mma_bf16(o[2 * dg + 1], ph[jj], f2, f3);
                    mma_bf16(o[2 * dg],     pl[jj], f0, f1);
                    mma_bf16(o[2 * dg + 1], pl[jj], f2, f3);
                    ldsm_x4t(ad + 4096, f0, f1, f2, f3);
                    mma_bf16(o[2 * dg],     ph[jj], f0, f1);
                    mma_bf16(o[2 * dg + 1], ph[jj], f2, f3);
                }
            }
        }
    }
#undef LOAD_KV

    const float inv1 = 1.0f / l1;
    const float inv2 = 1.0f / l2;
#pragma unroll
    for (int d = 0; d < 8; d++) {
        const int col = h * HD_ + d * 8 + ((lane & 3) << 1);
        {
            size_t ad = (size_t)(b * S_ + row1) * DM_ + col;
            const float x0 = o[d][0] * inv1, x1 = o[d][1] * inv1;
            const uint32_t hp = cvt_bf16x2(x1, x0);
            const float f0 = __uint_as_float(hp << 16);
            const float f1 = __uint_as_float(hp & 0xffff0000u);
            *(uint32_t*)(oh + ad) = hp;
            *(uint32_t*)(ol + ad) = cvt_bf16x2(x1 - f1, x0 - f0);
        }
        {
            size_t ad = (size_t)(b * S_ + row2) * DM_ + col;
            const float x0 = o[d][2] * inv2, x1 = o[d][3] * inv2;
            const uint32_t hp = cvt_bf16x2(x1, x0);
            const float f0 = __uint_as_float(hp << 16);
            const float f1 = __uint_as_float(hp & 0xffff0000u);
            *(uint32_t*)(oh + ad) = hp;
            *(uint32_t*)(ol + ad) = cvt_bf16x2(x1 - f1, x0 - f0);
        }
    }
}

// ================================ launch ======================================
extern "C" void kernel_launch(void* const* d_in, const int* in_sizes, int n_in,
                              void* d_out, int out_size)
{
    const float* hs    = (const float*)d_in[0];
    const float* cosb  = (const float*)d_in[2];
    const float* sinb  = (const float*)d_in[3];
    const float* W_q   = (const float*)d_in[4];
    const float* W_k   = (const float*)d_in[5];
    const float* W_v   = (const float*)d_in[6];
    const float* b_v   = (const float*)d_in[7];
    const float* W_o   = (const float*)d_in[8];
    const float* b_o   = (const float*)d_in[9];
    float* out = (float*)d_out;

    float* qkv;
    cudaGetSymbolAddress((void**)&qkv, g_qkv);
    __nv_bfloat16 *hsh, *hsl, *aoh, *aol, *wqkvh, *wqkvl, *woh, *wol;
    __nv_bfloat16 *qhp, *qlp, *khp, *klp, *vhp, *vlp;
    cudaGetSymbolAddress((void**)&hsh, g_hsh);
    cudaGetSymbolAddress((void**)&hsl, g_hsl);
    cudaGetSymbolAddress((void**)&aoh, g_aoh);
    cudaGetSymbolAddress((void**)&aol, g_aol);
    cudaGetSymbolAddress((void**)&wqkvh, g_wqkvh);
    cudaGetSymbolAddress((void**)&wqkvl, g_wqkvl);
    cudaGetSymbolAddress((void**)&woh, g_woh);
    cudaGetSymbolAddress((void**)&wol, g_wol);
    cudaGetSymbolAddress((void**)&qhp, g_qh);
    cudaGetSymbolAddress((void**)&qlp, g_ql);
    cudaGetSymbolAddress((void**)&khp, g_kh);
    cudaGetSymbolAddress((void**)&klp, g_kl);
    cudaGetSymbolAddress((void**)&vhp, g_vh);
    cudaGetSymbolAddress((void**)&vlp, g_vl);

    cudaFuncSetAttribute(gemm_mma,
                         cudaFuncAttributeMaxDynamicSharedMemorySize, GSMEM);
    cudaFuncSetAttribute(attn_mma,
                         cudaFuncAttributeMaxDynamicSharedMemorySize, ASMEM);

    const int M = B_ * S_;       // 4096

    // launch 0: ALL prep (weights + activations + counter reset) in one grid
    prep_all<<<dim3(128, 64, 5), dim3(32, 8)>>>(
        hs, W_q, W_k, W_v, W_o, hsh, hsl, wqkvh, wqkvl, woh, wol);

    // launch 1: fused QKV projection (persistent, work-stealing on ctr 0)
    gemm_mma<<<GGRID, 256, GSMEM>>>(
        hsh, hsl, wqkvh, wqkvl, b_v, VOFF, qkv, M, NQKV, DM_, 0);

    // launch 2: RoPE + scale(log2e/8) + split to attention operand layouts
    {
        int total = B_ * S_ * 48 * 32;
        rope_split_kernel<<<(total + 255) / 256, 256>>>(
            qkv, cosb, sinb, qhp, qlp, khp, klp, vhp, vlp);
    }

    // launch 3 (PROFILED): tensor-core flash attention, 4 CTAs/SM
    attn_mma<<<dim3(S_ / 64, H_, B_), 128, ASMEM>>>(
        qhp, qlp, khp, klp, vhp, vlp, aoh, aol);

    // launch 4: O projection (persistent, work-stealing on ctr 1)
    gemm_mma<<<GGRID, 256, GSMEM>>>(
        aoh, aol, woh, wol, b_o, 0, out, M, DM_, DM_, 1);
}

// round 15
// speedup vs baseline: 1.6871x; 1.0005x over previous
#include <cuda_runtime.h>
#include <cuda_bf16.h>
#include <cstdint>

#define B_   2
#define S_   2048
#define DM_  2048
#define H_   32
#define KV_  8
#define HD_  64
#define GRP_ (H_ / KV_)   // 4
#define NQKV 3072          // fused QKV width: 2048 q | 512 k | 512 v
#define KOFF 2048
#define VOFF 2560

// ============================ PTX helpers (base sm_103 safe) ==================
__device__ __forceinline__ uint32_t smem_u32(const void* p) {
    uint32_t a;
    asm("{ .reg .u64 t; cvta.to.shared.u64 t, %1; cvt.u32.u64 %0, t; }"
        : "=r"(a) : "l"(p));
    return a;
}
__device__ __forceinline__ void cp_async16(uint32_t s, const void* g) {
    asm volatile("cp.async.cg.shared.global [%0], [%1], 16;" :: "r"(s), "l"(g));
}
#define CP_COMMIT() asm volatile("cp.async.commit_group;" ::: "memory")
#define CP_WAIT(n)  asm volatile("cp.async.wait_group %0;" :: "n"(n) : "memory")

__device__ __forceinline__ void ldsm_x4(uint32_t addr, uint32_t& r0, uint32_t& r1,
                                        uint32_t& r2, uint32_t& r3) {
    asm volatile("ldmatrix.sync.aligned.m8n8.x4.shared.b16 {%0,%1,%2,%3}, [%4];"
                 : "=r"(r0), "=r"(r1), "=r"(r2), "=r"(r3) : "r"(addr));
}
__device__ __forceinline__ void ldsm_x4t(uint32_t addr, uint32_t& r0, uint32_t& r1,
                                         uint32_t& r2, uint32_t& r3) {
    asm volatile("ldmatrix.sync.aligned.m8n8.x4.trans.shared.b16 {%0,%1,%2,%3}, [%4];"
                 : "=r"(r0), "=r"(r1), "=r"(r2), "=r"(r3) : "r"(addr));
}
__device__ __forceinline__ void mma_bf16(float* d, const uint32_t* a,
                                         uint32_t b0, uint32_t b1) {
    asm volatile("mma.sync.aligned.m16n8k16.row.col.f32.bf16.bf16.f32 "
                 "{%0,%1,%2,%3}, {%4,%5,%6,%7}, {%8,%9}, {%0,%1,%2,%3};"
                 : "+f"(d[0]), "+f"(d[1]), "+f"(d[2]), "+f"(d[3])
                 : "r"(a[0]), "r"(a[1]), "r"(a[2]), "r"(a[3]), "r"(b0), "r"(b1));
}
__device__ __forceinline__ uint32_t cvt_bf16x2(float hi_f, float lo_f) {
    uint32_t r;
    asm("cvt.rn.bf16x2.f32 %0, %1, %2;" : "=r"(r) : "f"(hi_f), "f"(lo_f));
    return r;
}
__device__ __forceinline__ float ex2f(float x) {
    float y;
    asm("ex2.approx.f32 %0, %1;" : "=f"(y) : "f"(x));
    return y;
}

// ============================ scratch =========================================
__device__ float g_qkv[(size_t)B_ * S_ * NQKV];          // 48 MB fused q|k|v
__device__ int   g_ctr[2];                               // work-steal counters

__device__ __nv_bfloat16 g_hsh[(size_t)B_ * S_ * DM_];   // activations hi/lo
__device__ __nv_bfloat16 g_hsl[(size_t)B_ * S_ * DM_];
__device__ __nv_bfloat16 g_aoh[(size_t)B_ * S_ * DM_];   // attn out hi/lo
__device__ __nv_bfloat16 g_aol[(size_t)B_ * S_ * DM_];
__device__ __nv_bfloat16 g_wqkvh[(size_t)NQKV * DM_];    // [N,K] fused weights
__device__ __nv_bfloat16 g_wqkvl[(size_t)NQKV * DM_];
__device__ __nv_bfloat16 g_woh[(size_t)DM_ * DM_];
__device__ __nv_bfloat16 g_wol[(size_t)DM_ * DM_];
// attention operands (bf16 hi/lo, post-RoPE, Q pre-scaled by log2(e)/8)
__device__ __nv_bfloat16 g_qh[(size_t)B_ * S_ * DM_];    // [row, h*64+d]
__device__ __nv_bfloat16 g_ql[(size_t)B_ * S_ * DM_];
__device__ __nv_bfloat16 g_kh[(size_t)B_ * KV_ * S_ * HD_]; // [b*KV+kvh][s][d]
__device__ __nv_bfloat16 g_kl[(size_t)B_ * KV_ * S_ * HD_];
__device__ __nv_bfloat16 g_vh[(size_t)B_ * KV_ * S_ * HD_];
__device__ __nv_bfloat16 g_vl[(size_t)B_ * KV_ * S_ * HD_];

#define GGRID   296

// ====== ONE prep launch, EXACT 1-D grid (13312 blocks, zero empty CTAs) =======
// blocks [0,8192):    activation fp32 -> bf16 hi/lo split
// blocks [8192,10240): W_q transpose+split   (64 nb x 32 kb)
// blocks [10240,10752): W_k                  (16 nb x 32 kb)
// blocks [10752,11264): W_v                  (16 nb x 32 kb)
// blocks [11264,13312): W_o                  (64 nb x 32 kb)
__global__ void prep_all(const float* __restrict__ hs,
                         const float* __restrict__ Wq, const float* __restrict__ Wk,
                         const float* __restrict__ Wv, const float* __restrict__ Wo,
                         __nv_bfloat16* __restrict__ hsh, __nv_bfloat16* __restrict__ hsl,
                         __nv_bfloat16* __restrict__ qkvh, __nv_bfloat16* __restrict__ qkvl,
                         __nv_bfloat16* __restrict__ woh,  __nv_bfloat16* __restrict__ wol)
{
    const int tid = threadIdx.y * 32 + threadIdx.x;
    const int bid = blockIdx.x;

    if (bid == 0 && tid == 0) {        // reset work-steal counters per replay
        g_ctr[0] = GGRID;
        g_ctr[1] = GGRID;
    }

    if (bid < 8192) {
        int i = bid * 256 + tid;
        float4 v = ((const float4*)hs)[i];
        uint32_t hp0 = cvt_bf16x2(v.y, v.x);
        uint32_t hp1 = cvt_bf16x2(v.w, v.z);
        float f0 = __uint_as_float(hp0 << 16);
        float f1 = __uint_as_float(hp0 & 0xffff0000u);
        float f2 = __uint_as_float(hp1 << 16);
        float f3 = __uint_as_float(hp1 & 0xffff0000u);
        ((uint32_t*)hsh)[2 * i]     = hp0;
        ((uint32_t*)hsh)[2 * i + 1] = hp1;
        ((uint32_t*)hsl)[2 * i]     = cvt_bf16x2(v.y - f1, v.x - f0);
        ((uint32_t*)hsl)[2 * i + 1] = cvt_bf16x2(v.w - f3, v.z - f2);
        return;
    }

    // weight transpose+split zones
    int w = bid - 8192;
    const float* W;
    __nv_bfloat16 *h, *l;
    size_t dof;
    int N;
    if (w < 2048)        { W = Wq; h = qkvh; l = qkvl; dof = 0;                   N = 2048; }
    else if (w < 2560)   { w -= 2048; W = Wk; h = qkvh; l = qkvl;
                           dof = (size_t)KOFF * DM_;                              N = 512; }
    else if (w < 3072)   { w -= 2560; W = Wv; h = qkvh; l = qkvl;
                           dof = (size_t)VOFF * DM_;                              N = 512; }
    else                 { w -= 3072; W = Wo; h = woh; l = wol; dof = 0;          N = 2048; }
    const int n0 = (w >> 5) * 32;
    const int k0 = (w & 31) * 64;

    __shared__ float ts[64][33];
    const int tx = threadIdx.x, ty = threadIdx.y;
    for (int i = ty; i < 64; i += 8)
        ts[i][tx] = W[(size_t)(k0 + i) * N + n0 + tx];
    __syncthreads();
    for (int i = ty; i < 32; i += 8) {
        const float x0 = ts[2 * tx][i];
        const float x1 = ts[2 * tx + 1][i];
        const uint32_t hp = cvt_bf16x2(x1, x0);
        const float f0 = __uint_as_float(hp << 16);
        const float f1 = __uint_as_float(hp & 0xffff0000u);
        const size_t o = dof + (size_t)(n0 + i) * DM_ + k0 + 2 * tx;
        *(uint32_t*)(h + o) = hp;
        *(uint32_t*)(l + o) = cvt_bf16x2(x1 - f1, x0 - f0);
    }
}

// ====== persistent warp-MMA GEMM, 3-term compensated, WORK-STEALING (r14) =====
#define TILE_B  8192
#define STAGE_B (4 * TILE_B)
#define NSTG    3
#define GSMEM   (NSTG * STAGE_B + 16)   // +16: next-tile broadcast word

__global__ __launch_bounds__(256, 2) void gemm_mma(
    const __nv_bfloat16* __restrict__ Ah, const __nv_bfloat16* __restrict__ Al,
    const __nv_bfloat16* __restrict__ Bh, const __nv_bfloat16* __restrict__ Bl,
    const float* __restrict__ bias, int boff, float* __restrict__ C,
    int M, int N, int K, int ctr_id)
{
    extern __shared__ char smem[];
    const uint32_t sb = smem_u32(smem);
    int* snext = (int*)(smem + NSTG * STAGE_B);
    const int tid  = threadIdx.x;
    const int lane = tid & 31;
    const int wid  = tid >> 5;
    const int wm   = wid >> 2;
    const int wn   = wid & 3;
    const int K32 = K / 32;
    const int nx = N >> 7;
    const int ntiles = (M >> 7) * nx;

    const int lr0 = tid >> 2, lc = tid & 3;
    const int lr1 = lr0 + 64;
    const uint32_t so0 = (uint32_t)lr0 * 64 + ((uint32_t)(lc ^ ((lr0 >> 1) & 3)) << 4);
    const uint32_t so1 = (uint32_t)lr1 * 64 + ((uint32_t)(lc ^ ((lr1 >> 1) & 3)) << 4);
    const int ge = lc * 8;

    const int lrow = lane & 15, half = lane >> 4;
    const uint32_t lsw = (uint32_t)((lrow >> 1) & 3);
    const uint32_t a_row_off = (uint32_t)(wm * 64 + lrow) * 64;
    const uint32_t b_row_off = (uint32_t)(wn * 32 + lrow) * 64;

    int t = blockIdx.x;
    while (t < ntiles) {
        const int m0 = (t / nx) << 7;
        const int n0 = (t % nx) << 7;

        float acc[4][4][4];
#pragma unroll
        for (int i = 0; i < 4; i++)
#pragma unroll
            for (int j = 0; j < 4; j++)
#pragma unroll
                for (int r = 0; r < 4; r++) acc[i][j][r] = 0.0f;

#define LOAD_STAGE(kt)                                                           \
    do {                                                                         \
        const int _k0 = (kt) * 32;                                               \
        const uint32_t _st = sb + ((kt) % NSTG) * STAGE_B;                       \
        size_t _a0 = (size_t)(m0 + lr0) * K + _k0 + ge;                          \
        size_t _a1 = (size_t)(m0 + lr1) * K + _k0 + ge;                          \
        size_t _b0 = (size_t)(n0 + lr0) * K + _k0 + ge;                          \
        size_t _b1 = (size_t)(n0 + lr1) * K + _k0 + ge;                          \
        cp_async16(_st + so0,              Ah + _a0);                            \
        cp_async16(_st + so1,              Ah + _a1);                            \
        cp_async16(_st + TILE_B + so0,     Al + _a0);                            \
        cp_async16(_st + TILE_B + so1,     Al + _a1);                            \
        cp_async16(_st + 2 * TILE_B + so0, Bh + _b0);                            \
        cp_async16(_st + 2 * TILE_B + so1, Bh + _b1);                            \
        cp_async16(_st + 3 * TILE_B + so0, Bl + _b0);                            \
        cp_async16(_st + 3 * TILE_B + so1, Bl + _b1);                            \
    } while (0)

        __syncthreads();
        LOAD_STAGE(0); CP_COMMIT();
        LOAD_STAGE(1); CP_COMMIT();

        for (int kt = 0; kt < K32; kt++) {
            CP_WAIT(1);
            __syncthreads();
            if (kt + 2 < K32) LOAD_STAGE(kt + 2);
            CP_COMMIT();

            const uint32_t st = sb + (kt % NSTG) * STAGE_B;
#pragma unroll
            for (int ks = 0; ks < 2; ks++) {
                const uint32_t cp0 = (((uint32_t)(ks * 2 + half)) ^ lsw) << 4;

                uint32_t bh[8], bl[8];
#pragma unroll
                for (int p = 0; p < 2; p++) {
                    uint32_t q0, q1, q2, q3;
                    ldsm_x4(st + 2 * TILE_B + b_row_off + p * 1024 + cp0, q0, q1, q2, q3);
                    bh[4 * p + 0] = q0; bh[4 * p + 1] = q2;
                    bh[4 * p + 2] = q1; bh[4 * p + 3] = q3;
                    ldsm_x4(st + 3 * TILE_B + b_row_off + p * 1024 + cp0, q0, q1, q2, q3);
                    bl[4 * p + 0] = q0; bl[4 * p + 1] = q2;
                    bl[4 * p + 2] = q1; bl[4 * p + 3] = q3;
                }

                uint32_t a[4][4];
#pragma unroll
                for (int i = 0; i < 4; i++)
                    ldsm_x4(st + a_row_off + i * 1024 + cp0,
                            a[i][0], a[i][1], a[i][2], a[i][3]);

#pragma unroll
                for (int i = 0; i < 4; i++)
#pragma unroll
                    for (int j = 0; j < 4; j++)
                        mma_bf16(acc[i][j], a[i], bh[2 * j], bh[2 * j + 1]);
#pragma unroll
                for (int i = 0; i < 4; i++)
#pragma unroll
                    for (int j = 0; j < 4; j++)
                        mma_bf16(acc[i][j], a[i], bl[2 * j], bl[2 * j + 1]);

#pragma unroll
                for (int i = 0; i < 4; i++)
                    ldsm_x4(st + TILE_B + a_row_off + i * 1024 + cp0,
                            a[i][0], a[i][1], a[i][2], a[i][3]);
#pragma unroll
                for (int i = 0; i < 4; i++)
#pragma unroll
                    for (int j = 0; j < 4; j++)
                        mma_bf16(acc[i][j], a[i], bh[2 * j], bh[2 * j + 1]);
            }
        }
#undef LOAD_STAGE

        // grab next tile early (ATOMG latency hides behind the epilogue stores)
        if (tid == 0) *snext = atomicAdd(&g_ctr[ctr_id], 1);

#pragma unroll
        for (int i = 0; i < 4; i++) {
            const int row = m0 + wm * 64 + i * 16 + (lane >> 2);
#pragma unroll
            for (int j = 0; j < 4; j++) {
                const int col = n0 + wn * 32 + j * 8 + (lane & 3) * 2;
                float b0 = 0.f, b1 = 0.f;
                const int bi = col - boff;
                if (bias && bi >= 0) { b0 = bias[bi]; b1 = bias[bi + 1]; }
                float2 v0, v1;
                v0.x = acc[i][j][0] + b0; v0.y = acc[i][j][1] + b1;
                v1.x = acc[i][j][2] + b0; v1.y = acc[i][j][3] + b1;
                *(float2*)(C + (size_t)row * N + col)       = v0;
                *(float2*)(C + (size_t)(row + 8) * N + col) = v1;
            }
        }

        __syncthreads();          // snext visible to all threads
        t = *snext;
    }
}

// ====== RoPE + scale + bf16 hi/lo split, vectorized (4 elems/thread) ==========
// thread -> (row r, pseudo-head hh 0..47, pair-base d2 = 2*(idx&15))
// handles elements d2, d2+1 (with rope partners d2+32, d2+33); packed 4B stores.
#define QSCALE 0.1803368801111204f   // 0.125 * log2(e)

__global__ void rope_split_kernel(const float* __restrict__ qkv,
                                  const float* __restrict__ cosb,
                                  const float* __restrict__ sinb,
                                  __nv_bfloat16* __restrict__ qh, __nv_bfloat16* __restrict__ ql,
                                  __nv_bfloat16* __restrict__ kh, __nv_bfloat16* __restrict__ kl,
                                  __nv_bfloat16* __restrict__ vh, __nv_bfloat16* __restrict__ vl)
{
    int idx = blockIdx.x * blockDim.x + threadIdx.x;
    if (idx >= B_ * S_ * 48 * 16) return;
    const int d2 = (idx & 15) << 1;          // 0..30, even
    const int hh = (idx >> 4) % 48;
    const int r  = idx / (16 * 48);

    const float* cp = cosb + (size_t)r * HD_;
    const float* sp = sinb + (size_t)r * HD_;
    const float2 c1 = *(const float2*)(cp + d2);
    const float2 s1 = *(const float2*)(sp + d2);
    const float2 c2 = *(const float2*)(cp + d2 + 32);
    const float2 s2 = *(const float2*)(sp + d2 + 32);

    __nv_bfloat16 *dh, *dl;
    size_t doff;
    float y1x, y1y, y2x, y2y;
    if (hh < 32) {                           // q: rope + QSCALE
        const float* p = qkv + (size_t)r * NQKV + hh * HD_;
        const float2 a = *(const float2*)(p + d2);
        const float2 b = *(const float2*)(p + d2 + 32);
        y1x = (a.x * c1.x - b.x * s1.x) * QSCALE;
        y1y = (a.y * c1.y - b.y * s1.y) * QSCALE;
        y2x = (b.x * c2.x + a.x * s2.x) * QSCALE;
        y2y = (b.y * c2.y + a.y * s2.y) * QSCALE;
        dh = qh; dl = ql;
        doff = (size_t)r * DM_ + hh * HD_ + d2;
    } else if (hh < 40) {                    // k: rope
        const int kvh = hh - 32;
        const float* p = qkv + (size_t)r * NQKV + KOFF + kvh * HD_;
        const float2 a = *(const float2*)(p + d2);
        const float2 b = *(const float2*)(p + d2 + 32);
        y1x = a.x * c1.x - b.x * s1.x;
        y1y = a.y * c1.y - b.y * s1.y;
        y2x = b.x * c2.x + a.x * s2.x;
        y2y = b.y * c2.y + a.y * s2.y;
        const int bb = r >> 11, s = r & (S_ - 1);
        dh = kh; dl = kl;
        doff = ((size_t)(bb * KV_ + kvh) * S_ + s) * HD_ + d2;
    } else {                                 // v: passthrough
        const int kvh = hh - 40;
        const float* p = qkv + (size_t)r * NQKV + VOFF + kvh * HD_;
        const float2 a = *(const float2*)(p + d2);
        const float2 b = *(const float2*)(p + d2 + 32);
        y1x = a.x; y1y = a.y; y2x = b.x; y2y = b.y;
        const int bb = r >> 11, s = r & (S_ - 1);
        dh = vh; dl = vl;
        doff = ((size_t)(bb * KV_ + kvh) * S_ + s) * HD_ + d2;
    }
    const uint32_t h1 = cvt_bf16x2(y1y, y1x);
    const uint32_t h2 = cvt_bf16x2(y2y, y2x);
    const float g0 = __uint_as_float(h1 << 16);
    const float g1 = __uint_as_float(h1 & 0xffff0000u);
    const float g2 = __uint_as_float(h2 << 16);
    const float g3 = __uint_as_float(h2 & 0xffff0000u);
    *(uint32_t*)(dh + doff)      = h1;
    *(uint32_t*)(dh + doff + 32) = h2;
    *(uint32_t*)(dl + doff)      = cvt_bf16x2(y1y - g1, y1x - g0);
    *(uint32_t*)(dl + doff + 32) = cvt_bf16x2(y2y - g3, y2x - g2);
}

// =========== tensor-core flash attention (3-term split-bf16, EXACT r14) =======
#define AQ_L   8192
#define AKV0   16384
#define AKV_ST 16384
#define ASMEM  49152

__global__ __launch_bounds__(128, 4) void attn_mma(
    const __nv_bfloat16* __restrict__ qh, const __nv_bfloat16* __restrict__ ql,
    const __nv_bfloat16* __restrict__ kh, const __nv_bfloat16* __restrict__ kl,
    const __nv_bfloat16* __restrict__ vh, const __nv_bfloat16* __restrict__ vl,
    __nv_bfloat16* __restrict__ oh, __nv_bfloat16* __restrict__ ol)
{
    extern __shared__ char smem[];
    const uint32_t sb = smem_u32(smem);
    const int tid  = threadIdx.x;
    const int lane = tid & 31;
    const int warp = tid >> 5;
    const int wr0  = warp * 16;
    const int m0 = (gridDim.x - 1 - blockIdx.x) * 64;    // heavy tiles first
    const int h  = blockIdx.y;
    const int b  = blockIdx.z;
    const int kvh = h >> 2;

    const size_t kvbase = (size_t)(b * KV_ + kvh) * S_ * HD_;

    {
        const size_t qg = (size_t)(b * S_ + m0) * DM_ + h * HD_;
#pragma unroll
        for (int i = 0; i < 4; i++) {
            int c = tid + 128 * i;
            int row = c >> 3, u = c & 7;
            uint32_t ad = sb + row * 128 + (((uint32_t)(u ^ (row & 7))) << 4);
            cp_async16(ad,          qh + qg + (size_t)row * DM_ + u * 8);
            cp_async16(ad + AQ_L,   ql + qg + (size_t)row * DM_ + u * 8);
        }
    }
    CP_COMMIT();

    const int NT = (m0 >> 5) + 2;

#define LOAD_KV(t)                                                                \
    do {                                                                          \
        const int _j0 = (t) * 32;                                                 \
        const uint32_t _st = sb + AKV0 + ((t) & 1) * AKV_ST;                      \
        _Pragma("unroll")                                                         \
        for (int _i = 0; _i < 2; _i++) {                                          \
            int _c = tid * 2 + _i;                                                \
            int _r = _c >> 3, _u = _c & 7;                                        \
            uint32_t _ad = _st + _r * 128 + (((uint32_t)(_u ^ (_r & 7))) << 4);   \
            size_t _g = kvbase + (size_t)(_j0 + _r) * HD_ + _u * 8;               \
            cp_async16(_ad,          kh + _g);                                    \
            cp_async16(_ad + 4096,   kl + _g);                                    \
            cp_async16(_ad + 8192,   vh + _g);                                    \
            cp_async16(_ad + 12288,  vl + _g);                                    \
        }                                                                         \
    } while (0)

    LOAD_KV(0);
    CP_COMMIT();

    CP_WAIT(1);
    __syncthreads();

    uint32_t Qh_[4][4], Ql_[4][4];
    {
        const int row = wr0 + (lane & 15);
#pragma unroll
        for (int kk = 0; kk < 4; kk++) {
            uint32_t u = (uint32_t)(kk * 2 + (lane >> 4));
            uint32_t ad = sb + row * 128 + ((u ^ (uint32_t)(row & 7)) << 4);
            ldsm_x4(ad,        Qh_[kk][0], Qh_[kk][1], Qh_[kk][2], Qh_[kk][3]);
            ldsm_x4(ad + AQ_L, Ql_[kk][0], Ql_[kk][1], Ql_[kk][2], Ql_[kk][3]);
        }
    }

    float o[8][4];
#pragma unroll
    for (int d = 0; d < 8; d++)
#pragma unroll
        for (int r = 0; r < 4; r++) o[d][r] = 0.0f;
    float m1 = -1e30f, m2 = -1e30f, l1 = 0.0f, l2 = 0.0f;

    const int row1 = m0 + wr0 + (lane >> 2);
    const int row2 = row1 + 8;

    for (int t = 0; t < NT; t++) {
        CP_WAIT(0);
        __syncthreads();
        if (t + 1 < NT) LOAD_KV(t + 1);
        CP_COMMIT();

        const int j0 = t * 32;
        if (j0 <= m0 + wr0 + 15) {
            const uint32_t st = sb + AKV0 + (t & 1) * AKV_ST;

            float s[4][4];
#pragma unroll
            for (int n = 0; n < 4; n++)
#pragma unroll
                for (int r = 0; r < 4; r++) s[n][r] = 0.0f;

#pragma unroll
            for (int np = 0; np < 2; np++) {
                const int krow = np * 16 + (lane & 15);
#pragma unroll
                for (int kk = 0; kk < 4; kk++) {
                    uint32_t u = (uint32_t)(kk * 2 + (lane >> 4));
                    uint32_t ad = st + krow * 128 + ((u ^ (uint32_t)(krow & 7)) << 4);
                    uint32_t f0, f1, f2, f3;
                    ldsm_x4(ad, f0, f1, f2, f3);
                    mma_bf16(s[2 * np],     Qh_[kk], f0, f2);
                    mma_bf16(s[2 * np + 1], Qh_[kk], f1, f3);
                    mma_bf16(s[2 * np],     Ql_[kk], f0, f2);
                    mma_bf16(s[2 * np + 1], Ql_[kk], f1, f3);
                    ldsm_x4(ad + 4096, f0, f1, f2, f3);
                    mma_bf16(s[2 * np],     Qh_[kk], f0, f2);
                    mma_bf16(s[2 * np + 1], Qh_[kk], f1, f3);
                }
            }

            if (j0 + 31 > m0 + wr0) {
#pragma unroll
                for (int n = 0; n < 4; n++) {
                    const int col = j0 + n * 8 + ((lane & 3) << 1);
                    if (col     > row1) s[n][0] = -1e30f;
                    if (col + 1 > row1) s[n][1] = -1e30f;
                    if (col     > row2) s[n][2] = -1e30f;
                    if (col + 1 > row2) s[n][3] = -1e30f;
                }
            }

            float mx1 = -1e30f, mx2 = -1e30f;
#pragma unroll
            for (int n = 0; n < 4; n++) {
                mx1 = fmaxf(mx1, fmaxf(s[n][0], s[n][1]));
                mx2 = fmaxf(mx2, fmaxf(s[n][2], s[n][3]));
            }
            mx1 = fmaxf(mx1, __shfl_xor_sync(0xffffffff, mx1, 1));
            mx1 = fmaxf(mx1, __shfl_xor_sync(0xffffffff, mx1, 2));
            mx2 = fmaxf(mx2, __shfl_xor_sync(0xffffffff, mx2, 1));
            mx2 = fmaxf(mx2, __shfl_xor_sync(0xffffffff, mx2, 2));

            const float M1 = fmaxf(m1, mx1), M2 = fmaxf(m2, mx2);
            const float c1 = ex2f(m1 - M1), c2 = ex2f(m2 - M2);
            float ls1 = 0.0f, ls2 = 0.0f;
#pragma unroll
            for (int n = 0; n < 4; n++) {
                s[n][0] = ex2f(s[n][0] - M1); ls1 += s[n][0];
                s[n][1] = ex2f(s[n][1] - M1); ls1 += s[n][1];
                s[n][2] = ex2f(s[n][2] - M2); ls2 += s[n][2];
                s[n][3] = ex2f(s[n][3] - M2); ls2 += s[n][3];
            }
            ls1 += __shfl_xor_sync(0xffffffff, ls1, 1);
            ls1 += __shfl_xor_sync(0xffffffff, ls1, 2);
            ls2 += __shfl_xor_sync(0xffffffff, ls2, 1);
            ls2 += __shfl_xor_sync(0xffffffff, ls2, 2);
            l1 = l1 * c1 + ls1;  l2 = l2 * c2 + ls2;
            m1 = M1;             m2 = M2;
#pragma unroll
            for (int d = 0; d < 8; d++) {
                o[d][0] *= c1; o[d][1] *= c1;
                o[d][2] *= c2; o[d][3] *= c2;
            }

            uint32_t ph[2][4], pl[2][4];
#pragma unroll
            for (int jj = 0; jj < 2; jj++) {
#pragma unroll
                for (int q = 0; q < 4; q++) {
                    const int n = 2 * jj + (q >> 1);
                    const int r = (q & 1) * 2;
                    const float a = s[n][r], bq = s[n][r + 1];
                    const uint32_t hp = cvt_bf16x2(bq, a);
                    const float fa = __uint_as_float(hp << 16);
                    const float fb = __uint_as_float(hp & 0xffff0000u);
                    ph[jj][q] = hp;
                    pl[jj][q] = cvt_bf16x2(bq - fb, a - fa);
                }
            }

#pragma unroll
            for (int dg = 0; dg < 4; dg++) {
#pragma unroll
                for (int jj = 0; jj < 2; jj++) {
                    const int vrow = jj * 16 + (lane & 15);
                    uint32_t u = (uint32_t)(dg * 2 + (lane >> 4));
                    uint32_t ad = st + 8192 + vrow * 128 + ((u ^ (uint32_t)(vrow & 7)) << 4);
                    uint32_t f0, f1, f2, f3;
                    ldsm_x4t(ad, f0, f1, f2, f3);
                    mma_bf16(o[2 * dg],     ph[jj], f0, f1);
                    mma_bf16(o[2 * dg + 1], ph[jj], f2, f3);
                    mma_bf16(o[2 * dg],     pl[jj], f0, f1);
                    mma_bf16(o[2 * dg + 1], pl[jj], f2, f3);
                    ldsm_x4t(ad + 4096, f0, f1, f2, f3);
                    mma_bf16(o[2 * dg],     ph[jj], f0, f1);
                    mma_bf16(o[2 * dg + 1], ph[jj], f2, f3);
                }
            }
        }
    }
#undef LOAD_KV

    const float inv1 = 1.0f / l1;
    const float inv2 = 1.0f / l2;
#pragma unroll
    for (int d = 0; d < 8; d++) {
        const int col = h * HD_ + d * 8 + ((lane & 3) << 1);
        {
            size_t ad = (size_t)(b * S_ + row1) * DM_ + col;
            const float x0 = o[d][0] * inv1, x1 = o[d][1] * inv1;
            const uint32_t hp = cvt_bf16x2(x1, x0);
            const float f0 = __uint_as_float(hp << 16);
            const float f1 = __uint_as_float(hp & 0xffff0000u);
            *(uint32_t*)(oh + ad) = hp;
            *(uint32_t*)(ol + ad) = cvt_bf16x2(x1 - f1, x0 - f0);
        }
        {
            size_t ad = (size_t)(b * S_ + row2) * DM_ + col;
            const float x0 = o[d][2] * inv2, x1 = o[d][3] * inv2;
            const uint32_t hp = cvt_bf16x2(x1, x0);
            const float f0 = __uint_as_float(hp << 16);
            const float f1 = __uint_as_float(hp & 0xffff0000u);
            *(uint32_t*)(oh + ad) = hp;
            *(uint32_t*)(ol + ad) = cvt_bf16x2(x1 - f1, x0 - f0);
        }
    }
}

// ================================ launch ======================================
extern "C" void kernel_launch(void* const* d_in, const int* in_sizes, int n_in,
                              void* d_out, int out_size)
{
    const float* hs    = (const float*)d_in[0];
    const float* cosb  = (const float*)d_in[2];
    const float* sinb  = (const float*)d_in[3];
    const float* W_q   = (const float*)d_in[4];
    const float* W_k   = (const float*)d_in[5];
    const float* W_v   = (const float*)d_in[6];
    const float* b_v   = (const float*)d_in[7];
    const float* W_o   = (const float*)d_in[8];
    const float* b_o   = (const float*)d_in[9];
    float* out = (float*)d_out;

    float* qkv;
    cudaGetSymbolAddress((void**)&qkv, g_qkv);
    __nv_bfloat16 *hsh, *hsl, *aoh, *aol, *wqkvh, *wqkvl, *woh, *wol;
    __nv_bfloat16 *qhp, *qlp, *khp, *klp, *vhp, *vlp;
    cudaGetSymbolAddress((void**)&hsh, g_hsh);
    cudaGetSymbolAddress((void**)&hsl, g_hsl);
    cudaGetSymbolAddress((void**)&aoh, g_aoh);
    cudaGetSymbolAddress((void**)&aol, g_aol);
    cudaGetSymbolAddress((void**)&wqkvh, g_wqkvh);
    cudaGetSymbolAddress((void**)&wqkvl, g_wqkvl);
    cudaGetSymbolAddress((void**)&woh, g_woh);
    cudaGetSymbolAddress((void**)&wol, g_wol);
    cudaGetSymbolAddress((void**)&qhp, g_qh);
    cudaGetSymbolAddress((void**)&qlp, g_ql);
    cudaGetSymbolAddress((void**)&khp, g_kh);
    cudaGetSymbolAddress((void**)&klp, g_kl);
    cudaGetSymbolAddress((void**)&vhp, g_vh);
    cudaGetSymbolAddress((void**)&vlp, g_vl);

    cudaFuncSetAttribute(gemm_mma,
                         cudaFuncAttributeMaxDynamicSharedMemorySize, GSMEM);
    cudaFuncSetAttribute(attn_mma,
                         cudaFuncAttributeMaxDynamicSharedMemorySize, ASMEM);

    const int M = B_ * S_;       // 4096

    // launch 0: ALL prep (weights + activations + counter reset), exact grid
    prep_all<<<13312, dim3(32, 8)>>>(
        hs, W_q, W_k, W_v, W_o, hsh, hsl, wqkvh, wqkvl, woh, wol);

    // launch 1: fused QKV projection (persistent, work-stealing on ctr 0)
    gemm_mma<<<GGRID, 256, GSMEM>>>(
        hsh, hsl, wqkvh, wqkvl, b_v, VOFF, qkv, M, NQKV, DM_, 0);

    // launch 2: RoPE + scale(log2e/8) + split, vectorized
    {
        int total = B_ * S_ * 48 * 16;
        rope_split_kernel<<<(total + 255) / 256, 256>>>(
            qkv, cosb, sinb, qhp, qlp, khp, klp, vhp, vlp);
    }

    // launch 3 (PROFILED): tensor-core flash attention, 4 CTAs/SM
    attn_mma<<<dim3(S_ / 64, H_, B_), 128, ASMEM>>>(
        qhp, qlp, khp, klp, vhp, vlp, aoh, aol);

    // launch 4: O projection (persistent, work-stealing on ctr 1)
    gemm_mma<<<GGRID, 256, GSMEM>>>(
        aoh, aol, woh, wol, b_o, 0, out, M, DM_, DM_, 1);
}

// round 16
// speedup vs baseline: 1.6952x; 1.0048x over previous
#include <cuda_runtime.h>
#include <cuda_bf16.h>
#include <cstdint>

#define B_   2
#define S_   2048
#define DM_  2048
#define H_   32
#define KV_  8
#define HD_  64
#define GRP_ (H_ / KV_)   // 4
#define NQKV 3072          // fused QKV width: 2048 q | 512 k | 512 v
#define KOFF 2048
#define VOFF 2560

// ============================ PTX helpers (base sm_103 safe) ==================
__device__ __forceinline__ uint32_t smem_u32(const void* p) {
    uint32_t a;
    asm("{ .reg .u64 t; cvta.to.shared.u64 t, %1; cvt.u32.u64 %0, t; }"
        : "=r"(a) : "l"(p));
    return a;
}
__device__ __forceinline__ void cp_async16(uint32_t s, const void* g) {
    asm volatile("cp.async.cg.shared.global [%0], [%1], 16;" :: "r"(s), "l"(g));
}
#define CP_COMMIT() asm volatile("cp.async.commit_group;" ::: "memory")
#define CP_WAIT(n)  asm volatile("cp.async.wait_group %0;" :: "n"(n) : "memory")

__device__ __forceinline__ void ldsm_x4(uint32_t addr, uint32_t& r0, uint32_t& r1,
                                        uint32_t& r2, uint32_t& r3) {
    asm volatile("ldmatrix.sync.aligned.m8n8.x4.shared.b16 {%0,%1,%2,%3}, [%4];"
                 : "=r"(r0), "=r"(r1), "=r"(r2), "=r"(r3) : "r"(addr));
}
__device__ __forceinline__ void ldsm_x4t(uint32_t addr, uint32_t& r0, uint32_t& r1,
                                         uint32_t& r2, uint32_t& r3) {
    asm volatile("ldmatrix.sync.aligned.m8n8.x4.trans.shared.b16 {%0,%1,%2,%3}, [%4];"
                 : "=r"(r0), "=r"(r1), "=r"(r2), "=r"(r3) : "r"(addr));
}
__device__ __forceinline__ void mma_bf16(float* d, const uint32_t* a,
                                         uint32_t b0, uint32_t b1) {
    asm volatile("mma.sync.aligned.m16n8k16.row.col.f32.bf16.bf16.f32 "
                 "{%0,%1,%2,%3}, {%4,%5,%6,%7}, {%8,%9}, {%0,%1,%2,%3};"
                 : "+f"(d[0]), "+f"(d[1]), "+f"(d[2]), "+f"(d[3])
                 : "r"(a[0]), "r"(a[1]), "r"(a[2]), "r"(a[3]), "r"(b0), "r"(b1));
}
__device__ __forceinline__ uint32_t cvt_bf16x2(float hi_f, float lo_f) {
    uint32_t r;
    asm("cvt.rn.bf16x2.f32 %0, %1, %2;" : "=r"(r) : "f"(hi_f), "f"(lo_f));
    return r;
}
__device__ __forceinline__ float ex2f(float x) {
    float y;
    asm("ex2.approx.f32 %0, %1;" : "=f"(y) : "f"(x));
    return y;
}

// ============================ scratch =========================================
__device__ float g_qkv[(size_t)B_ * S_ * NQKV];          // 48 MB fused q|k|v
__device__ int   g_ctr[2];                               // work-steal counters

__device__ __nv_bfloat16 g_hsh[(size_t)B_ * S_ * DM_];   // activations hi/lo
__device__ __nv_bfloat16 g_hsl[(size_t)B_ * S_ * DM_];
__device__ __nv_bfloat16 g_aoh[(size_t)B_ * S_ * DM_];   // attn out hi/lo
__device__ __nv_bfloat16 g_aol[(size_t)B_ * S_ * DM_];
__device__ __nv_bfloat16 g_wqkvh[(size_t)NQKV * DM_];    // [N,K] fused weights
__device__ __nv_bfloat16 g_wqkvl[(size_t)NQKV * DM_];
__device__ __nv_bfloat16 g_woh[(size_t)DM_ * DM_];
__device__ __nv_bfloat16 g_wol[(size_t)DM_ * DM_];
// attention operands (bf16 hi/lo, post-RoPE, Q pre-scaled by log2(e)/8)
__device__ __nv_bfloat16 g_qh[(size_t)B_ * S_ * DM_];    // [row, h*64+d]
__device__ __nv_bfloat16 g_ql[(size_t)B_ * S_ * DM_];
__device__ __nv_bfloat16 g_kh[(size_t)B_ * KV_ * S_ * HD_]; // [b*KV+kvh][s][d]
__device__ __nv_bfloat16 g_kl[(size_t)B_ * KV_ * S_ * HD_];
__device__ __nv_bfloat16 g_vh[(size_t)B_ * KV_ * S_ * HD_];
__device__ __nv_bfloat16 g_vl[(size_t)B_ * KV_ * S_ * HD_];

#define GGRID   296

// ====== ONE prep launch, EXACT 1-D grid (13312 blocks, zero empty CTAs) =======
__global__ void prep_all(const float* __restrict__ hs,
                         const float* __restrict__ Wq, const float* __restrict__ Wk,
                         const float* __restrict__ Wv, const float* __restrict__ Wo,
                         __nv_bfloat16* __restrict__ hsh, __nv_bfloat16* __restrict__ hsl,
                         __nv_bfloat16* __restrict__ qkvh, __nv_bfloat16* __restrict__ qkvl,
                         __nv_bfloat16* __restrict__ woh,  __nv_bfloat16* __restrict__ wol)
{
    const int tid = threadIdx.y * 32 + threadIdx.x;
    const int bid = blockIdx.x;

    if (bid == 0 && tid == 0) {        // reset work-steal counters per replay
        g_ctr[0] = GGRID;
        g_ctr[1] = GGRID;
    }

    if (bid < 8192) {
        int i = bid * 256 + tid;
        float4 v = ((const float4*)hs)[i];
        uint32_t hp0 = cvt_bf16x2(v.y, v.x);
        uint32_t hp1 = cvt_bf16x2(v.w, v.z);
        float f0 = __uint_as_float(hp0 << 16);
        float f1 = __uint_as_float(hp0 & 0xffff0000u);
        float f2 = __uint_as_float(hp1 << 16);
        float f3 = __uint_as_float(hp1 & 0xffff0000u);
        ((uint32_t*)hsh)[2 * i]     = hp0;
        ((uint32_t*)hsh)[2 * i + 1] = hp1;
        ((uint32_t*)hsl)[2 * i]     = cvt_bf16x2(v.y - f1, v.x - f0);
        ((uint32_t*)hsl)[2 * i + 1] = cvt_bf16x2(v.w - f3, v.z - f2);
        return;
    }

    int w = bid - 8192;
    const float* W;
    __nv_bfloat16 *h, *l;
    size_t dof;
    int N;
    if (w < 2048)        { W = Wq; h = qkvh; l = qkvl; dof = 0;                   N = 2048; }
    else if (w < 2560)   { w -= 2048; W = Wk; h = qkvh; l = qkvl;
                           dof = (size_t)KOFF * DM_;                              N = 512; }
    else if (w < 3072)   { w -= 2560; W = Wv; h = qkvh; l = qkvl;
                           dof = (size_t)VOFF * DM_;                              N = 512; }
    else                 { w -= 3072; W = Wo; h = woh; l = wol; dof = 0;          N = 2048; }
    const int n0 = (w >> 5) * 32;
    const int k0 = (w & 31) * 64;

    __shared__ float ts[64][33];
    const int tx = threadIdx.x, ty = threadIdx.y;
    for (int i = ty; i < 64; i += 8)
        ts[i][tx] = W[(size_t)(k0 + i) * N + n0 + tx];
    __syncthreads();
    for (int i = ty; i < 32; i += 8) {
        const float x0 = ts[2 * tx][i];
        const float x1 = ts[2 * tx + 1][i];
        const uint32_t hp = cvt_bf16x2(x1, x0);
        const float f0 = __uint_as_float(hp << 16);
        const float f1 = __uint_as_float(hp & 0xffff0000u);
        const size_t o = dof + (size_t)(n0 + i) * DM_ + k0 + 2 * tx;
        *(uint32_t*)(h + o) = hp;
        *(uint32_t*)(l + o) = cvt_bf16x2(x1 - f1, x0 - f0);
    }
}

// ====== persistent warp-MMA GEMM, 3-term compensated, WORK-STEALING (r15) =====
#define TILE_B  8192
#define STAGE_B (4 * TILE_B)
#define NSTG    3
#define GSMEM   (NSTG * STAGE_B + 16)   // +16: next-tile broadcast word

__global__ __launch_bounds__(256, 2) void gemm_mma(
    const __nv_bfloat16* __restrict__ Ah, const __nv_bfloat16* __restrict__ Al,
    const __nv_bfloat16* __restrict__ Bh, const __nv_bfloat16* __restrict__ Bl,
    const float* __restrict__ bias, int boff, float* __restrict__ C,
    int M, int N, int K, int ctr_id)
{
    extern __shared__ char smem[];
    const uint32_t sb = smem_u32(smem);
    int* snext = (int*)(smem + NSTG * STAGE_B);
    const int tid  = threadIdx.x;
    const int lane = tid & 31;
    const int wid  = tid >> 5;
    const int wm   = wid >> 2;
    const int wn   = wid & 3;
    const int K32 = K / 32;
    const int nx = N >> 7;
    const int ntiles = (M >> 7) * nx;

    const int lr0 = tid >> 2, lc = tid & 3;
    const int lr1 = lr0 + 64;
    const uint32_t so0 = (uint32_t)lr0 * 64 + ((uint32_t)(lc ^ ((lr0 >> 1) & 3)) << 4);
    const uint32_t so1 = (uint32_t)lr1 * 64 + ((uint32_t)(lc ^ ((lr1 >> 1) & 3)) << 4);
    const int ge = lc * 8;

    const int lrow = lane & 15, half = lane >> 4;
    const uint32_t lsw = (uint32_t)((lrow >> 1) & 3);
    const uint32_t a_row_off = (uint32_t)(wm * 64 + lrow) * 64;
    const uint32_t b_row_off = (uint32_t)(wn * 32 + lrow) * 64;

    int t = blockIdx.x;
    while (t < ntiles) {
        const int m0 = (t / nx) << 7;
        const int n0 = (t % nx) << 7;

        float acc[4][4][4];
#pragma unroll
        for (int i = 0; i < 4; i++)
#pragma unroll
            for (int j = 0; j < 4; j++)
#pragma unroll
                for (int r = 0; r < 4; r++) acc[i][j][r] = 0.0f;

#define LOAD_STAGE(kt)                                                           \
    do {                                                                         \
        const int _k0 = (kt) * 32;                                               \
        const uint32_t _st = sb + ((kt) % NSTG) * STAGE_B;                       \
        size_t _a0 = (size_t)(m0 + lr0) * K + _k0 + ge;                          \
        size_t _a1 = (size_t)(m0 + lr1) * K + _k0 + ge;                          \
        size_t _b0 = (size_t)(n0 + lr0) * K + _k0 + ge;                          \
        size_t _b1 = (size_t)(n0 + lr1) * K + _k0 + ge;                          \
        cp_async16(_st + so0,              Ah + _a0);                            \
        cp_async16(_st + so1,              Ah + _a1);                            \
        cp_async16(_st + TILE_B + so0,     Al + _a0);                            \
        cp_async16(_st + TILE_B + so1,     Al + _a1);                            \
        cp_async16(_st + 2 * TILE_B + so0, Bh + _b0);                            \
        cp_async16(_st + 2 * TILE_B + so1, Bh + _b1);                            \
        cp_async16(_st + 3 * TILE_B + so0, Bl + _b0);                            \
        cp_async16(_st + 3 * TILE_B + so1, Bl + _b1);                            \
    } while (0)

        __syncthreads();
        LOAD_STAGE(0); CP_COMMIT();
        LOAD_STAGE(1); CP_COMMIT();

        for (int kt = 0; kt < K32; kt++) {
            CP_WAIT(1);
            __syncthreads();
            if (kt + 2 < K32) LOAD_STAGE(kt + 2);
            CP_COMMIT();

            const uint32_t st = sb + (kt % NSTG) * STAGE_B;
#pragma unroll
            for (int ks = 0; ks < 2; ks++) {
                const uint32_t cp0 = (((uint32_t)(ks * 2 + half)) ^ lsw) << 4;

                uint32_t bh[8], bl[8];
#pragma unroll
                for (int p = 0; p < 2; p++) {
                    uint32_t q0, q1, q2, q3;
                    ldsm_x4(st + 2 * TILE_B + b_row_off + p * 1024 + cp0, q0, q1, q2, q3);
                    bh[4 * p + 0] = q0; bh[4 * p + 1] = q2;
                    bh[4 * p + 2] = q1; bh[4 * p + 3] = q3;
                    ldsm_x4(st + 3 * TILE_B + b_row_off + p * 1024 + cp0, q0, q1, q2, q3);
                    bl[4 * p + 0] = q0; bl[4 * p + 1] = q2;
                    bl[4 * p + 2] = q1; bl[4 * p + 3] = q3;
                }

                uint32_t a[4][4];
#pragma unroll
                for (int i = 0; i < 4; i++)
                    ldsm_x4(st + a_row_off + i * 1024 + cp0,
                            a[i][0], a[i][1], a[i][2], a[i][3]);

#pragma unroll
                for (int i = 0; i < 4; i++)
#pragma unroll
                    for (int j = 0; j < 4; j++)
                        mma_bf16(acc[i][j], a[i], bh[2 * j], bh[2 * j + 1]);
#pragma unroll
                for (int i = 0; i < 4; i++)
#pragma unroll
                    for (int j = 0; j < 4; j++)
                        mma_bf16(acc[i][j], a[i], bl[2 * j], bl[2 * j + 1]);

#pragma unroll
                for (int i = 0; i < 4; i++)
                    ldsm_x4(st + TILE_B + a_row_off + i * 1024 + cp0,
                            a[i][0], a[i][1], a[i][2], a[i][3]);
#pragma unroll
                for (int i = 0; i < 4; i++)
#pragma unroll
                    for (int j = 0; j < 4; j++)
                        mma_bf16(acc[i][j], a[i], bh[2 * j], bh[2 * j + 1]);
            }
        }
#undef LOAD_STAGE

        if (tid == 0) *snext = atomicAdd(&g_ctr[ctr_id], 1);

#pragma unroll
        for (int i = 0; i < 4; i++) {
            const int row = m0 + wm * 64 + i * 16 + (lane >> 2);
#pragma unroll
            for (int j = 0; j < 4; j++) {
                const int col = n0 + wn * 32 + j * 8 + (lane & 3) * 2;
                float b0 = 0.f, b1 = 0.f;
                const int bi = col - boff;
                if (bias && bi >= 0) { b0 = bias[bi]; b1 = bias[bi + 1]; }
                float2 v0, v1;
                v0.x = acc[i][j][0] + b0; v0.y = acc[i][j][1] + b1;
                v1.x = acc[i][j][2] + b0; v1.y = acc[i][j][3] + b1;
                *(float2*)(C + (size_t)row * N + col)       = v0;
                *(float2*)(C + (size_t)(row + 8) * N + col) = v1;
            }
        }

        __syncthreads();
        t = *snext;
    }
}

// ====== RoPE + scale + bf16 hi/lo split, vectorized (r15) =====================
#define QSCALE 0.1803368801111204f   // 0.125 * log2(e)

__global__ void rope_split_kernel(const float* __restrict__ qkv,
                                  const float* __restrict__ cosb,
                                  const float* __restrict__ sinb,
                                  __nv_bfloat16* __restrict__ qh, __nv_bfloat16* __restrict__ ql,
                                  __nv_bfloat16* __restrict__ kh, __nv_bfloat16* __restrict__ kl,
                                  __nv_bfloat16* __restrict__ vh, __nv_bfloat16* __restrict__ vl)
{
    int idx = blockIdx.x * blockDim.x + threadIdx.x;
    if (idx >= B_ * S_ * 48 * 16) return;
    const int d2 = (idx & 15) << 1;
    const int hh = (idx >> 4) % 48;
    const int r  = idx / (16 * 48);

    const float* cp = cosb + (size_t)r * HD_;
    const float* sp = sinb + (size_t)r * HD_;
    const float2 c1 = *(const float2*)(cp + d2);
    const float2 s1 = *(const float2*)(sp + d2);
    const float2 c2 = *(const float2*)(cp + d2 + 32);
    const float2 s2 = *(const float2*)(sp + d2 + 32);

    __nv_bfloat16 *dh, *dl;
    size_t doff;
    float y1x, y1y, y2x, y2y;
    if (hh < 32) {
        const float* p = qkv + (size_t)r * NQKV + hh * HD_;
        const float2 a = *(const float2*)(p + d2);
        const float2 b = *(const float2*)(p + d2 + 32);
        y1x = (a.x * c1.x - b.x * s1.x) * QSCALE;
        y1y = (a.y * c1.y - b.y * s1.y) * QSCALE;
        y2x = (b.x * c2.x + a.x * s2.x) * QSCALE;
        y2y = (b.y * c2.y + a.y * s2.y) * QSCALE;
        dh = qh; dl = ql;
        doff = (size_t)r * DM_ + hh * HD_ + d2;
    } else if (hh < 40) {
        const int kvh = hh - 32;
        const float* p = qkv + (size_t)r * NQKV + KOFF + kvh * HD_;
        const float2 a = *(const float2*)(p + d2);
        const float2 b = *(const float2*)(p + d2 + 32);
        y1x = a.x * c1.x - b.x * s1.x;
        y1y = a.y * c1.y - b.y * s1.y;
        y2x = b.x * c2.x + a.x * s2.x;
        y2y = b.y * c2.y + a.y * s2.y;
        const int bb = r >> 11, s = r & (S_ - 1);
        dh = kh; dl = kl;
        doff = ((size_t)(bb * KV_ + kvh) * S_ + s) * HD_ + d2;
    } else {
        const int kvh = hh - 40;
        const float* p = qkv + (size_t)r * NQKV + VOFF + kvh * HD_;
        const float2 a = *(const float2*)(p + d2);
        const float2 b = *(const float2*)(p + d2 + 32);
        y1x = a.x; y1y = a.y; y2x = b.x; y2y = b.y;
        const int bb = r >> 11, s = r & (S_ - 1);
        dh = vh; dl = vl;
        doff = ((size_t)(bb * KV_ + kvh) * S_ + s) * HD_ + d2;
    }
    const uint32_t h1 = cvt_bf16x2(y1y, y1x);
    const uint32_t h2 = cvt_bf16x2(y2y, y2x);
    const float g0 = __uint_as_float(h1 << 16);
    const float g1 = __uint_as_float(h1 & 0xffff0000u);
    const float g2 = __uint_as_float(h2 << 16);
    const float g3 = __uint_as_float(h2 & 0xffff0000u);
    *(uint32_t*)(dh + doff)      = h1;
    *(uint32_t*)(dh + doff + 32) = h2;
    *(uint32_t*)(dl + doff)      = cvt_bf16x2(y1y - g1, y1x - g0);
    *(uint32_t*)(dl + doff + 32) = cvt_bf16x2(y2y - g3, y2x - g2);
}

// =========== tensor-core flash attention (3-term split-bf16) ==================
// r16: S-phase MMAs interleaved across all 4 accumulator chains (dependency
// distance 2 -> 4 issues) with a dual K-fragment window. Accumulation order
// per chain unchanged -> bit-identical results.
#define AQ_L   8192
#define AKV0   16384
#define AKV_ST 16384
#define ASMEM  49152

__global__ __launch_bounds__(128, 4) void attn_mma(
    const __nv_bfloat16* __restrict__ qh, const __nv_bfloat16* __restrict__ ql,
    const __nv_bfloat16* __restrict__ kh, const __nv_bfloat16* __restrict__ kl,
    const __nv_bfloat16* __restrict__ vh, const __nv_bfloat16* __restrict__ vl,
    __nv_bfloat16* __restrict__ oh, __nv_bfloat16* __restrict__ ol)
{
    extern __shared__ char smem[];
    const uint32_t sb = smem_u32(smem);
    const int tid  = threadIdx.x;
    const int lane = tid & 31;
    const int warp = tid >> 5;
    const int wr0  = warp * 16;
    const int m0 = (gridDim.x - 1 - blockIdx.x) * 64;    // heavy tiles first
    const int h  = blockIdx.y;
    const int b  = blockIdx.z;
    const int kvh = h >> 2;

    const size_t kvbase = (size_t)(b * KV_ + kvh) * S_ * HD_;

    {
        const size_t qg = (size_t)(b * S_ + m0) * DM_ + h * HD_;
#pragma unroll
        for (int i = 0; i < 4; i++) {
            int c = tid + 128 * i;
            int row = c >> 3, u = c & 7;
            uint32_t ad = sb + row * 128 + (((uint32_t)(u ^ (row & 7))) << 4);
            cp_async16(ad,          qh + qg + (size_t)row * DM_ + u * 8);
            cp_async16(ad + AQ_L,   ql + qg + (size_t)row * DM_ + u * 8);
        }
    }
    CP_COMMIT();

    const int NT = (m0 >> 5) + 2;

#define LOAD_KV(t)                                                                \
    do {                                                                          \
        const int _j0 = (t) * 32;                                                 \
        const uint32_t _st = sb + AKV0 + ((t) & 1) * AKV_ST;                      \
        _Pragma("unroll")                                                         \
        for (int _i = 0; _i < 2; _i++) {                                          \
            int _c = tid * 2 + _i;                                                \
            int _r = _c >> 3, _u = _c & 7;                                        \
            uint32_t _ad = _st + _r * 128 + (((uint32_t)(_u ^ (_r & 7))) << 4);   \
            size_t _g = kvbase + (size_t)(_j0 + _r) * HD_ + _u * 8;               \
            cp_async16(_ad,          kh + _g);                                    \
            cp_async16(_ad + 4096,   kl + _g);                                    \
            cp_async16(_ad + 8192,   vh + _g);                                    \
            cp_async16(_ad + 12288,  vl + _g);                                    \
        }                                                                         \
    } while (0)

    LOAD_KV(0);
    CP_COMMIT();

    CP_WAIT(1);
    __syncthreads();

    uint32_t Qh_[4][4], Ql_[4][4];
    {
        const int row = wr0 + (lane & 15);
#pragma unroll
        for (int kk = 0; kk < 4; kk++) {
            uint32_t u = (uint32_t)(kk * 2 + (lane >> 4));
            uint32_t ad = sb + row * 128 + ((u ^ (uint32_t)(row & 7)) << 4);
            ldsm_x4(ad,        Qh_[kk][0], Qh_[kk][1], Qh_[kk][2], Qh_[kk][3]);
            ldsm_x4(ad + AQ_L, Ql_[kk][0], Ql_[kk][1], Ql_[kk][2], Ql_[kk][3]);
        }
    }

    float o[8][4];
#pragma unroll
    for (int d = 0; d < 8; d++)
#pragma unroll
        for (int r = 0; r < 4; r++) o[d][r] = 0.0f;
    float m1 = -1e30f, m2 = -1e30f, l1 = 0.0f, l2 = 0.0f;

    const int row1 = m0 + wr0 + (lane >> 2);
    const int row2 = row1 + 8;

    for (int t = 0; t < NT; t++) {
        CP_WAIT(0);
        __syncthreads();
        if (t + 1 < NT) LOAD_KV(t + 1);
        CP_COMMIT();

        const int j0 = t * 32;
        if (j0 <= m0 + wr0 + 15) {
            const uint32_t st = sb + AKV0 + (t & 1) * AKV_ST;

            // ---- S = Q K^T (3-term, log2 domain), 4-chain interleave -----------
            float s[4][4];
#pragma unroll
            for (int n = 0; n < 4; n++)
#pragma unroll
                for (int r = 0; r < 4; r++) s[n][r] = 0.0f;

            {
                const int krow = lane & 15;                 // np0 row; np1 = +16
#pragma unroll
                for (int kk = 0; kk < 4; kk++) {
                    uint32_t u = (uint32_t)(kk * 2 + (lane >> 4));
                    uint32_t ad0 = st + krow * 128 + ((u ^ (uint32_t)(krow & 7)) << 4);
                    uint32_t ad1 = ad0 + 2048;              // (16+krow)&7 == krow&7
                    uint32_t a0, a1, a2, a3, b0, b1, b2, b3;
                    ldsm_x4(ad0, a0, a1, a2, a3);           // Kh np0
                    ldsm_x4(ad1, b0, b1, b2, b3);           // Kh np1
                    mma_bf16(s[0], Qh_[kk], a0, a2);
                    mma_bf16(s[2], Qh_[kk], b0, b2);
                    mma_bf16(s[1], Qh_[kk], a1, a3);
                    mma_bf16(s[3], Qh_[kk], b1, b3);
                    mma_bf16(s[0], Ql_[kk], a0, a2);
                    mma_bf16(s[2], Ql_[kk], b0, b2);
                    mma_bf16(s[1], Ql_[kk], a1, a3);
                    mma_bf16(s[3], Ql_[kk], b1, b3);
                    ldsm_x4(ad0 + 4096, a0, a1, a2, a3);    // Kl np0 (reuse window)
                    ldsm_x4(ad1 + 4096, b0, b1, b2, b3);    // Kl np1
                    mma_bf16(s[0], Qh_[kk], a0, a2);
                    mma_bf16(s[2], Qh_[kk], b0, b2);
                    mma_bf16(s[1], Qh_[kk], a1, a3);
                    mma_bf16(s[3], Qh_[kk], b1, b3);
                }
            }

            if (j0 + 31 > m0 + wr0) {
#pragma unroll
                for (int n = 0; n < 4; n++) {
                    const int col = j0 + n * 8 + ((lane & 3) << 1);
                    if (col     > row1) s[n][0] = -1e30f;
                    if (col + 1 > row1) s[n][1] = -1e30f;
                    if (col     > row2) s[n][2] = -1e30f;
                    if (col + 1 > row2) s[n][3] = -1e30f;
                }
            }

            float mx1 = -1e30f, mx2 = -1e30f;
#pragma unroll
            for (int n = 0; n < 4; n++) {
                mx1 = fmaxf(mx1, fmaxf(s[n][0], s[n][1]));
                mx2 = fmaxf(mx2, fmaxf(s[n][2], s[n][3]));
            }
            mx1 = fmaxf(mx1, __shfl_xor_sync(0xffffffff, mx1, 1));
            mx1 = fmaxf(mx1, __shfl_xor_sync(0xffffffff, mx1, 2));
            mx2 = fmaxf(mx2, __shfl_xor_sync(0xffffffff, mx2, 1));
            mx2 = fmaxf(mx2, __shfl_xor_sync(0xffffffff, mx2, 2));

            const float M1 = fmaxf(m1, mx1), M2 = fmaxf(m2, mx2);
            const float c1 = ex2f(m1 - M1), c2 = ex2f(m2 - M2);
            float ls1 = 0.0f, ls2 = 0.0f;
#pragma unroll
            for (int n = 0; n < 4; n++) {
                s[n][0] = ex2f(s[n][0] - M1); ls1 += s[n][0];
                s[n][1] = ex2f(s[n][1] - M1); ls1 += s[n][1];
                s[n][2] = ex2f(s[n][2] - M2); ls2 += s[n][2];
                s[n][3] = ex2f(s[n][3] - M2); ls2 += s[n][3];
            }
            ls1 += __shfl_xor_sync(0xffffffff, ls1, 1);
            ls1 += __shfl_xor_sync(0xffffffff, ls1, 2);
            ls2 += __shfl_xor_sync(0xffffffff, ls2, 1);
            ls2 += __shfl_xor_sync(0xffffffff, ls2, 2);
            l1 = l1 * c1 + ls1;  l2 = l2 * c2 + ls2;
            m1 = M1;             m2 = M2;
#pragma unroll
            for (int d = 0; d < 8; d++) {
                o[d][0] *= c1; o[d][1] *= c1;
                o[d][2] *= c2; o[d][3] *= c2;
            }

            uint32_t ph[2][4], pl[2][4];
#pragma unroll
            for (int jj = 0; jj < 2; jj++) {
#pragma unroll
                for (int q = 0; q < 4; q++) {
                    const int n = 2 * jj + (q >> 1);
                    const int r = (q & 1) * 2;
                    const float a = s[n][r], bq = s[n][r + 1];
                    const uint32_t hp = cvt_bf16x2(bq, a);
                    const float fa = __uint_as_float(hp << 16);
                    const float fb = __uint_as_float(hp & 0xffff0000u);
                    ph[jj][q] = hp;
                    pl[jj][q] = cvt_bf16x2(bq - fb, a - fa);
                }
            }

#pragma unroll
            for (int dg = 0; dg < 4; dg++) {
#pragma unroll
                for (int jj = 0; jj < 2; jj++) {
                    const int vrow = jj * 16 + (lane & 15);
                    uint32_t u = (uint32_t)(dg * 2 + (lane >> 4));
                    uint32_t ad = st + 8192 + vrow * 128 + ((u ^ (uint32_t)(vrow & 7)) << 4);
                    uint32_t f0, f1, f2, f3;
                    ldsm_x4t(ad, f0, f1, f2, f3);
                    mma_bf16(o[2 * dg],     ph[jj], f0, f1);
                    mma_bf16(o[2 * dg + 1], ph[jj], f2, f3);
                    mma_bf16(o[2 * dg],     pl[jj], f0, f1);
                    mma_bf16(o[2 * dg + 1], pl[jj], f2, f3);
                    ldsm_x4t(ad + 4096, f0, f1, f2, f3);
                    mma_bf16(o[2 * dg],     ph[jj], f0, f1);
                    mma_bf16(o[2 * dg + 1], ph[jj], f2, f3);
                }
            }
        }
    }
#undef LOAD_KV

    const float inv1 = 1.0f / l1;
    const float inv2 = 1.0f / l2;
#pragma unroll
    for (int d = 0; d < 8; d++) {
        const int col = h * HD_ + d * 8 + ((lane & 3) << 1);
        {
            size_t ad = (size_t)(b * S_ + row1) * DM_ + col;
            const float x0 = o[d][0] * inv1, x1 = o[d][1] * inv1;
            const uint32_t hp = cvt_bf16x2(x1, x0);
            const float f0 = __uint_as_float(hp << 16);
            const float f1 = __uint_as_float(hp & 0xffff0000u);
            *(uint32_t*)(oh + ad) = hp;
            *(uint32_t*)(ol + ad) = cvt_bf16x2(x1 - f1, x0 - f0);
        }
        {
            size_t ad = (size_t)(b * S_ + row2) * DM_ + col;
            const float x0 = o[d][2] * inv2, x1 = o[d][3] * inv2;
            const uint32_t hp = cvt_bf16x2(x1, x0);
            const float f0 = __uint_as_float(hp << 16);
            const float f1 = __uint_as_float(hp & 0xffff0000u);
            *(uint32_t*)(oh + ad) = hp;
            *(uint32_t*)(ol + ad) = cvt_bf16x2(x1 - f1, x0 - f0);
        }
    }
}

// ================================ launch ======================================
extern "C" void kernel_launch(void* const* d_in, const int* in_sizes, int n_in,
                              void* d_out, int out_size)
{
    const float* hs    = (const float*)d_in[0];
    const float* cosb  = (const float*)d_in[2];
    const float* sinb  = (const float*)d_in[3];
    const float* W_q   = (const float*)d_in[4];
    const float* W_k   = (const float*)d_in[5];
    const float* W_v   = (const float*)d_in[6];
    const float* b_v   = (const float*)d_in[7];
    const float* W_o   = (const float*)d_in[8];
    const float* b_o   = (const float*)d_in[9];
    float* out = (float*)d_out;

    float* qkv;
    cudaGetSymbolAddress((void**)&qkv, g_qkv);
    __nv_bfloat16 *hsh, *hsl, *aoh, *aol, *wqkvh, *wqkvl, *woh, *wol;
    __nv_bfloat16 *qhp, *qlp, *khp, *klp, *vhp, *vlp;
    cudaGetSymbolAddress((void**)&hsh, g_hsh);
    cudaGetSymbolAddress((void**)&hsl, g_hsl);
    cudaGetSymbolAddress((void**)&aoh, g_aoh);
    cudaGetSymbolAddress((void**)&aol, g_aol);
    cudaGetSymbolAddress((void**)&wqkvh, g_wqkvh);
    cudaGetSymbolAddress((void**)&wqkvl, g_wqkvl);
    cudaGetSymbolAddress((void**)&woh, g_woh);
    cudaGetSymbolAddress((void**)&wol, g_wol);
    cudaGetSymbolAddress((void**)&qhp, g_qh);
    cudaGetSymbolAddress((void**)&qlp, g_ql);
    cudaGetSymbolAddress((void**)&khp, g_kh);
    cudaGetSymbolAddress((void**)&klp, g_kl);
    cudaGetSymbolAddress((void**)&vhp, g_vh);
    cudaGetSymbolAddress((void**)&vlp, g_vl);

    cudaFuncSetAttribute(gemm_mma,
                         cudaFuncAttributeMaxDynamicSharedMemorySize, GSMEM);
    cudaFuncSetAttribute(attn_mma,
                         cudaFuncAttributeMaxDynamicSharedMemorySize, ASMEM);

    const int M = B_ * S_;       // 4096

    // launch 0: ALL prep (weights + activations + counter reset), exact grid
    prep_all<<<13312, dim3(32, 8)>>>(
        hs, W_q, W_k, W_v, W_o, hsh, hsl, wqkvh, wqkvl, woh, wol);

    // launch 1: fused QKV projection (persistent, work-stealing on ctr 0)
    gemm_mma<<<GGRID, 256, GSMEM>>>(
        hsh, hsl, wqkvh, wqkvl, b_v, VOFF, qkv, M, NQKV, DM_, 0);

    // launch 2: RoPE + scale(log2e/8) + split, vectorized
    {
        int total = B_ * S_ * 48 * 16;
        rope_split_kernel<<<(total + 255) / 256, 256>>>(
            qkv, cosb, sinb, qhp, qlp, khp, klp, vhp, vlp);
    }

    // launch 3 (PROFILED): tensor-core flash attention, 4 CTAs/SM
    attn_mma<<<dim3(S_ / 64, H_, B_), 128, ASMEM>>>(
        qhp, qlp, khp, klp, vhp, vlp, aoh, aol);

    // launch 4: O projection (persistent, work-stealing on ctr 1)
    gemm_mma<<<GGRID, 256, GSMEM>>>(
        aoh, aol, woh, wol, b_o, 0, out, M, DM_, DM_, 1);
}

// round 17
// speedup vs baseline: 1.6952x; 1.0000x over previous
#include <cuda_runtime.h>
#include <cuda_bf16.h>
#include <cstdint>

#define B_   2
#define S_   2048
#define DM_  2048
#define H_   32
#define KV_  8
#define HD_  64
#define GRP_ (H_ / KV_)   // 4
#define NQKV 3072          // fused QKV width: 2048 q | 512 k | 512 v
#define KOFF 2048
#define VOFF 2560

// ============================ PTX helpers (base sm_103 safe) ==================
__device__ __forceinline__ uint32_t smem_u32(const void* p) {
    uint32_t a;
    asm("{ .reg .u64 t; cvta.to.shared.u64 t, %1; cvt.u32.u64 %0, t; }"
        : "=r"(a) : "l"(p));
    return a;
}
__device__ __forceinline__ void cp_async16(uint32_t s, const void* g) {
    asm volatile("cp.async.cg.shared.global [%0], [%1], 16;" :: "r"(s), "l"(g));
}
#define CP_COMMIT() asm volatile("cp.async.commit_group;" ::: "memory")
#define CP_WAIT(n)  asm volatile("cp.async.wait_group %0;" :: "n"(n) : "memory")

__device__ __forceinline__ void ldsm_x4(uint32_t addr, uint32_t& r0, uint32_t& r1,
                                        uint32_t& r2, uint32_t& r3) {
    asm volatile("ldmatrix.sync.aligned.m8n8.x4.shared.b16 {%0,%1,%2,%3}, [%4];"
                 : "=r"(r0), "=r"(r1), "=r"(r2), "=r"(r3) : "r"(addr));
}
__device__ __forceinline__ void ldsm_x4t(uint32_t addr, uint32_t& r0, uint32_t& r1,
                                         uint32_t& r2, uint32_t& r3) {
    asm volatile("ldmatrix.sync.aligned.m8n8.x4.trans.shared.b16 {%0,%1,%2,%3}, [%4];"
                 : "=r"(r0), "=r"(r1), "=r"(r2), "=r"(r3) : "r"(addr));
}
__device__ __forceinline__ void mma_bf16(float* d, const uint32_t* a,
                                         uint32_t b0, uint32_t b1) {
    asm volatile("mma.sync.aligned.m16n8k16.row.col.f32.bf16.bf16.f32 "
                 "{%0,%1,%2,%3}, {%4,%5,%6,%7}, {%8,%9}, {%0,%1,%2,%3};"
                 : "+f"(d[0]), "+f"(d[1]), "+f"(d[2]), "+f"(d[3])
                 : "r"(a[0]), "r"(a[1]), "r"(a[2]), "r"(a[3]), "r"(b0), "r"(b1));
}
__device__ __forceinline__ uint32_t cvt_bf16x2(float hi_f, float lo_f) {
    uint32_t r;
    asm("cvt.rn.bf16x2.f32 %0, %1, %2;" : "=r"(r) : "f"(hi_f), "f"(lo_f));
    return r;
}
__device__ __forceinline__ float ex2f(float x) {
    float y;
    asm("ex2.approx.f32 %0, %1;" : "=f"(y) : "f"(x));
    return y;
}

// ============================ scratch =========================================
__device__ float g_qkv[(size_t)B_ * S_ * NQKV];          // 48 MB fused q|k|v
__device__ int   g_ctr[2];                               // work-steal counters

__device__ __nv_bfloat16 g_hsh[(size_t)B_ * S_ * DM_];   // activations hi/lo
__device__ __nv_bfloat16 g_hsl[(size_t)B_ * S_ * DM_];
__device__ __nv_bfloat16 g_aoh[(size_t)B_ * S_ * DM_];   // attn out hi/lo
__device__ __nv_bfloat16 g_aol[(size_t)B_ * S_ * DM_];
__device__ __nv_bfloat16 g_wqkvh[(size_t)NQKV * DM_];    // [N,K] fused weights
__device__ __nv_bfloat16 g_wqkvl[(size_t)NQKV * DM_];
__device__ __nv_bfloat16 g_woh[(size_t)DM_ * DM_];
__device__ __nv_bfloat16 g_wol[(size_t)DM_ * DM_];
// attention operands (bf16 hi/lo, post-RoPE, Q pre-scaled by log2(e)/8)
__device__ __nv_bfloat16 g_qh[(size_t)B_ * S_ * DM_];    // [row, h*64+d]
__device__ __nv_bfloat16 g_ql[(size_t)B_ * S_ * DM_];
__device__ __nv_bfloat16 g_kh[(size_t)B_ * KV_ * S_ * HD_]; // [b*KV+kvh][s][d]
__device__ __nv_bfloat16 g_kl[(size_t)B_ * KV_ * S_ * HD_];
__device__ __nv_bfloat16 g_vh[(size_t)B_ * KV_ * S_ * HD_];
__device__ __nv_bfloat16 g_vl[(size_t)B_ * KV_ * S_ * HD_];

#define GGRID   296

// ====== ONE prep launch, EXACT 1-D grid (13312 blocks, zero empty CTAs) =======
__global__ void prep_all(const float* __restrict__ hs,
                         const float* __restrict__ Wq, const float* __restrict__ Wk,
                         const float* __restrict__ Wv, const float* __restrict__ Wo,
                         __nv_bfloat16* __restrict__ hsh, __nv_bfloat16* __restrict__ hsl,
                         __nv_bfloat16* __restrict__ qkvh, __nv_bfloat16* __restrict__ qkvl,
                         __nv_bfloat16* __restrict__ woh,  __nv_bfloat16* __restrict__ wol)
{
    const int tid = threadIdx.y * 32 + threadIdx.x;
    const int bid = blockIdx.x;

    if (bid == 0 && tid == 0) {        // reset work-steal counters per replay
        g_ctr[0] = GGRID;
        g_ctr[1] = GGRID;
    }

    if (bid < 8192) {
        int i = bid * 256 + tid;
        float4 v = ((const float4*)hs)[i];
        uint32_t hp0 = cvt_bf16x2(v.y, v.x);
        uint32_t hp1 = cvt_bf16x2(v.w, v.z);
        float f0 = __uint_as_float(hp0 << 16);
        float f1 = __uint_as_float(hp0 & 0xffff0000u);
        float f2 = __uint_as_float(hp1 << 16);
        float f3 = __uint_as_float(hp1 & 0xffff0000u);
        ((uint32_t*)hsh)[2 * i]     = hp0;
        ((uint32_t*)hsh)[2 * i + 1] = hp1;
        ((uint32_t*)hsl)[2 * i]     = cvt_bf16x2(v.y - f1, v.x - f0);
        ((uint32_t*)hsl)[2 * i + 1] = cvt_bf16x2(v.w - f3, v.z - f2);
        return;
    }

    int w = bid - 8192;
    const float* W;
    __nv_bfloat16 *h, *l;
    size_t dof;
    int N;
    if (w < 2048)        { W = Wq; h = qkvh; l = qkvl; dof = 0;                   N = 2048; }
    else if (w < 2560)   { w -= 2048; W = Wk; h = qkvh; l = qkvl;
                           dof = (size_t)KOFF * DM_;                              N = 512; }
    else if (w < 3072)   { w -= 2560; W = Wv; h = qkvh; l = qkvl;
                           dof = (size_t)VOFF * DM_;                              N = 512; }
    else                 { w -= 3072; W = Wo; h = woh; l = wol; dof = 0;          N = 2048; }
    const int n0 = (w >> 5) * 32;
    const int k0 = (w & 31) * 64;

    __shared__ float ts[64][33];
    const int tx = threadIdx.x, ty = threadIdx.y;
    for (int i = ty; i < 64; i += 8)
        ts[i][tx] = W[(size_t)(k0 + i) * N + n0 + tx];
    __syncthreads();
    for (int i = ty; i < 32; i += 8) {
        const float x0 = ts[2 * tx][i];
        const float x1 = ts[2 * tx + 1][i];
        const uint32_t hp = cvt_bf16x2(x1, x0);
        const float f0 = __uint_as_float(hp << 16);
        const float f1 = __uint_as_float(hp & 0xffff0000u);
        const size_t o = dof + (size_t)(n0 + i) * DM_ + k0 + 2 * tx;
        *(uint32_t*)(h + o) = hp;
        *(uint32_t*)(l + o) = cvt_bf16x2(x1 - f1, x0 - f0);
    }
}

// ====== persistent warp-MMA GEMM, 3-term compensated, WORK-STEALING (r16) =====
#define TILE_B  8192
#define STAGE_B (4 * TILE_B)
#define NSTG    3
#define GSMEM   (NSTG * STAGE_B + 16)   // +16: next-tile broadcast word

__global__ __launch_bounds__(256, 2) void gemm_mma(
    const __nv_bfloat16* __restrict__ Ah, const __nv_bfloat16* __restrict__ Al,
    const __nv_bfloat16* __restrict__ Bh, const __nv_bfloat16* __restrict__ Bl,
    const float* __restrict__ bias, int boff, float* __restrict__ C,
    int M, int N, int K, int ctr_id)
{
    extern __shared__ char smem[];
    const uint32_t sb = smem_u32(smem);
    int* snext = (int*)(smem + NSTG * STAGE_B);
    const int tid  = threadIdx.x;
    const int lane = tid & 31;
    const int wid  = tid >> 5;
    const int wm   = wid >> 2;
    const int wn   = wid & 3;
    const int K32 = K / 32;
    const int nx = N >> 7;
    const int ntiles = (M >> 7) * nx;

    const int lr0 = tid >> 2, lc = tid & 3;
    const int lr1 = lr0 + 64;
    const uint32_t so0 = (uint32_t)lr0 * 64 + ((uint32_t)(lc ^ ((lr0 >> 1) & 3)) << 4);
    const uint32_t so1 = (uint32_t)lr1 * 64 + ((uint32_t)(lc ^ ((lr1 >> 1) & 3)) << 4);
    const int ge = lc * 8;

    const int lrow = lane & 15, half = lane >> 4;
    const uint32_t lsw = (uint32_t)((lrow >> 1) & 3);
    const uint32_t a_row_off = (uint32_t)(wm * 64 + lrow) * 64;
    const uint32_t b_row_off = (uint32_t)(wn * 32 + lrow) * 64;

    int t = blockIdx.x;
    while (t < ntiles) {
        const int m0 = (t / nx) << 7;
        const int n0 = (t % nx) << 7;

        float acc[4][4][4];
#pragma unroll
        for (int i = 0; i < 4; i++)
#pragma unroll
            for (int j = 0; j < 4; j++)
#pragma unroll
                for (int r = 0; r < 4; r++) acc[i][j][r] = 0.0f;

#define LOAD_STAGE(kt)                                                           \
    do {                                                                         \
        const int _k0 = (kt) * 32;                                               \
        const uint32_t _st = sb + ((kt) % NSTG) * STAGE_B;                       \
        size_t _a0 = (size_t)(m0 + lr0) * K + _k0 + ge;                          \
        size_t _a1 = (size_t)(m0 + lr1) * K + _k0 + ge;                          \
        size_t _b0 = (size_t)(n0 + lr0) * K + _k0 + ge;                          \
        size_t _b1 = (size_t)(n0 + lr1) * K + _k0 + ge;                          \
        cp_async16(_st + so0,              Ah + _a0);                            \
        cp_async16(_st + so1,              Ah + _a1);                            \
        cp_async16(_st + TILE_B + so0,     Al + _a0);                            \
        cp_async16(_st + TILE_B + so1,     Al + _a1);                            \
        cp_async16(_st + 2 * TILE_B + so0, Bh + _b0);                            \
        cp_async16(_st + 2 * TILE_B + so1, Bh + _b1);                            \
        cp_async16(_st + 3 * TILE_B + so0, Bl + _b0);                            \
        cp_async16(_st + 3 * TILE_B + so1, Bl + _b1);                            \
    } while (0)

        __syncthreads();
        LOAD_STAGE(0); CP_COMMIT();
        LOAD_STAGE(1); CP_COMMIT();

        for (int kt = 0; kt < K32; kt++) {
            CP_WAIT(1);
            __syncthreads();
            if (kt + 2 < K32) LOAD_STAGE(kt + 2);
            CP_COMMIT();

            const uint32_t st = sb + (kt % NSTG) * STAGE_B;
#pragma unroll
            for (int ks = 0; ks < 2; ks++) {
                const uint32_t cp0 = (((uint32_t)(ks * 2 + half)) ^ lsw) << 4;

                uint32_t bh[8], bl[8];
#pragma unroll
                for (int p = 0; p < 2; p++) {
                    uint32_t q0, q1, q2, q3;
                    ldsm_x4(st + 2 * TILE_B + b_row_off + p * 1024 + cp0, q0, q1, q2, q3);
                    bh[4 * p + 0] = q0; bh[4 * p + 1] = q2;
                    bh[4 * p + 2] = q1; bh[4 * p + 3] = q3;
                    ldsm_x4(st + 3 * TILE_B + b_row_off + p * 1024 + cp0, q0, q1, q2, q3);
                    bl[4 * p + 0] = q0; bl[4 * p + 1] = q2;
                    bl[4 * p + 2] = q1; bl[4 * p + 3] = q3;
                }

                uint32_t a[4][4];
#pragma unroll
                for (int i = 0; i < 4; i++)
                    ldsm_x4(st + a_row_off + i * 1024 + cp0,
                            a[i][0], a[i][1], a[i][2], a[i][3]);

#pragma unroll
                for (int i = 0; i < 4; i++)
#pragma unroll
                    for (int j = 0; j < 4; j++)
                        mma_bf16(acc[i][j], a[i], bh[2 * j], bh[2 * j + 1]);
#pragma unroll
                for (int i = 0; i < 4; i++)
#pragma unroll
                    for (int j = 0; j < 4; j++)
                        mma_bf16(acc[i][j], a[i], bl[2 * j], bl[2 * j + 1]);

#pragma unroll
                for (int i = 0; i < 4; i++)
                    ldsm_x4(st + TILE_B + a_row_off + i * 1024 + cp0,
                            a[i][0], a[i][1], a[i][2], a[i][3]);
#pragma unroll
                for (int i = 0; i < 4; i++)
#pragma unroll
                    for (int j = 0; j < 4; j++)
                        mma_bf16(acc[i][j], a[i], bh[2 * j], bh[2 * j + 1]);
            }
        }
#undef LOAD_STAGE

        if (tid == 0) *snext = atomicAdd(&g_ctr[ctr_id], 1);

#pragma unroll
        for (int i = 0; i < 4; i++) {
            const int row = m0 + wm * 64 + i * 16 + (lane >> 2);
#pragma unroll
            for (int j = 0; j < 4; j++) {
                const int col = n0 + wn * 32 + j * 8 + (lane & 3) * 2;
                float b0 = 0.f, b1 = 0.f;
                const int bi = col - boff;
                if (bias && bi >= 0) { b0 = bias[bi]; b1 = bias[bi + 1]; }
                float2 v0, v1;
                v0.x = acc[i][j][0] + b0; v0.y = acc[i][j][1] + b1;
                v1.x = acc[i][j][2] + b0; v1.y = acc[i][j][3] + b1;
                *(float2*)(C + (size_t)row * N + col)       = v0;
                *(float2*)(C + (size_t)(row + 8) * N + col) = v1;
            }
        }

        __syncthreads();
        t = *snext;
    }
}

// ====== RoPE + scale + bf16 hi/lo split, vectorized (r16) =====================
#define QSCALE 0.1803368801111204f   // 0.125 * log2(e)

__global__ void rope_split_kernel(const float* __restrict__ qkv,
                                  const float* __restrict__ cosb,
                                  const float* __restrict__ sinb,
                                  __nv_bfloat16* __restrict__ qh, __nv_bfloat16* __restrict__ ql,
                                  __nv_bfloat16* __restrict__ kh, __nv_bfloat16* __restrict__ kl,
                                  __nv_bfloat16* __restrict__ vh, __nv_bfloat16* __restrict__ vl)
{
    int idx = blockIdx.x * blockDim.x + threadIdx.x;
    if (idx >= B_ * S_ * 48 * 16) return;
    const int d2 = (idx & 15) << 1;
    const int hh = (idx >> 4) % 48;
    const int r  = idx / (16 * 48);

    const float* cp = cosb + (size_t)r * HD_;
    const float* sp = sinb + (size_t)r * HD_;
    const float2 c1 = *(const float2*)(cp + d2);
    const float2 s1 = *(const float2*)(sp + d2);
    const float2 c2 = *(const float2*)(cp + d2 + 32);
    const float2 s2 = *(const float2*)(sp + d2 + 32);

    __nv_bfloat16 *dh, *dl;
    size_t doff;
    float y1x, y1y, y2x, y2y;
    if (hh < 32) {
        const float* p = qkv + (size_t)r * NQKV + hh * HD_;
        const float2 a = *(const float2*)(p + d2);
        const float2 b = *(const float2*)(p + d2 + 32);
        y1x = (a.x * c1.x - b.x * s1.x) * QSCALE;
        y1y = (a.y * c1.y - b.y * s1.y) * QSCALE;
        y2x = (b.x * c2.x + a.x * s2.x) * QSCALE;
        y2y = (b.y * c2.y + a.y * s2.y) * QSCALE;
        dh = qh; dl = ql;
        doff = (size_t)r * DM_ + hh * HD_ + d2;
    } else if (hh < 40) {
        const int kvh = hh - 32;
        const float* p = qkv + (size_t)r * NQKV + KOFF + kvh * HD_;
        const float2 a = *(const float2*)(p + d2);
        const float2 b = *(const float2*)(p + d2 + 32);
        y1x = a.x * c1.x - b.x * s1.x;
        y1y = a.y * c1.y - b.y * s1.y;
        y2x = b.x * c2.x + a.x * s2.x;
        y2y = b.y * c2.y + a.y * s2.y;
        const int bb = r >> 11, s = r & (S_ - 1);
        dh = kh; dl = kl;
        doff = ((size_t)(bb * KV_ + kvh) * S_ + s) * HD_ + d2;
    } else {
        const int kvh = hh - 40;
        const float* p = qkv + (size_t)r * NQKV + VOFF + kvh * HD_;
        const float2 a = *(const float2*)(p + d2);
        const float2 b = *(const float2*)(p + d2 + 32);
        y1x = a.x; y1y = a.y; y2x = b.x; y2y = b.y;
        const int bb = r >> 11, s = r & (S_ - 1);
        dh = vh; dl = vl;
        doff = ((size_t)(bb * KV_ + kvh) * S_ + s) * HD_ + d2;
    }
    const uint32_t h1 = cvt_bf16x2(y1y, y1x);
    const uint32_t h2 = cvt_bf16x2(y2y, y2x);
    const float g0 = __uint_as_float(h1 << 16);
    const float g1 = __uint_as_float(h1 & 0xffff0000u);
    const float g2 = __uint_as_float(h2 << 16);
    const float g3 = __uint_as_float(h2 & 0xffff0000u);
    *(uint32_t*)(dh + doff)      = h1;
    *(uint32_t*)(dh + doff + 32) = h2;
    *(uint32_t*)(dl + doff)      = cvt_bf16x2(y1y - g1, y1x - g0);
    *(uint32_t*)(dl + doff + 32) = cvt_bf16x2(y2y - g3, y2x - g2);
}

// =========== tensor-core flash attention (3-term split-bf16) ==================
// r17: S-phase AND PV-phase MMAs interleaved across 4 accumulator chains with
// dual fragment windows. Per-chain accumulation order unchanged -> bit-identical.
#define AQ_L   8192
#define AKV0   16384
#define AKV_ST 16384
#define ASMEM  49152

__global__ __launch_bounds__(128, 4) void attn_mma(
    const __nv_bfloat16* __restrict__ qh, const __nv_bfloat16* __restrict__ ql,
    const __nv_bfloat16* __restrict__ kh, const __nv_bfloat16* __restrict__ kl,
    const __nv_bfloat16* __restrict__ vh, const __nv_bfloat16* __restrict__ vl,
    __nv_bfloat16* __restrict__ oh, __nv_bfloat16* __restrict__ ol)
{
    extern __shared__ char smem[];
    const uint32_t sb = smem_u32(smem);
    const int tid  = threadIdx.x;
    const int lane = tid & 31;
    const int warp = tid >> 5;
    const int wr0  = warp * 16;
    const int m0 = (gridDim.x - 1 - blockIdx.x) * 64;    // heavy tiles first
    const int h  = blockIdx.y;
    const int b  = blockIdx.z;
    const int kvh = h >> 2;

    const size_t kvbase = (size_t)(b * KV_ + kvh) * S_ * HD_;

    {
        const size_t qg = (size_t)(b * S_ + m0) * DM_ + h * HD_;
#pragma unroll
        for (int i = 0; i < 4; i++) {
            int c = tid + 128 * i;
            int row = c >> 3, u = c & 7;
            uint32_t ad = sb + row * 128 + (((uint32_t)(u ^ (row & 7))) << 4);
            cp_async16(ad,          qh + qg + (size_t)row * DM_ + u * 8);
            cp_async16(ad + AQ_L,   ql + qg + (size_t)row * DM_ + u * 8);
        }
    }
    CP_COMMIT();

    const int NT = (m0 >> 5) + 2;

#define LOAD_KV(t)                                                                \
    do {                                                                          \
        const int _j0 = (t) * 32;                                                 \
        const uint32_t _st = sb + AKV0 + ((t) & 1) * AKV_ST;                      \
        _Pragma("unroll")                                                         \
        for (int _i = 0; _i < 2; _i++) {                                          \
            int _c = tid * 2 + _i;                                                \
            int _r = _c >> 3, _u = _c & 7;                                        \
            uint32_t _ad = _st + _r * 128 + (((uint32_t)(_u ^ (_r & 7))) << 4);   \
            size_t _g = kvbase + (size_t)(_j0 + _r) * HD_ + _u * 8;               \
            cp_async16(_ad,          kh + _g);                                    \
            cp_async16(_ad + 4096,   kl + _g);                                    \
            cp_async16(_ad + 8192,   vh + _g);                                    \
            cp_async16(_ad + 12288,  vl + _g);                                    \
        }                                                                         \
    } while (0)

    LOAD_KV(0);
    CP_COMMIT();

    CP_WAIT(1);
    __syncthreads();

    uint32_t Qh_[4][4], Ql_[4][4];
    {
        const int row = wr0 + (lane & 15);
#pragma unroll
        for (int kk = 0; kk < 4; kk++) {
            uint32_t u = (uint32_t)(kk * 2 + (lane >> 4));
            uint32_t ad = sb + row * 128 + ((u ^ (uint32_t)(row & 7)) << 4);
            ldsm_x4(ad,        Qh_[kk][0], Qh_[kk][1], Qh_[kk][2], Qh_[kk][3]);
            ldsm_x4(ad + AQ_L, Ql_[kk][0], Ql_[kk][1], Ql_[kk][2], Ql_[kk][3]);
        }
    }

    float o[8][4];
#pragma unroll
    for (int d = 0; d < 8; d++)
#pragma unroll
        for (int r = 0; r < 4; r++) o[d][r] = 0.0f;
    float m1 = -1e30f, m2 = -1e30f, l1 = 0.0f, l2 = 0.0f;

    const int row1 = m0 + wr0 + (lane >> 2);
    const int row2 = row1 + 8;

    for (int t = 0; t < NT; t++) {
        CP_WAIT(0);
        __syncthreads();
        if (t + 1 < NT) LOAD_KV(t + 1);
        CP_COMMIT();

        const int j0 = t * 32;
        if (j0 <= m0 + wr0 + 15) {
            const uint32_t st = sb + AKV0 + (t & 1) * AKV_ST;

            // ---- S = Q K^T (3-term, log2 domain), 4-chain interleave -----------
            float s[4][4];
#pragma unroll
            for (int n = 0; n < 4; n++)
#pragma unroll
                for (int r = 0; r < 4; r++) s[n][r] = 0.0f;

            {
                const int krow = lane & 15;                 // np0 row; np1 = +16
#pragma unroll
                for (int kk = 0; kk < 4; kk++) {
                    uint32_t u = (uint32_t)(kk * 2 + (lane >> 4));
                    uint32_t ad0 = st + krow * 128 + ((u ^ (uint32_t)(krow & 7)) << 4);
                    uint32_t ad1 = ad0 + 2048;              // (16+krow)&7 == krow&7
                    uint32_t a0, a1, a2, a3, b0, b1, b2, b3;
                    ldsm_x4(ad0, a0, a1, a2, a3);           // Kh np0
                    ldsm_x4(ad1, b0, b1, b2, b3);           // Kh np1
                    mma_bf16(s[0], Qh_[kk], a0, a2);
                    mma_bf16(s[2], Qh_[kk], b0, b2);
                    mma_bf16(s[1], Qh_[kk], a1, a3);
                    mma_bf16(s[3], Qh_[kk], b1, b3);
                    mma_bf16(s[0], Ql_[kk], a0, a2);
                    mma_bf16(s[2], Ql_[kk], b0, b2);
                    mma_bf16(s[1], Ql_[kk], a1, a3);
                    mma_bf16(s[3], Ql_[kk], b1, b3);
                    ldsm_x4(ad0 + 4096, a0, a1, a2, a3);    // Kl np0 (reuse window)
                    ldsm_x4(ad1 + 4096, b0, b1, b2, b3);    // Kl np1
                    mma_bf16(s[0], Qh_[kk], a0, a2);
                    mma_bf16(s[2], Qh_[kk], b0, b2);
                    mma_bf16(s[1], Qh_[kk], a1, a3);
                    mma_bf16(s[3], Qh_[kk], b1, b3);
                }
            }

            if (j0 + 31 > m0 + wr0) {
#pragma unroll
                for (int n = 0; n < 4; n++) {
                    const int col = j0 + n * 8 + ((lane & 3) << 1);
                    if (col     > row1) s[n][0] = -1e30f;
                    if (col + 1 > row1) s[n][1] = -1e30f;
                    if (col     > row2) s[n][2] = -1e30f;
                    if (col + 1 > row2) s[n][3] = -1e30f;
                }
            }

            float mx1 = -1e30f, mx2 = -1e30f;
#pragma unroll
            for (int n = 0; n < 4; n++) {
                mx1 = fmaxf(mx1, fmaxf(s[n][0], s[n][1]));
                mx2 = fmaxf(mx2, fmaxf(s[n][2], s[n][3]));
            }
            mx1 = fmaxf(mx1, __shfl_xor_sync(0xffffffff, mx1, 1));
            mx1 = fmaxf(mx1, __shfl_xor_sync(0xffffffff, mx1, 2));
            mx2 = fmaxf(mx2, __shfl_xor_sync(0xffffffff, mx2, 1));
            mx2 = fmaxf(mx2, __shfl_xor_sync(0xffffffff, mx2, 2));

            const float M1 = fmaxf(m1, mx1), M2 = fmaxf(m2, mx2);
            const float c1 = ex2f(m1 - M1), c2 = ex2f(m2 - M2);
            float ls1 = 0.0f, ls2 = 0.0f;
#pragma unroll
            for (int n = 0; n < 4; n++) {
                s[n][0] = ex2f(s[n][0] - M1); ls1 += s[n][0];
                s[n][1] = ex2f(s[n][1] - M1); ls1 += s[n][1];
                s[n][2] = ex2f(s[n][2] - M2); ls2 += s[n][2];
                s[n][3] = ex2f(s[n][3] - M2); ls2 += s[n][3];
            }
            ls1 += __shfl_xor_sync(0xffffffff, ls1, 1);
            ls1 += __shfl_xor_sync(0xffffffff, ls1, 2);
            ls2 += __shfl_xor_sync(0xffffffff, ls2, 1);
            ls2 += __shfl_xor_sync(0xffffffff, ls2, 2);
            l1 = l1 * c1 + ls1;  l2 = l2 * c2 + ls2;
            m1 = M1;             m2 = M2;
#pragma unroll
            for (int d = 0; d < 8; d++) {
                o[d][0] *= c1; o[d][1] *= c1;
                o[d][2] *= c2; o[d][3] *= c2;
            }

            uint32_t ph[2][4], pl[2][4];
#pragma unroll
            for (int jj = 0; jj < 2; jj++) {
#pragma unroll
                for (int q = 0; q < 4; q++) {
                    const int n = 2 * jj + (q >> 1);
                    const int r = (q & 1) * 2;
                    const float a = s[n][r], bq = s[n][r + 1];
                    const uint32_t hp = cvt_bf16x2(bq, a);
                    const float fa = __uint_as_float(hp << 16);
                    const float fb = __uint_as_float(hp & 0xffff0000u);
                    ph[jj][q] = hp;
                    pl[jj][q] = cvt_bf16x2(bq - fb, a - fa);
                }
            }

            // ---- O += P V (3-term), 4-chain interleave over dg pairs ------------
#pragma unroll
            for (int dgp = 0; dgp < 2; dgp++) {
                const int dgA = 2 * dgp, dgB = 2 * dgp + 1;
#pragma unroll
                for (int jj = 0; jj < 2; jj++) {
                    const int vrow = jj * 16 + (lane & 15);
                    const uint32_t sw = (uint32_t)(vrow & 7);
                    uint32_t uA = (uint32_t)(dgA * 2 + (lane >> 4));
                    uint32_t uB = uA + 2;
                    uint32_t adA = st + 8192 + vrow * 128 + ((uA ^ sw) << 4);
                    uint32_t adB = st + 8192 + vrow * 128 + ((uB ^ sw) << 4);
                    uint32_t a0, a1, a2, a3, b0, b1, b2, b3;
                    ldsm_x4t(adA, a0, a1, a2, a3);          // Vh dgA
                    ldsm_x4t(adB, b0, b1, b2, b3);          // Vh dgB
                    mma_bf16(o[2 * dgA],     ph[jj], a0, a1);
                    mma_bf16(o[2 * dgB],     ph[jj], b0, b1);
                    mma_bf16(o[2 * dgA + 1], ph[jj], a2, a3);
                    mma_bf16(o[2 * dgB + 1], ph[jj], b2, b3);
                    mma_bf16(o[2 * dgA],     pl[jj], a0, a1);
                    mma_bf16(o[2 * dgB],     pl[jj], b0, b1);
                    mma_bf16(o[2 * dgA + 1], pl[jj], a2, a3);
                    mma_bf16(o[2 * dgB + 1], pl[jj], b2, b3);
                    ldsm_x4t(adA + 4096, a0, a1, a2, a3);   // Vl dgA (reuse window)
                    ldsm_x4t(adB + 4096, b0, b1, b2, b3);   // Vl dgB
                    mma_bf16(o[2 * dgA],     ph[jj], a0, a1);
                    mma_bf16(o[2 * dgB],     ph[jj], b0, b1);
                    mma_bf16(o[2 * dgA + 1], ph[jj], a2, a3);
                    mma_bf16(o[2 * dgB + 1], ph[jj], b2, b3);
                }
            }
        }
    }
#undef LOAD_KV

    const float inv1 = 1.0f / l1;
    const float inv2 = 1.0f / l2;
#pragma unroll
    for (int d = 0; d < 8; d++) {
        const int col = h * HD_ + d * 8 + ((lane & 3) << 1);
        {
            size_t ad = (size_t)(b * S_ + row1) * DM_ + col;
            const float x0 = o[d][0] * inv1, x1 = o[d][1] * inv1;
            const uint32_t hp = cvt_bf16x2(x1, x0);
            const float f0 = __uint_as_float(hp << 16);
            const float f1 = __uint_as_float(hp & 0xffff0000u);
            *(uint32_t*)(oh + ad) = hp;
            *(uint32_t*)(ol + ad) = cvt_bf16x2(x1 - f1, x0 - f0);
        }
        {
            size_t ad = (size_t)(b * S_ + row2) * DM_ + col;
            const float x0 = o[d][2] * inv2, x1 = o[d][3] * inv2;
            const uint32_t hp = cvt_bf16x2(x1, x0);
            const float f0 = __uint_as_float(hp << 16);
            const float f1 = __uint_as_float(hp & 0xffff0000u);
            *(uint32_t*)(oh + ad) = hp;
            *(uint32_t*)(ol + ad) = cvt_bf16x2(x1 - f1, x0 - f0);
        }
    }
}

// ================================ launch ======================================
extern "C" void kernel_launch(void* const* d_in, const int* in_sizes, int n_in,
                              void* d_out, int out_size)
{
    const float* hs    = (const float*)d_in[0];
    const float* cosb  = (const float*)d_in[2];
    const float* sinb  = (const float*)d_in[3];
    const float* W_q   = (const float*)d_in[4];
    const float* W_k   = (const float*)d_in[5];
    const float* W_v   = (const float*)d_in[6];
    const float* b_v   = (const float*)d_in[7];
    const float* W_o   = (const float*)d_in[8];
    const float* b_o   = (const float*)d_in[9];
    float* out = (float*)d_out;

    float* qkv;
    cudaGetSymbolAddress((void**)&qkv, g_qkv);
    __nv_bfloat16 *hsh, *hsl, *aoh, *aol, *wqkvh, *wqkvl, *woh, *wol;
    __nv_bfloat16 *qhp, *qlp, *khp, *klp, *vhp, *vlp;
    cudaGetSymbolAddress((void**)&hsh, g_hsh);
    cudaGetSymbolAddress((void**)&hsl, g_hsl);
    cudaGetSymbolAddress((void**)&aoh, g_aoh);
    cudaGetSymbolAddress((void**)&aol, g_aol);
    cudaGetSymbolAddress((void**)&wqkvh, g_wqkvh);
    cudaGetSymbolAddress((void**)&wqkvl, g_wqkvl);
    cudaGetSymbolAddress((void**)&woh, g_woh);
    cudaGetSymbolAddress((void**)&wol, g_wol);
    cudaGetSymbolAddress((void**)&qhp, g_qh);
    cudaGetSymbolAddress((void**)&qlp, g_ql);
    cudaGetSymbolAddress((void**)&khp, g_kh);
    cudaGetSymbolAddress((void**)&klp, g_kl);
    cudaGetSymbolAddress((void**)&vhp, g_vh);
    cudaGetSymbolAddress((void**)&vlp, g_vl);

    cudaFuncSetAttribute(gemm_mma,
                         cudaFuncAttributeMaxDynamicSharedMemorySize, GSMEM);
    cudaFuncSetAttribute(attn_mma,
                         cudaFuncAttributeMaxDynamicSharedMemorySize, ASMEM);

    const int M = B_ * S_;       // 4096

    // launch 0: ALL prep (weights + activations + counter reset), exact grid
    prep_all<<<13312, dim3(32, 8)>>>(
        hs, W_q, W_k, W_v, W_o, hsh, hsl, wqkvh, wqkvl, woh, wol);

    // launch 1: fused QKV projection (persistent, work-stealing on ctr 0)
    gemm_mma<<<GGRID, 256, GSMEM>>>(
        hsh, hsl, wqkvh, wqkvl, b_v, VOFF, qkv, M, NQKV, DM_, 0);

    // launch 2: RoPE + scale(log2e/8) + split, vectorized
    {
        int total = B_ * S_ * 48 * 16;
        rope_split_kernel<<<(total + 255) / 256, 256>>>(
            qkv, cosb, sinb, qhp, qlp, khp, klp, vhp, vlp);
    }

    // launch 3 (PROFILED): tensor-core flash attention, 4 CTAs/SM
    attn_mma<<<dim3(S_ / 64, H_, B_), 128, ASMEM>>>(
        qhp, qlp, khp, klp, vhp, vlp, aoh, aol);

    // launch 4: O projection (persistent, work-stealing on ctr 1)
    gemm_mma<<<GGRID, 256, GSMEM>>>(
        aoh, aol, woh, wol, b_o, 0, out, M, DM_, DM_, 1);
}